// round 1
// baseline (speedup 1.0000x reference)
#include <cuda_runtime.h>
#include <cuda_bf16.h>

// ---------------------------------------------------------------------------
// Problem constants
//   B=32, N=196, DQ=256, DC=1024, H=4, DH=64, DHC=256, 4N=784
// ---------------------------------------------------------------------------

#define SZ_BNDC   6422528LL   // 32*196*1024  (also 32*784*256)
#define SZ_SC     4917248LL   // 32*4*196*196
#define SZ_Q      1605632LL   // 32*196*256
#define SZ_ATTN  19668992LL   // 32*4*196*784

// Scratch (device .bss, allocation-free)
__device__ float g_q3[SZ_BNDC];
__device__ float g_k3[SZ_BNDC];
__device__ float g_v3[SZ_BNDC];
__device__ float g_sc[SZ_SC];
__device__ float g_oat[SZ_BNDC];
__device__ float g_that[SZ_BNDC];
__device__ float g_kvs[SZ_BNDC];
__device__ float g_Kb[SZ_BNDC];
__device__ float g_Vb[SZ_BNDC];
__device__ float g_Qb[SZ_Q];
__device__ float g_attn[SZ_ATTN];
__device__ float g_ctx[SZ_Q];
__device__ float g_gain[128];

// ---------------------------------------------------------------------------
// Generic batched tiled GEMM: C = alpha * op(A) @ op(B)
//   TA: A stored [K, M] row-major (lda = row length), element A(m,k)=A[k*lda+m]
//   TB: B stored [N, K] row-major (ldb = row length), element B(k,n)=B[n*ldb+k]
// Batch index z = bb*nh + hh;  offsets = bb*s?b + hh*s?h.
// ---------------------------------------------------------------------------
#define BM 64
#define BN 64
#define BK 16

template<bool TA, bool TB>
__global__ __launch_bounds__(256)
void gemm_bt(const float* __restrict__ A, const float* __restrict__ B,
             float* __restrict__ C,
             int M, int N, int K, int lda, int ldb, int ldc,
             long long sAb, long long sAh, long long sBb, long long sBh,
             long long sCb, long long sCh, int nh, float alpha)
{
    int z  = blockIdx.z;
    int bb = z / nh, hh = z % nh;
    A += bb * sAb + hh * sAh;
    B += bb * sBb + hh * sBh;
    C += bb * sCb + hh * sCh;

    __shared__ float As[BK][BM + 1];
    __shared__ float Bs[BK][BN + 1];

    int tid = threadIdx.x;
    int m0 = blockIdx.y * BM, n0 = blockIdx.x * BN;
    int ty = tid >> 4, tx = tid & 15;

    float acc[4][4];
#pragma unroll
    for (int i = 0; i < 4; i++)
#pragma unroll
        for (int j = 0; j < 4; j++) acc[i][j] = 0.f;

    for (int k0 = 0; k0 < K; k0 += BK) {
#pragma unroll
        for (int i = 0; i < 4; i++) {
            int e = tid + i * 256;
            int k = e >> 6, m = e & 63;
            int gm = m0 + m, gk = k0 + k;
            float v = 0.f;
            if (gm < M && gk < K)
                v = TA ? A[(long long)gk * lda + gm]
                       : A[(long long)gm * lda + gk];
            As[k][m] = v;
        }
#pragma unroll
        for (int i = 0; i < 4; i++) {
            int e = tid + i * 256;
            int k = e >> 6, n = e & 63;
            int gn = n0 + n, gk = k0 + k;
            float v = 0.f;
            if (gn < N && gk < K)
                v = TB ? B[(long long)gn * ldb + gk]
                       : B[(long long)gk * ldb + gn];
            Bs[k][n] = v;
        }
        __syncthreads();
#pragma unroll
        for (int k = 0; k < BK; k++) {
            float a[4], b[4];
#pragma unroll
            for (int i = 0; i < 4; i++) a[i] = As[k][ty * 4 + i];
#pragma unroll
            for (int j = 0; j < 4; j++) b[j] = Bs[k][tx * 4 + j];
#pragma unroll
            for (int i = 0; i < 4; i++)
#pragma unroll
                for (int j = 0; j < 4; j++) acc[i][j] += a[i] * b[j];
        }
        __syncthreads();
    }

#pragma unroll
    for (int i = 0; i < 4; i++) {
        int gm = m0 + ty * 4 + i;
        if (gm >= M) continue;
#pragma unroll
        for (int j = 0; j < 4; j++) {
            int gn = n0 + tx * 4 + j;
            if (gn < N) C[(long long)gm * ldc + gn] = alpha * acc[i][j];
        }
    }
}

// KV_S[b, j*196+t, c] = T_hat[b, t, j*256 + c]
__global__ void kvs_kernel(const float* __restrict__ T, float* __restrict__ KVS)
{
    long long i = (long long)blockIdx.x * blockDim.x + threadIdx.x;
    if (i >= SZ_BNDC) return;
    int c = (int)(i & 255);
    long long t2 = i >> 8;
    int n = (int)(t2 % 784);
    int b = (int)(t2 / 784);
    int j = n / 196, t = n % 196;
    KVS[i] = T[((long long)b * 196 + t) * 1024 + (long long)j * 256 + c];
}

// Row softmax in place, logits = x * scale (scale from per-group gain array)
__global__ void softmax_kernel(float* __restrict__ X, int cols,
                               const float* __restrict__ g, int rows_per_g)
{
    int row = blockIdx.x;
    float scale = g ? g[row / rows_per_g] : 1.0f;
    float* x = X + (long long)row * cols;
    int tid = threadIdx.x;
    __shared__ float red[256];

    float m = -1e30f;
    for (int c = tid; c < cols; c += 256) m = fmaxf(m, x[c] * scale);
    red[tid] = m; __syncthreads();
    for (int s = 128; s > 0; s >>= 1) {
        if (tid < s) red[tid] = fmaxf(red[tid], red[tid + s]);
        __syncthreads();
    }
    m = red[0]; __syncthreads();

    float sum = 0.f;
    for (int c = tid; c < cols; c += 256) {
        float e = __expf(x[c] * scale - m);
        x[c] = e; sum += e;
    }
    red[tid] = sum; __syncthreads();
    for (int s = 128; s > 0; s >>= 1) {
        if (tid < s) red[tid] += red[tid + s];
        __syncthreads();
    }
    float inv = 1.0f / red[0];
    for (int c = tid; c < cols; c += 256) x[c] *= inv;
}

// Per-(b,h) mean/var over the [196,784] score map -> gain = rsqrt(var + 1e-5)
__global__ void meanvar_kernel(const float* __restrict__ X, float* __restrict__ g,
                               long long nelem)
{
    int z = blockIdx.x;
    const float4* x = (const float4*)(X + (long long)z * nelem);
    long long n4 = nelem >> 2;
    float s = 0.f, s2 = 0.f;
    for (long long i = threadIdx.x; i < n4; i += blockDim.x) {
        float4 v = x[i];
        s  += v.x + v.y + v.z + v.w;
        s2 += v.x * v.x + v.y * v.y + v.z * v.z + v.w * v.w;
    }
    __shared__ float rs[256], rs2[256];
    rs[threadIdx.x] = s; rs2[threadIdx.x] = s2; __syncthreads();
    for (int t = 128; t > 0; t >>= 1) {
        if (threadIdx.x < t) {
            rs[threadIdx.x]  += rs[threadIdx.x + t];
            rs2[threadIdx.x] += rs2[threadIdx.x + t];
        }
        __syncthreads();
    }
    if (threadIdx.x == 0) {
        float mean = rs[0] / (float)nelem;
        float var  = rs2[0] / (float)nelem - mean * mean;
        g[z] = rsqrtf(var + 1e-5f);
    }
}

// ---------------------------------------------------------------------------
// Host-side driver
// ---------------------------------------------------------------------------
static inline void gemm(int ta, int tb,
                        const float* A, const float* B, float* C,
                        int M, int N, int K, int lda, int ldb, int ldc,
                        long long sAb, long long sAh,
                        long long sBb, long long sBh,
                        long long sCb, long long sCh,
                        int batch, int nh, float alpha)
{
    dim3 g((N + BN - 1) / BN, (M + BM - 1) / BM, batch), b(256);
    if (!ta && !tb)
        gemm_bt<false, false><<<g, b>>>(A, B, C, M, N, K, lda, ldb, ldc,
                                        sAb, sAh, sBb, sBh, sCb, sCh, nh, alpha);
    else if (!ta && tb)
        gemm_bt<false, true><<<g, b>>>(A, B, C, M, N, K, lda, ldb, ldc,
                                       sAb, sAh, sBb, sBh, sCb, sCh, nh, alpha);
    else
        gemm_bt<true, false><<<g, b>>>(A, B, C, M, N, K, lda, ldb, ldc,
                                       sAb, sAh, sBb, sBh, sCb, sCh, nh, alpha);
}

extern "C" void kernel_launch(void* const* d_in, const int* in_sizes, int n_in,
                              void* d_out, int out_size)
{
    const float* emb[4] = { (const float*)d_in[0], (const float*)d_in[1],
                            (const float*)d_in[2], (const float*)d_in[3] };
    const float* emb_C = (const float*)d_in[4];
    const float* Wq_c  = (const float*)d_in[5];
    const float* Wk_c  = (const float*)d_in[6];
    const float* Wv_c  = (const float*)d_in[7];
    const float* Wo_c  = (const float*)d_in[8];
    const float* Wq[4] = { (const float*)d_in[9],  (const float*)d_in[10],
                           (const float*)d_in[11], (const float*)d_in[12] };
    const float* Wk    = (const float*)d_in[13];
    const float* Wv    = (const float*)d_in[14];
    const float* Wo[4] = { (const float*)d_in[15], (const float*)d_in[16],
                           (const float*)d_in[17], (const float*)d_in[18] };
    float* out = (float*)d_out;

    float *q3, *k3, *v3, *sc, *oat, *that, *kvs, *Kb, *Vb, *Qb, *attn, *ctx, *gain;
    cudaGetSymbolAddress((void**)&q3,   g_q3);
    cudaGetSymbolAddress((void**)&k3,   g_k3);
    cudaGetSymbolAddress((void**)&v3,   g_v3);
    cudaGetSymbolAddress((void**)&sc,   g_sc);
    cudaGetSymbolAddress((void**)&oat,  g_oat);
    cudaGetSymbolAddress((void**)&that, g_that);
    cudaGetSymbolAddress((void**)&kvs,  g_kvs);
    cudaGetSymbolAddress((void**)&Kb,   g_Kb);
    cudaGetSymbolAddress((void**)&Vb,   g_Vb);
    cudaGetSymbolAddress((void**)&Qb,   g_Qb);
    cudaGetSymbolAddress((void**)&attn, g_attn);
    cudaGetSymbolAddress((void**)&ctx,  g_ctx);
    cudaGetSymbolAddress((void**)&gain, g_gain);

    // ---------------- Stage A: SATAT over emb_C ----------------
    // QKV: [6272,1024] @ [1024,1024]  (batches fused in M)
    gemm(0, 0, emb_C, Wq_c, q3, 6272, 1024, 1024, 1024, 1024, 1024,
         0, 0, 0, 0, 0, 0, 1, 1, 1.0f);
    gemm(0, 0, emb_C, Wk_c, k3, 6272, 1024, 1024, 1024, 1024, 1024,
         0, 0, 0, 0, 0, 0, 1, 1, 1.0f);
    gemm(0, 0, emb_C, Wv_c, v3, 6272, 1024, 1024, 1024, 1024, 1024,
         0, 0, 0, 0, 0, 0, 1, 1, 1.0f);
    // scores[b,h] = Qh @ Kh^T / 16 : M=196,N=196,K=256; heads are column slices
    gemm(0, 1, q3, k3, sc, 196, 196, 256, 1024, 1024, 196,
         200704, 256, 200704, 256, 153664, 38416, 128, 4, 0.0625f);
    // softmax over 196 cols
    softmax_kernel<<<25088, 256>>>(sc, 196, nullptr, 1);
    // o[b,h] = P @ Vh : M=196,N=256,K=196
    gemm(0, 0, sc, v3, oat, 196, 256, 196, 196, 1024, 1024,
         153664, 38416, 200704, 256, 200704, 256, 128, 4, 1.0f);
    // T_hat = o @ Wo_c
    gemm(0, 0, oat, Wo_c, that, 6272, 1024, 1024, 1024, 1024, 1024,
         0, 0, 0, 0, 0, 0, 1, 1, 1.0f);

    // ---------------- Stage B: KV token mix ----------------
    {
        long long total = SZ_BNDC;
        int thr = 256;
        long long blk = (total + thr - 1) / thr;
        kvs_kernel<<<(unsigned)blk, thr>>>(that, kvs);
    }
    // K[b] = Wk^T @ KV_S[b] : TN, M=784,N=256,K=784
    gemm(1, 0, Wk, kvs, Kb, 784, 256, 784, 784, 256, 256,
         0, 0, 200704, 0, 200704, 0, 32, 1, 1.0f);
    gemm(1, 0, Wv, kvs, Vb, 784, 256, 784, 784, 256, 256,
         0, 0, 200704, 0, 200704, 0, 32, 1, 1.0f);

    // ---------------- Stage C: 4 query branches ----------------
    for (int br = 0; br < 4; br++) {
        // Q[b] = Wq^T @ emb[b] : TN, M=196,N=256,K=196
        gemm(1, 0, Wq[br], emb[br], Qb, 196, 256, 196, 196, 256, 256,
             0, 0, 50176, 0, 50176, 0, 32, 1, 1.0f);
        // attn[b,h] = Qh @ Kh^T : M=196,N=784,K=64 (head = 64-col slice)
        gemm(0, 1, Qb, Kb, attn, 196, 784, 64, 256, 256, 784,
             50176, 64, 200704, 64, 614656, 153664, 128, 4, 1.0f);
        // instance-norm gain per (b,h): mean shift cancels in softmax
        meanvar_kernel<<<128, 256>>>(attn, gain, 153664LL);
        // row softmax with logits attn * gain[b,h]
        softmax_kernel<<<25088, 256>>>(attn, 784, gain, 196);
        // ctx[b,h] = P @ Vh : M=196,N=64,K=784
        gemm(0, 0, attn, Vb, ctx, 196, 64, 784, 784, 256, 256,
             614656, 153664, 200704, 64, 50176, 64, 128, 4, 1.0f);
        // O = ctx @ Wo : [6272,256] @ [256,256]
        gemm(0, 0, ctx, Wo[br], out + (long long)br * SZ_Q,
             6272, 256, 256, 256, 256, 256,
             0, 0, 0, 0, 0, 0, 1, 1, 1.0f);
    }
}

// round 2
// speedup vs baseline: 3.1413x; 3.1413x over previous
#include <cuda_runtime.h>
#include <cuda_bf16.h>
#include <cstdint>

// ---------------------------------------------------------------------------
// Problem constants: B=32, N=196, DQ=256, DC=1024, H=4, DH=64, DHC=256, 4N=784
// ---------------------------------------------------------------------------

#define SZ_BNDC   6422528LL   // 32*196*1024  (also 32*784*256)
#define SZ_SC     4917248LL   // 32*4*196*196
#define SZ_Q      1605632LL   // 32*196*256
#define SZ_ATTN  19668992LL   // 32*4*196*784

// Scratch (device .bss, allocation-free)
__device__ float g_q3[SZ_BNDC];
__device__ float g_k3[SZ_BNDC];
__device__ float g_v3[SZ_BNDC];
__device__ float g_sc[SZ_SC];
__device__ float g_oat[SZ_BNDC];
__device__ float g_that[SZ_BNDC];
__device__ float g_kvs[SZ_BNDC];
__device__ float g_Kb[SZ_BNDC];
__device__ float g_Vb[SZ_BNDC];
__device__ float g_Qb[SZ_Q];
__device__ float g_attn[SZ_ATTN];
__device__ float g_ctx[SZ_Q];
__device__ float g_gain[128];
__device__ float g_WkT[614656];       // 784*784
__device__ float g_WvT[614656];
__device__ float g_WqT[4 * 38416];    // 4 * 196*196

// ---------------------------------------------------------------------------
// PTX helpers
// ---------------------------------------------------------------------------
__device__ __forceinline__ uint32_t smem_u32(const void* p) {
    return (uint32_t)__cvta_generic_to_shared(p);
}

__device__ __forceinline__ void ldsm_x4(uint32_t& r0, uint32_t& r1,
                                        uint32_t& r2, uint32_t& r3, uint32_t addr) {
    asm volatile("ldmatrix.sync.aligned.m8n8.x4.shared.b16 {%0,%1,%2,%3},[%4];"
                 : "=r"(r0), "=r"(r1), "=r"(r2), "=r"(r3) : "r"(addr));
}

__device__ __forceinline__ void ldsm_x4_t(uint32_t& r0, uint32_t& r1,
                                          uint32_t& r2, uint32_t& r3, uint32_t addr) {
    asm volatile("ldmatrix.sync.aligned.m8n8.x4.trans.shared.b16 {%0,%1,%2,%3},[%4];"
                 : "=r"(r0), "=r"(r1), "=r"(r2), "=r"(r3) : "r"(addr));
}

__device__ __forceinline__ void mma_bf16(float* c, const uint32_t* a, const uint32_t* b) {
    asm volatile("mma.sync.aligned.m16n8k16.row.col.f32.bf16.bf16.f32 "
                 "{%0,%1,%2,%3},{%4,%5,%6,%7},{%8,%9},{%0,%1,%2,%3};"
                 : "+f"(c[0]), "+f"(c[1]), "+f"(c[2]), "+f"(c[3])
                 : "r"(a[0]), "r"(a[1]), "r"(a[2]), "r"(a[3]),
                   "r"(b[0]), "r"(b[1]));
}

// ---------------------------------------------------------------------------
// Tensor-core batched GEMM with split-bf16 (3-term) fp32 emulation.
//   C = alpha * A @ op(B);  A is [M,K] row-major (lda).
//   TB=false: B is [K,N] row-major (ldb).   TB=true: B is [N,K] row-major (ldb).
// Batch: z = bb*nh + hh, pointer offsets sXb/sXh.
// ---------------------------------------------------------------------------
#define TBM 128
#define TBN 128
#define TBK 32
#define APAD 8
#define BPAD 8

template<bool TB>
__global__ __launch_bounds__(256)
void gemm_mma(const float* __restrict__ A, const float* __restrict__ B,
              float* __restrict__ C,
              int M, int N, int K, int lda, int ldb, int ldc,
              long long sAb, long long sAh, long long sBb, long long sBh,
              long long sCb, long long sCh, int nh, float alpha)
{
    int z  = blockIdx.z;
    int bb = z / nh, hh = z % nh;
    A += bb * sAb + hh * sAh;
    B += bb * sBb + hh * sBh;
    C += bb * sCb + hh * sCh;

    __shared__ __align__(16) __nv_bfloat16 As[2][TBM][TBK + APAD];
    __shared__ __align__(16) __nv_bfloat16 Bs[2][TBK][TBN + BPAD];

    const int tid  = threadIdx.x;
    const int lane = tid & 31;
    const int wid  = tid >> 5;
    const int wm   = wid >> 2;   // 0..1
    const int wn   = wid & 3;    // 0..3
    const int m0 = blockIdx.y * TBM, n0 = blockIdx.x * TBN;

    float acc[4][4][4];
#pragma unroll
    for (int i = 0; i < 4; i++)
#pragma unroll
        for (int j = 0; j < 4; j++)
#pragma unroll
            for (int r = 0; r < 4; r++) acc[i][j][r] = 0.f;

    // thread mappings for global loads
    const int ar  = tid >> 3, ac4 = tid & 7;          // A: 32 rows/pass, 8 float4 per row
    const int bkr = tid >> 5, bc4 = tid & 31;         // B NN: 8 k-rows/pass, 32 float4/row
    const int bnr = tid >> 3, bk4 = tid & 7;          // B NT: 32 n-rows/pass, 8 float4/row

    float4 aPre[4], bPre[4];

#define LOAD_REGS(K0)                                                           \
    {                                                                           \
        int k0_ = (K0);                                                         \
        _Pragma("unroll")                                                       \
        for (int i = 0; i < 4; i++) {                                           \
            int gm = m0 + ar + i * 32, gk = k0_ + ac4 * 4;                      \
            aPre[i] = (gm < M && gk < K)                                        \
                ? *(const float4*)&A[(long long)gm * lda + gk]                  \
                : make_float4(0.f, 0.f, 0.f, 0.f);                              \
        }                                                                       \
        if (!TB) {                                                              \
            _Pragma("unroll")                                                   \
            for (int i = 0; i < 4; i++) {                                       \
                int gk = k0_ + bkr + i * 8, gn = n0 + bc4 * 4;                  \
                bPre[i] = (gk < K && gn < N)                                    \
                    ? *(const float4*)&B[(long long)gk * ldb + gn]              \
                    : make_float4(0.f, 0.f, 0.f, 0.f);                          \
            }                                                                   \
        } else {                                                                \
            _Pragma("unroll")                                                   \
            for (int i = 0; i < 4; i++) {                                       \
                int gn = n0 + bnr + i * 32, gk = k0_ + bk4 * 4;                 \
                bPre[i] = (gn < N && gk < K)                                    \
                    ? *(const float4*)&B[(long long)gn * ldb + gk]              \
                    : make_float4(0.f, 0.f, 0.f, 0.f);                          \
            }                                                                   \
        }                                                                       \
    }

#define CVT_STORE_A(dstRow, dstCol, f)                                          \
    {                                                                           \
        __nv_bfloat16 hi_ = __float2bfloat16(f);                                \
        As[0][dstRow][dstCol] = hi_;                                            \
        As[1][dstRow][dstCol] = __float2bfloat16((f) - __bfloat162float(hi_));  \
    }
#define CVT_STORE_B(dstRow, dstCol, f)                                          \
    {                                                                           \
        __nv_bfloat16 hi_ = __float2bfloat16(f);                                \
        Bs[0][dstRow][dstCol] = hi_;                                            \
        Bs[1][dstRow][dstCol] = __float2bfloat16((f) - __bfloat162float(hi_));  \
    }

#define STORE_SMEM()                                                            \
    {                                                                           \
        _Pragma("unroll")                                                       \
        for (int i = 0; i < 4; i++) {                                           \
            int m = ar + i * 32, c = ac4 * 4;                                   \
            CVT_STORE_A(m, c + 0, aPre[i].x);                                   \
            CVT_STORE_A(m, c + 1, aPre[i].y);                                   \
            CVT_STORE_A(m, c + 2, aPre[i].z);                                   \
            CVT_STORE_A(m, c + 3, aPre[i].w);                                   \
        }                                                                       \
        if (!TB) {                                                              \
            _Pragma("unroll")                                                   \
            for (int i = 0; i < 4; i++) {                                       \
                int k = bkr + i * 8, c = bc4 * 4;                               \
                CVT_STORE_B(k, c + 0, bPre[i].x);                               \
                CVT_STORE_B(k, c + 1, bPre[i].y);                               \
                CVT_STORE_B(k, c + 2, bPre[i].z);                               \
                CVT_STORE_B(k, c + 3, bPre[i].w);                               \
            }                                                                   \
        } else {                                                                \
            _Pragma("unroll")                                                   \
            for (int i = 0; i < 4; i++) {                                       \
                int n = bnr + i * 32, k = bk4 * 4;                              \
                CVT_STORE_B(k + 0, n, bPre[i].x);                               \
                CVT_STORE_B(k + 1, n, bPre[i].y);                               \
                CVT_STORE_B(k + 2, n, bPre[i].z);                               \
                CVT_STORE_B(k + 3, n, bPre[i].w);                               \
            }                                                                   \
        }                                                                       \
    }

#define COMPUTE()                                                               \
    {                                                                           \
        _Pragma("unroll")                                                       \
        for (int kk = 0; kk < TBK; kk += 16) {                                  \
            uint32_t Ah[4][4], Al[4][4], Bh[4][2], Bl[4][2];                    \
            _Pragma("unroll")                                                   \
            for (int i = 0; i < 4; i++) {                                       \
                int row = wm * 64 + i * 16 + (lane & 15);                       \
                int col = kk + ((lane >> 4) << 3);                              \
                ldsm_x4(Ah[i][0], Ah[i][1], Ah[i][2], Ah[i][3],                 \
                        smem_u32(&As[0][row][col]));                            \
                ldsm_x4(Al[i][0], Al[i][1], Al[i][2], Al[i][3],                 \
                        smem_u32(&As[1][row][col]));                            \
            }                                                                   \
            _Pragma("unroll")                                                   \
            for (int t = 0; t < 2; t++) {                                       \
                int row = kk + (lane & 15);                                     \
                int col = wn * 32 + t * 16 + ((lane >> 4) << 3);                \
                uint32_t r0, r1, r2, r3;                                        \
                ldsm_x4_t(r0, r1, r2, r3, smem_u32(&Bs[0][row][col]));          \
                Bh[t*2][0] = r0; Bh[t*2][1] = r1;                               \
                Bh[t*2+1][0] = r2; Bh[t*2+1][1] = r3;                           \
                ldsm_x4_t(r0, r1, r2, r3, smem_u32(&Bs[1][row][col]));          \
                Bl[t*2][0] = r0; Bl[t*2][1] = r1;                               \
                Bl[t*2+1][0] = r2; Bl[t*2+1][1] = r3;                           \
            }                                                                   \
            _Pragma("unroll")                                                   \
            for (int i = 0; i < 4; i++)                                         \
                _Pragma("unroll")                                               \
                for (int j = 0; j < 4; j++) {                                   \
                    mma_bf16(acc[i][j], Ah[i], Bh[j]);                          \
                    mma_bf16(acc[i][j], Ah[i], Bl[j]);                          \
                    mma_bf16(acc[i][j], Al[i], Bh[j]);                          \
                }                                                               \
        }                                                                       \
    }

    const int ktiles = (K + TBK - 1) / TBK;

    LOAD_REGS(0);
    STORE_SMEM();
    __syncthreads();

    for (int t = 0; t < ktiles; t++) {
        bool last = (t == ktiles - 1);
        if (!last) LOAD_REGS((t + 1) * TBK);
        COMPUTE();
        if (!last) {
            __syncthreads();
            STORE_SMEM();
            __syncthreads();
        }
    }

    // Epilogue
    const int g  = lane >> 2;
    const int tg = lane & 3;
#pragma unroll
    for (int i = 0; i < 4; i++) {
        int r0w = m0 + wm * 64 + i * 16 + g;
        int r1w = r0w + 8;
#pragma unroll
        for (int j = 0; j < 4; j++) {
            int c0 = n0 + wn * 32 + j * 8 + tg * 2;
            if (c0 < N) {
                if (r0w < M) {
                    float2 v = make_float2(alpha * acc[i][j][0], alpha * acc[i][j][1]);
                    *(float2*)&C[(long long)r0w * ldc + c0] = v;
                }
                if (r1w < M) {
                    float2 v = make_float2(alpha * acc[i][j][2], alpha * acc[i][j][3]);
                    *(float2*)&C[(long long)r1w * ldc + c0] = v;
                }
            }
        }
    }
#undef LOAD_REGS
#undef STORE_SMEM
#undef COMPUTE
#undef CVT_STORE_A
#undef CVT_STORE_B
}

// ---------------------------------------------------------------------------
// Transpose: dst[N,M] = src[M,N]^T
// ---------------------------------------------------------------------------
__global__ void transpose_kernel(const float* __restrict__ src, float* __restrict__ dst,
                                 int M, int N)
{
    __shared__ float t[32][33];
    int x = blockIdx.x * 32 + threadIdx.x;
    int y0 = blockIdx.y * 32 + threadIdx.y;
#pragma unroll
    for (int i = 0; i < 32; i += 8) {
        int y = y0 + i;
        t[threadIdx.y + i][threadIdx.x] = (y < M && x < N) ? src[(long long)y * N + x] : 0.f;
    }
    __syncthreads();
    int xo = blockIdx.y * 32 + threadIdx.x;
    int yo0 = blockIdx.x * 32 + threadIdx.y;
#pragma unroll
    for (int i = 0; i < 32; i += 8) {
        int yo = yo0 + i;
        if (yo < N && xo < M) dst[(long long)yo * M + xo] = t[threadIdx.x][threadIdx.y + i];
    }
}

// KV_S[b, j*196+t, c] = T_hat[b, t, j*256 + c]
__global__ void kvs_kernel(const float* __restrict__ T, float* __restrict__ KVS)
{
    long long i = (long long)blockIdx.x * blockDim.x + threadIdx.x;
    if (i >= SZ_BNDC) return;
    int c = (int)(i & 255);
    long long t2 = i >> 8;
    int n = (int)(t2 % 784);
    int b = (int)(t2 / 784);
    int j = n / 196, t = n % 196;
    KVS[i] = T[((long long)b * 196 + t) * 1024 + (long long)j * 256 + c];
}

// Row softmax in place, logits = x * scale (scale from per-group gain array)
__global__ void softmax_kernel(float* __restrict__ X, int cols,
                               const float* __restrict__ g, int rows_per_g)
{
    int row = blockIdx.x;
    float scale = g ? g[row / rows_per_g] : 1.0f;
    float* x = X + (long long)row * cols;
    int tid = threadIdx.x;
    __shared__ float red[256];

    float m = -1e30f;
    for (int c = tid; c < cols; c += 256) m = fmaxf(m, x[c] * scale);
    red[tid] = m; __syncthreads();
    for (int s = 128; s > 0; s >>= 1) {
        if (tid < s) red[tid] = fmaxf(red[tid], red[tid + s]);
        __syncthreads();
    }
    m = red[0]; __syncthreads();

    float sum = 0.f;
    for (int c = tid; c < cols; c += 256) {
        float e = __expf(x[c] * scale - m);
        x[c] = e; sum += e;
    }
    red[tid] = sum; __syncthreads();
    for (int s = 128; s > 0; s >>= 1) {
        if (tid < s) red[tid] += red[tid + s];
        __syncthreads();
    }
    float inv = 1.0f / red[0];
    for (int c = tid; c < cols; c += 256) x[c] *= inv;
}

// Per-(b,h) mean/var over the [196,784] score map -> gain = rsqrt(var + 1e-5)
__global__ void meanvar_kernel(const float* __restrict__ X, float* __restrict__ g,
                               long long nelem)
{
    int z = blockIdx.x;
    const float4* x = (const float4*)(X + (long long)z * nelem);
    long long n4 = nelem >> 2;
    float s = 0.f, s2 = 0.f;
    for (long long i = threadIdx.x; i < n4; i += blockDim.x) {
        float4 v = x[i];
        s  += v.x + v.y + v.z + v.w;
        s2 += v.x * v.x + v.y * v.y + v.z * v.z + v.w * v.w;
    }
    __shared__ float rs[256], rs2[256];
    rs[threadIdx.x] = s; rs2[threadIdx.x] = s2; __syncthreads();
    for (int t = 128; t > 0; t >>= 1) {
        if (threadIdx.x < t) {
            rs[threadIdx.x]  += rs[threadIdx.x + t];
            rs2[threadIdx.x] += rs2[threadIdx.x + t];
        }
        __syncthreads();
    }
    if (threadIdx.x == 0) {
        float mean = rs[0] / (float)nelem;
        float var  = rs2[0] / (float)nelem - mean * mean;
        g[z] = rsqrtf(var + 1e-5f);
    }
}

// ---------------------------------------------------------------------------
// Host-side driver
// ---------------------------------------------------------------------------
static inline void gemm(int tb,
                        const float* A, const float* B, float* C,
                        int M, int N, int K, int lda, int ldb, int ldc,
                        long long sAb, long long sAh,
                        long long sBb, long long sBh,
                        long long sCb, long long sCh,
                        int batch, int nh, float alpha)
{
    dim3 g((N + TBN - 1) / TBN, (M + TBM - 1) / TBM, batch), b(256);
    if (tb)
        gemm_mma<true><<<g, b>>>(A, B, C, M, N, K, lda, ldb, ldc,
                                 sAb, sAh, sBb, sBh, sCb, sCh, nh, alpha);
    else
        gemm_mma<false><<<g, b>>>(A, B, C, M, N, K, lda, ldb, ldc,
                                  sAb, sAh, sBb, sBh, sCb, sCh, nh, alpha);
}

extern "C" void kernel_launch(void* const* d_in, const int* in_sizes, int n_in,
                              void* d_out, int out_size)
{
    const float* emb[4] = { (const float*)d_in[0], (const float*)d_in[1],
                            (const float*)d_in[2], (const float*)d_in[3] };
    const float* emb_C = (const float*)d_in[4];
    const float* Wq_c  = (const float*)d_in[5];
    const float* Wk_c  = (const float*)d_in[6];
    const float* Wv_c  = (const float*)d_in[7];
    const float* Wo_c  = (const float*)d_in[8];
    const float* Wq[4] = { (const float*)d_in[9],  (const float*)d_in[10],
                           (const float*)d_in[11], (const float*)d_in[12] };
    const float* Wk    = (const float*)d_in[13];
    const float* Wv    = (const float*)d_in[14];
    const float* Wo[4] = { (const float*)d_in[15], (const float*)d_in[16],
                           (const float*)d_in[17], (const float*)d_in[18] };
    float* out = (float*)d_out;

    float *q3, *k3, *v3, *sc, *oat, *that, *kvs, *Kb, *Vb, *Qb, *attn, *ctx, *gain;
    float *WkT, *WvT, *WqT;
    cudaGetSymbolAddress((void**)&q3,   g_q3);
    cudaGetSymbolAddress((void**)&k3,   g_k3);
    cudaGetSymbolAddress((void**)&v3,   g_v3);
    cudaGetSymbolAddress((void**)&sc,   g_sc);
    cudaGetSymbolAddress((void**)&oat,  g_oat);
    cudaGetSymbolAddress((void**)&that, g_that);
    cudaGetSymbolAddress((void**)&kvs,  g_kvs);
    cudaGetSymbolAddress((void**)&Kb,   g_Kb);
    cudaGetSymbolAddress((void**)&Vb,   g_Vb);
    cudaGetSymbolAddress((void**)&Qb,   g_Qb);
    cudaGetSymbolAddress((void**)&attn, g_attn);
    cudaGetSymbolAddress((void**)&ctx,  g_ctx);
    cudaGetSymbolAddress((void**)&gain, g_gain);
    cudaGetSymbolAddress((void**)&WkT,  g_WkT);
    cudaGetSymbolAddress((void**)&WvT,  g_WvT);
    cudaGetSymbolAddress((void**)&WqT,  g_WqT);

    // ---------------- Weight pre-transposes ----------------
    {
        dim3 b(32, 8);
        dim3 g784((784 + 31) / 32, (784 + 31) / 32);
        transpose_kernel<<<g784, b>>>(Wk, WkT, 784, 784);
        transpose_kernel<<<g784, b>>>(Wv, WvT, 784, 784);
        dim3 g196((196 + 31) / 32, (196 + 31) / 32);
        for (int i = 0; i < 4; i++)
            transpose_kernel<<<g196, b>>>(Wq[i], WqT + (long long)i * 38416, 196, 196);
    }

    // ---------------- Stage A: SATAT over emb_C ----------------
    gemm(0, emb_C, Wq_c, q3, 6272, 1024, 1024, 1024, 1024, 1024,
         0, 0, 0, 0, 0, 0, 1, 1, 1.0f);
    gemm(0, emb_C, Wk_c, k3, 6272, 1024, 1024, 1024, 1024, 1024,
         0, 0, 0, 0, 0, 0, 1, 1, 1.0f);
    gemm(0, emb_C, Wv_c, v3, 6272, 1024, 1024, 1024, 1024, 1024,
         0, 0, 0, 0, 0, 0, 1, 1, 1.0f);
    // scores[b,h] = Qh @ Kh^T / 16 : NT
    gemm(1, q3, k3, sc, 196, 196, 256, 1024, 1024, 196,
         200704, 256, 200704, 256, 153664, 38416, 128, 4, 0.0625f);
    softmax_kernel<<<25088, 256>>>(sc, 196, nullptr, 1);
    // o[b,h] = P @ Vh
    gemm(0, sc, v3, oat, 196, 256, 196, 196, 1024, 1024,
         153664, 38416, 200704, 256, 200704, 256, 128, 4, 1.0f);
    // T_hat = o @ Wo_c
    gemm(0, oat, Wo_c, that, 6272, 1024, 1024, 1024, 1024, 1024,
         0, 0, 0, 0, 0, 0, 1, 1, 1.0f);

    // ---------------- Stage B: KV token mix ----------------
    {
        long long total = SZ_BNDC;
        int thr = 256;
        long long blk = (total + thr - 1) / thr;
        kvs_kernel<<<(unsigned)blk, thr>>>(that, kvs);
    }
    // K[b] = WkT @ KV_S[b]
    gemm(0, WkT, kvs, Kb, 784, 256, 784, 784, 256, 256,
         0, 0, 200704, 0, 200704, 0, 32, 1, 1.0f);
    gemm(0, WvT, kvs, Vb, 784, 256, 784, 784, 256, 256,
         0, 0, 200704, 0, 200704, 0, 32, 1, 1.0f);

    // ---------------- Stage C: 4 query branches ----------------
    for (int br = 0; br < 4; br++) {
        // Q[b] = WqT @ emb[b]
        gemm(0, WqT + (long long)br * 38416, emb[br], Qb, 196, 256, 196, 196, 256, 256,
             0, 0, 50176, 0, 50176, 0, 32, 1, 1.0f);
        // attn[b,h] = Qh @ Kh^T : NT
        gemm(1, Qb, Kb, attn, 196, 784, 64, 256, 256, 784,
             50176, 64, 200704, 64, 614656, 153664, 128, 4, 1.0f);
        meanvar_kernel<<<128, 256>>>(attn, gain, 153664LL);
        softmax_kernel<<<25088, 256>>>(attn, 784, gain, 196);
        // ctx[b,h] = P @ Vh
        gemm(0, attn, Vb, ctx, 196, 64, 784, 784, 256, 256,
             614656, 153664, 200704, 64, 50176, 64, 128, 4, 1.0f);
        // O = ctx @ Wo
        gemm(0, ctx, Wo[br], out + (long long)br * SZ_Q,
             6272, 256, 256, 256, 256, 256,
             0, 0, 0, 0, 0, 0, 1, 1, 1.0f);
    }
}

// round 5
// speedup vs baseline: 3.3572x; 1.0688x over previous
#include <cuda_runtime.h>
#include <cuda_bf16.h>
#include <cstdint>

// ---------------------------------------------------------------------------
// Problem constants: B=32, N=196, DQ=256, DC=1024, H=4, DH=64, DHC=256, 4N=784
// ---------------------------------------------------------------------------

#define SZ_BNDC   6422528LL   // 32*196*1024  (also 32*784*256)
#define SZ_SC     4917248LL   // 32*4*196*196
#define SZ_Q      1605632LL   // 32*196*256
#define SZ_ATTN  19668992LL   // 32*4*196*784 (one branch)

// Scratch (device .bss, allocation-free) — same layout/size as the known-good
// round-2 kernel (~322 MB total).
__device__ float g_q3[SZ_BNDC];
__device__ float g_k3[SZ_BNDC];
__device__ float g_v3[SZ_BNDC];
__device__ float g_sc[SZ_SC];
__device__ float g_oat[SZ_BNDC];
__device__ float g_that[SZ_BNDC];
__device__ float g_kvs[SZ_BNDC];
__device__ float g_Kb[SZ_BNDC];
__device__ float g_Vb[SZ_BNDC];
__device__ float g_Qb[SZ_Q];
__device__ float g_attn[SZ_ATTN];
__device__ float g_ctx[SZ_Q];
__device__ float g_gain[128];
__device__ float g_rowmax[128 * 196];
__device__ float g_WkT[614656];       // 784*784
__device__ float g_WvT[614656];
__device__ float g_WqT[4 * 38416];    // 4 * 196*196

// ---------------------------------------------------------------------------
// PTX helpers
// ---------------------------------------------------------------------------
__device__ __forceinline__ uint32_t smem_u32(const void* p) {
    return (uint32_t)__cvta_generic_to_shared(p);
}

__device__ __forceinline__ void ldsm_x4(uint32_t& r0, uint32_t& r1,
                                        uint32_t& r2, uint32_t& r3, uint32_t addr) {
    asm volatile("ldmatrix.sync.aligned.m8n8.x4.shared.b16 {%0,%1,%2,%3},[%4];"
                 : "=r"(r0), "=r"(r1), "=r"(r2), "=r"(r3) : "r"(addr));
}

__device__ __forceinline__ void ldsm_x4_t(uint32_t& r0, uint32_t& r1,
                                          uint32_t& r2, uint32_t& r3, uint32_t addr) {
    asm volatile("ldmatrix.sync.aligned.m8n8.x4.trans.shared.b16 {%0,%1,%2,%3},[%4];"
                 : "=r"(r0), "=r"(r1), "=r"(r2), "=r"(r3) : "r"(addr));
}

__device__ __forceinline__ void mma_bf16(float* c, const uint32_t* a, const uint32_t* b) {
    asm volatile("mma.sync.aligned.m16n8k16.row.col.f32.bf16.bf16.f32 "
                 "{%0,%1,%2,%3},{%4,%5,%6,%7},{%8,%9},{%0,%1,%2,%3};"
                 : "+f"(c[0]), "+f"(c[1]), "+f"(c[2]), "+f"(c[3])
                 : "r"(a[0]), "r"(a[1]), "r"(a[2]), "r"(a[3]),
                   "r"(b[0]), "r"(b[1]));
}

// ---------------------------------------------------------------------------
// Tensor-core batched GEMM with split-bf16 (3-term) fp32 emulation.
//   C = alpha * A @ op(B);  A is [M,K] row-major (lda).
//   TB=false: B is [K,N] row-major (ldb).   TB=true: B is [N,K] row-major (ldb).
// Batch: z = bb*nh + hh, pointer offsets sXb/sXh.   (identical to round 2)
// ---------------------------------------------------------------------------
#define TBM 128
#define TBN 128
#define TBK 32
#define APAD 8
#define BPAD 8

template<bool TB>
__global__ __launch_bounds__(256)
void gemm_mma(const float* __restrict__ A, const float* __restrict__ B,
              float* __restrict__ C,
              int M, int N, int K, int lda, int ldb, int ldc,
              long long sAb, long long sAh, long long sBb, long long sBh,
              long long sCb, long long sCh, int nh, float alpha)
{
    int z  = blockIdx.z;
    int bb = z / nh, hh = z % nh;
    A += bb * sAb + hh * sAh;
    B += bb * sBb + hh * sBh;
    C += bb * sCb + hh * sCh;

    __shared__ __align__(16) __nv_bfloat16 As[2][TBM][TBK + APAD];
    __shared__ __align__(16) __nv_bfloat16 Bs[2][TBK][TBN + BPAD];

    const int tid  = threadIdx.x;
    const int lane = tid & 31;
    const int wid  = tid >> 5;
    const int wm   = wid >> 2;
    const int wn   = wid & 3;
    const int m0 = blockIdx.y * TBM, n0 = blockIdx.x * TBN;

    float acc[4][4][4];
#pragma unroll
    for (int i = 0; i < 4; i++)
#pragma unroll
        for (int j = 0; j < 4; j++)
#pragma unroll
            for (int r = 0; r < 4; r++) acc[i][j][r] = 0.f;

    const int ar  = tid >> 3, ac4 = tid & 7;
    const int bkr = tid >> 5, bc4 = tid & 31;
    const int bnr = tid >> 3, bk4 = tid & 7;

    float4 aPre[4], bPre[4];

#define LOAD_REGS(K0)                                                           \
    {                                                                           \
        int k0_ = (K0);                                                         \
        _Pragma("unroll")                                                       \
        for (int i = 0; i < 4; i++) {                                           \
            int gm = m0 + ar + i * 32, gk = k0_ + ac4 * 4;                      \
            aPre[i] = (gm < M && gk < K)                                        \
                ? *(const float4*)&A[(long long)gm * lda + gk]                  \
                : make_float4(0.f, 0.f, 0.f, 0.f);                              \
        }                                                                       \
        if (!TB) {                                                              \
            _Pragma("unroll")                                                   \
            for (int i = 0; i < 4; i++) {                                       \
                int gk = k0_ + bkr + i * 8, gn = n0 + bc4 * 4;                  \
                bPre[i] = (gk < K && gn < N)                                    \
                    ? *(const float4*)&B[(long long)gk * ldb + gn]              \
                    : make_float4(0.f, 0.f, 0.f, 0.f);                          \
            }                                                                   \
        } else {                                                                \
            _Pragma("unroll")                                                   \
            for (int i = 0; i < 4; i++) {                                       \
                int gn = n0 + bnr + i * 32, gk = k0_ + bk4 * 4;                 \
                bPre[i] = (gn < N && gk < K)                                    \
                    ? *(const float4*)&B[(long long)gn * ldb + gk]              \
                    : make_float4(0.f, 0.f, 0.f, 0.f);                          \
            }                                                                   \
        }                                                                       \
    }

#define CVT_A(dr, dc, f)                                                        \
    {                                                                           \
        __nv_bfloat16 hi_ = __float2bfloat16(f);                                \
        As[0][dr][dc] = hi_;                                                    \
        As[1][dr][dc] = __float2bfloat16((f) - __bfloat162float(hi_));          \
    }
#define CVT_B(dr, dc, f)                                                        \
    {                                                                           \
        __nv_bfloat16 hi_ = __float2bfloat16(f);                                \
        Bs[0][dr][dc] = hi_;                                                    \
        Bs[1][dr][dc] = __float2bfloat16((f) - __bfloat162float(hi_));          \
    }

#define STORE_SMEM()                                                            \
    {                                                                           \
        _Pragma("unroll")                                                       \
        for (int i = 0; i < 4; i++) {                                           \
            int m = ar + i * 32, c = ac4 * 4;                                   \
            CVT_A(m, c + 0, aPre[i].x); CVT_A(m, c + 1, aPre[i].y);             \
            CVT_A(m, c + 2, aPre[i].z); CVT_A(m, c + 3, aPre[i].w);             \
        }                                                                       \
        if (!TB) {                                                              \
            _Pragma("unroll")                                                   \
            for (int i = 0; i < 4; i++) {                                       \
                int k = bkr + i * 8, c = bc4 * 4;                               \
                CVT_B(k, c + 0, bPre[i].x); CVT_B(k, c + 1, bPre[i].y);         \
                CVT_B(k, c + 2, bPre[i].z); CVT_B(k, c + 3, bPre[i].w);         \
            }                                                                   \
        } else {                                                                \
            _Pragma("unroll")                                                   \
            for (int i = 0; i < 4; i++) {                                       \
                int n = bnr + i * 32, k = bk4 * 4;                              \
                CVT_B(k + 0, n, bPre[i].x); CVT_B(k + 1, n, bPre[i].y);         \
                CVT_B(k + 2, n, bPre[i].z); CVT_B(k + 3, n, bPre[i].w);         \
            }                                                                   \
        }                                                                       \
    }

#define COMPUTE()                                                               \
    {                                                                           \
        _Pragma("unroll")                                                       \
        for (int kk = 0; kk < TBK; kk += 16) {                                  \
            uint32_t Ah[4][4], Al[4][4], Bh[4][2], Bl[4][2];                    \
            _Pragma("unroll")                                                   \
            for (int i = 0; i < 4; i++) {                                       \
                int row = wm * 64 + i * 16 + (lane & 15);                       \
                int col = kk + ((lane >> 4) << 3);                              \
                ldsm_x4(Ah[i][0], Ah[i][1], Ah[i][2], Ah[i][3],                 \
                        smem_u32(&As[0][row][col]));                            \
                ldsm_x4(Al[i][0], Al[i][1], Al[i][2], Al[i][3],                 \
                        smem_u32(&As[1][row][col]));                            \
            }                                                                   \
            _Pragma("unroll")                                                   \
            for (int t = 0; t < 2; t++) {                                       \
                int row = kk + (lane & 15);                                     \
                int col = wn * 32 + t * 16 + ((lane >> 4) << 3);                \
                uint32_t r0, r1, r2, r3;                                        \
                ldsm_x4_t(r0, r1, r2, r3, smem_u32(&Bs[0][row][col]));          \
                Bh[t*2][0] = r0; Bh[t*2][1] = r1;                               \
                Bh[t*2+1][0] = r2; Bh[t*2+1][1] = r3;                           \
                ldsm_x4_t(r0, r1, r2, r3, smem_u32(&Bs[1][row][col]));          \
                Bl[t*2][0] = r0; Bl[t*2][1] = r1;                               \
                Bl[t*2+1][0] = r2; Bl[t*2+1][1] = r3;                           \
            }                                                                   \
            _Pragma("unroll")                                                   \
            for (int i = 0; i < 4; i++)                                         \
                _Pragma("unroll")                                               \
                for (int j = 0; j < 4; j++) {                                   \
                    mma_bf16(acc[i][j], Ah[i], Bh[j]);                          \
                    mma_bf16(acc[i][j], Ah[i], Bl[j]);                          \
                    mma_bf16(acc[i][j], Al[i], Bh[j]);                          \
                }                                                               \
        }                                                                       \
    }

    const int ktiles = (K + TBK - 1) / TBK;

    LOAD_REGS(0);
    STORE_SMEM();
    __syncthreads();

    for (int t = 0; t < ktiles; t++) {
        bool last = (t == ktiles - 1);
        if (!last) LOAD_REGS((t + 1) * TBK);
        COMPUTE();
        if (!last) {
            __syncthreads();
            STORE_SMEM();
            __syncthreads();
        }
    }

    const int g  = lane >> 2;
    const int tg = lane & 3;
#pragma unroll
    for (int i = 0; i < 4; i++) {
        int r0w = m0 + wm * 64 + i * 16 + g;
        int r1w = r0w + 8;
#pragma unroll
        for (int j = 0; j < 4; j++) {
            int c0 = n0 + wn * 32 + j * 8 + tg * 2;
            if (c0 < N) {
                if (r0w < M) {
                    float2 v = make_float2(alpha * acc[i][j][0], alpha * acc[i][j][1]);
                    *(float2*)&C[(long long)r0w * ldc + c0] = v;
                }
                if (r1w < M) {
                    float2 v = make_float2(alpha * acc[i][j][2], alpha * acc[i][j][3]);
                    *(float2*)&C[(long long)r1w * ldc + c0] = v;
                }
            }
        }
    }
#undef LOAD_REGS
#undef STORE_SMEM
#undef COMPUTE
#undef CVT_A
#undef CVT_B
}

// ---------------------------------------------------------------------------
// Fused attention stats (one branch): per z=(b,h) read logits once, produce
// per-row max and instance-norm gain (mean shift cancels in softmax).
// ---------------------------------------------------------------------------
__global__ __launch_bounds__(256)
void attn_stats_kernel(const float* __restrict__ attn,
                       float* __restrict__ rm, float* __restrict__ gn)
{
    int z = blockIdx.x;           // 0..127 = b*4+h
    const float* X = attn + (long long)z * 153664;
    int warp = threadIdx.x >> 5, lane = threadIdx.x & 31;
    float s = 0.f, s2 = 0.f;
    for (int r = warp; r < 196; r += 8) {
        const float* row = X + (long long)r * 784;
        float m = -1e30f;
        for (int c = lane; c < 784; c += 32) {
            float v = row[c];
            m = fmaxf(m, v); s += v; s2 += v * v;
        }
#pragma unroll
        for (int o = 16; o; o >>= 1) m = fmaxf(m, __shfl_xor_sync(~0u, m, o));
        if (lane == 0) rm[(long long)z * 196 + r] = m;
    }
    __shared__ float rs[256], rs2[256];
    rs[threadIdx.x] = s; rs2[threadIdx.x] = s2; __syncthreads();
    for (int t = 128; t; t >>= 1) {
        if (threadIdx.x < t) {
            rs[threadIdx.x]  += rs[threadIdx.x + t];
            rs2[threadIdx.x] += rs2[threadIdx.x + t];
        }
        __syncthreads();
    }
    if (threadIdx.x == 0) {
        float mean = rs[0] / 153664.f;
        float var  = rs2[0] / 153664.f - mean * mean;
        gn[z] = rsqrtf(var + 1e-5f);
    }
}

// ---------------------------------------------------------------------------
// Fused exp-softmax + P@V GEMM (one branch).  M=196, N=64, K=784 per z (128).
// p = exp(g*(x - rowmax)); denominator accumulated in smem (each block spans
// all of K); epilogue divides.  TBN=64, 4x2 warp layout.
// ---------------------------------------------------------------------------
__global__ __launch_bounds__(256)
void attn_pv_kernel(const float* __restrict__ attn, const float* __restrict__ V,
                    float* __restrict__ ctx,
                    const float* __restrict__ rm, const float* __restrict__ gn)
{
    const int Mv = 196, Kv = 784;
    int z = blockIdx.z;               // 0..127 = b*4+h
    int bb = z >> 2, hh = z & 3;
    const float* A = attn + (long long)bb * 614656 + (long long)hh * 153664;
    const float* B = V    + (long long)bb * 200704 + hh * 64;
    float*       C = ctx  + (long long)bb * 50176  + hh * 64;
    const float  gv  = gn[z];
    const float* rmz = rm + (long long)z * 196;

    __shared__ __align__(16) __nv_bfloat16 As[2][128][TBK + APAD];
    __shared__ __align__(16) __nv_bfloat16 Bs[2][TBK][64 + BPAD];
    __shared__ float sden[128];

    const int tid  = threadIdx.x;
    const int lane = tid & 31;
    const int wid  = tid >> 5;
    const int wm   = wid >> 1;   // 0..3 : 32 rows each
    const int wn   = wid & 1;    // 0..1 : 32 cols each
    const int m0 = blockIdx.y * 128;

    if (tid < 128) sden[tid] = 0.f;

    float acc[2][4][4];
#pragma unroll
    for (int i = 0; i < 2; i++)
#pragma unroll
        for (int j = 0; j < 4; j++)
#pragma unroll
            for (int r = 0; r < 4; r++) acc[i][j][r] = 0.f;

    const int ar  = tid >> 3, ac4 = tid & 7;   // A: 32 rows/pass, 8 f4/row
    const int brr = tid >> 4, bc4 = tid & 15;  // B: 16 rows/pass, 16 f4/row

    float4 aPre[4], bPre[2];
    int k0s = 0;

#define PV_LOAD(K0)                                                             \
    {                                                                           \
        int k0_ = (K0);                                                         \
        _Pragma("unroll")                                                       \
        for (int i = 0; i < 4; i++) {                                           \
            int gm = m0 + ar + i * 32, gk = k0_ + ac4 * 4;                      \
            aPre[i] = (gm < Mv && gk < Kv)                                      \
                ? *(const float4*)&A[(long long)gm * 784 + gk]                  \
                : make_float4(0.f, 0.f, 0.f, 0.f);                              \
        }                                                                       \
        _Pragma("unroll")                                                       \
        for (int i = 0; i < 2; i++) {                                           \
            int gk = k0_ + brr + i * 16;                                        \
            bPre[i] = (gk < Kv)                                                 \
                ? *(const float4*)&B[(long long)gk * 256 + bc4 * 4]             \
                : make_float4(0.f, 0.f, 0.f, 0.f);                              \
        }                                                                       \
        k0s = k0_;                                                              \
    }

#define PV_CVT_A(dr, dc, f)                                                     \
    {                                                                           \
        __nv_bfloat16 hi_ = __float2bfloat16(f);                                \
        As[0][dr][dc] = hi_;                                                    \
        As[1][dr][dc] = __float2bfloat16((f) - __bfloat162float(hi_));          \
    }
#define PV_CVT_B(dr, dc, f)                                                     \
    {                                                                           \
        __nv_bfloat16 hi_ = __float2bfloat16(f);                                \
        Bs[0][dr][dc] = hi_;                                                    \
        Bs[1][dr][dc] = __float2bfloat16((f) - __bfloat162float(hi_));          \
    }

#define PV_STORE()                                                              \
    {                                                                           \
        _Pragma("unroll")                                                       \
        for (int i = 0; i < 4; i++) {                                           \
            int m = ar + i * 32, gm = m0 + m;                                   \
            bool rok = (gm < Mv);                                               \
            float rmv = rok ? rmz[gm] : 0.f;                                    \
            float part = 0.f;                                                   \
            float vv[4] = { aPre[i].x, aPre[i].y, aPre[i].z, aPre[i].w };       \
            _Pragma("unroll")                                                   \
            for (int cc = 0; cc < 4; cc++) {                                    \
                int gk = k0s + ac4 * 4 + cc;                                    \
                float e = (rok && gk < Kv) ? __expf(gv * (vv[cc] - rmv)) : 0.f; \
                part += e;                                                      \
                PV_CVT_A(m, ac4 * 4 + cc, e);                                   \
            }                                                                   \
            if (part != 0.f) atomicAdd(&sden[m], part);                         \
        }                                                                       \
        _Pragma("unroll")                                                       \
        for (int i = 0; i < 2; i++) {                                           \
            int k = brr + i * 16, c = bc4 * 4;                                  \
            PV_CVT_B(k, c + 0, bPre[i].x); PV_CVT_B(k, c + 1, bPre[i].y);       \
            PV_CVT_B(k, c + 2, bPre[i].z); PV_CVT_B(k, c + 3, bPre[i].w);       \
        }                                                                       \
    }

    const int ktiles = (Kv + TBK - 1) / TBK;   // 25

    PV_LOAD(0);
    __syncthreads();           // sden init visible before first atomicAdd
    PV_STORE();
    __syncthreads();

    for (int t = 0; t < ktiles; t++) {
        bool last = (t == ktiles - 1);
        if (!last) PV_LOAD((t + 1) * TBK);
#pragma unroll
        for (int kk = 0; kk < TBK; kk += 16) {
            uint32_t Ah[2][4], Al[2][4], Bh[4][2], Bl[4][2];
#pragma unroll
            for (int i = 0; i < 2; i++) {
                int row = wm * 32 + i * 16 + (lane & 15);
                int col = kk + ((lane >> 4) << 3);
                ldsm_x4(Ah[i][0], Ah[i][1], Ah[i][2], Ah[i][3],
                        smem_u32(&As[0][row][col]));
                ldsm_x4(Al[i][0], Al[i][1], Al[i][2], Al[i][3],
                        smem_u32(&As[1][row][col]));
            }
            {
                int row = kk + (lane & 15);
                int col = wn * 32 + ((lane >> 4) << 3);
                uint32_t r0, r1, r2, r3;
                ldsm_x4_t(r0, r1, r2, r3, smem_u32(&Bs[0][row][col]));
                Bh[0][0] = r0; Bh[0][1] = r1; Bh[1][0] = r2; Bh[1][1] = r3;
                ldsm_x4_t(r0, r1, r2, r3, smem_u32(&Bs[0][row][col + 16]));
                Bh[2][0] = r0; Bh[2][1] = r1; Bh[3][0] = r2; Bh[3][1] = r3;
                ldsm_x4_t(r0, r1, r2, r3, smem_u32(&Bs[1][row][col]));
                Bl[0][0] = r0; Bl[0][1] = r1; Bl[1][0] = r2; Bl[1][1] = r3;
                ldsm_x4_t(r0, r1, r2, r3, smem_u32(&Bs[1][row][col + 16]));
                Bl[2][0] = r0; Bl[2][1] = r1; Bl[3][0] = r2; Bl[3][1] = r3;
            }
#pragma unroll
            for (int i = 0; i < 2; i++)
#pragma unroll
                for (int j = 0; j < 4; j++) {
                    mma_bf16(acc[i][j], Ah[i], Bh[j]);
                    mma_bf16(acc[i][j], Ah[i], Bl[j]);
                    mma_bf16(acc[i][j], Al[i], Bh[j]);
                }
        }
        if (!last) {
            __syncthreads();
            PV_STORE();
            __syncthreads();
        }
    }

    const int g  = lane >> 2;
    const int tg = lane & 3;
#pragma unroll
    for (int i = 0; i < 2; i++) {
        int lr0 = wm * 32 + i * 16 + g;
        int lr1 = lr0 + 8;
        int r0w = m0 + lr0, r1w = m0 + lr1;
        float d0 = (r0w < Mv) ? 1.0f / sden[lr0] : 0.f;
        float d1 = (r1w < Mv) ? 1.0f / sden[lr1] : 0.f;
#pragma unroll
        for (int j = 0; j < 4; j++) {
            int c0 = wn * 32 + j * 8 + tg * 2;
            if (r0w < Mv) {
                float2 v = make_float2(acc[i][j][0] * d0, acc[i][j][1] * d0);
                *(float2*)&C[(long long)r0w * 256 + c0] = v;
            }
            if (r1w < Mv) {
                float2 v = make_float2(acc[i][j][2] * d1, acc[i][j][3] * d1);
                *(float2*)&C[(long long)r1w * 256 + c0] = v;
            }
        }
    }
#undef PV_LOAD
#undef PV_STORE
#undef PV_CVT_A
#undef PV_CVT_B
}

// ---------------------------------------------------------------------------
// Small helpers
// ---------------------------------------------------------------------------
__global__ void transpose_kernel(const float* __restrict__ src, float* __restrict__ dst,
                                 int M, int N)
{
    __shared__ float t[32][33];
    int x = blockIdx.x * 32 + threadIdx.x;
    int y0 = blockIdx.y * 32 + threadIdx.y;
#pragma unroll
    for (int i = 0; i < 32; i += 8) {
        int y = y0 + i;
        t[threadIdx.y + i][threadIdx.x] = (y < M && x < N) ? src[(long long)y * N + x] : 0.f;
    }
    __syncthreads();
    int xo = blockIdx.y * 32 + threadIdx.x;
    int yo0 = blockIdx.x * 32 + threadIdx.y;
#pragma unroll
    for (int i = 0; i < 32; i += 8) {
        int yo = yo0 + i;
        if (yo < N && xo < M) dst[(long long)yo * M + xo] = t[threadIdx.x][threadIdx.y + i];
    }
}

// KV_S[b, j*196+t, c] = T_hat[b, t, j*256 + c]
__global__ void kvs_kernel(const float* __restrict__ T, float* __restrict__ KVS)
{
    long long i = (long long)blockIdx.x * blockDim.x + threadIdx.x;
    if (i >= SZ_BNDC) return;
    int c = (int)(i & 255);
    long long t2 = i >> 8;
    int n = (int)(t2 % 784);
    int b = (int)(t2 / 784);
    int j = n / 196, t = n % 196;
    KVS[i] = T[((long long)b * 196 + t) * 1024 + (long long)j * 256 + c];
}

// Plain row softmax (SATAT scores, 196 cols)
__global__ void softmax_kernel(float* __restrict__ X, int cols)
{
    int row = blockIdx.x;
    float* x = X + (long long)row * cols;
    int tid = threadIdx.x;
    __shared__ float red[256];

    float m = -1e30f;
    for (int c = tid; c < cols; c += 256) m = fmaxf(m, x[c]);
    red[tid] = m; __syncthreads();
    for (int s = 128; s > 0; s >>= 1) {
        if (tid < s) red[tid] = fmaxf(red[tid], red[tid + s]);
        __syncthreads();
    }
    m = red[0]; __syncthreads();

    float sum = 0.f;
    for (int c = tid; c < cols; c += 256) {
        float e = __expf(x[c] - m);
        x[c] = e; sum += e;
    }
    red[tid] = sum; __syncthreads();
    for (int s = 128; s > 0; s >>= 1) {
        if (tid < s) red[tid] += red[tid + s];
        __syncthreads();
    }
    float inv = 1.0f / red[0];
    for (int c = tid; c < cols; c += 256) x[c] *= inv;
}

// ---------------------------------------------------------------------------
// Host-side driver
// ---------------------------------------------------------------------------
static inline void gemm(int tb,
                        const float* A, const float* B, float* C,
                        int M, int N, int K, int lda, int ldb, int ldc,
                        long long sAb, long long sAh,
                        long long sBb, long long sBh,
                        long long sCb, long long sCh,
                        int batch, int nh, float alpha)
{
    dim3 g((N + TBN - 1) / TBN, (M + TBM - 1) / TBM, batch), b(256);
    if (tb)
        gemm_mma<true><<<g, b>>>(A, B, C, M, N, K, lda, ldb, ldc,
                                 sAb, sAh, sBb, sBh, sCb, sCh, nh, alpha);
    else
        gemm_mma<false><<<g, b>>>(A, B, C, M, N, K, lda, ldb, ldc,
                                  sAb, sAh, sBb, sBh, sCb, sCh, nh, alpha);
}

extern "C" void kernel_launch(void* const* d_in, const int* in_sizes, int n_in,
                              void* d_out, int out_size)
{
    const float* emb[4] = { (const float*)d_in[0], (const float*)d_in[1],
                            (const float*)d_in[2], (const float*)d_in[3] };
    const float* emb_C = (const float*)d_in[4];
    const float* Wq_c  = (const float*)d_in[5];
    const float* Wk_c  = (const float*)d_in[6];
    const float* Wv_c  = (const float*)d_in[7];
    const float* Wo_c  = (const float*)d_in[8];
    const float* Wq[4] = { (const float*)d_in[9],  (const float*)d_in[10],
                           (const float*)d_in[11], (const float*)d_in[12] };
    const float* Wk    = (const float*)d_in[13];
    const float* Wv    = (const float*)d_in[14];
    const float* Wo[4] = { (const float*)d_in[15], (const float*)d_in[16],
                           (const float*)d_in[17], (const float*)d_in[18] };
    float* out = (float*)d_out;

    float *q3, *k3, *v3, *sc, *oat, *that, *kvs, *Kb, *Vb, *Qb, *attn, *ctx;
    float *gain, *rowmax, *WkT, *WvT, *WqT;
    cudaGetSymbolAddress((void**)&q3,    g_q3);
    cudaGetSymbolAddress((void**)&k3,    g_k3);
    cudaGetSymbolAddress((void**)&v3,    g_v3);
    cudaGetSymbolAddress((void**)&sc,    g_sc);
    cudaGetSymbolAddress((void**)&oat,   g_oat);
    cudaGetSymbolAddress((void**)&that,  g_that);
    cudaGetSymbolAddress((void**)&kvs,   g_kvs);
    cudaGetSymbolAddress((void**)&Kb,    g_Kb);
    cudaGetSymbolAddress((void**)&Vb,    g_Vb);
    cudaGetSymbolAddress((void**)&Qb,    g_Qb);
    cudaGetSymbolAddress((void**)&attn,  g_attn);
    cudaGetSymbolAddress((void**)&ctx,   g_ctx);
    cudaGetSymbolAddress((void**)&gain,  g_gain);
    cudaGetSymbolAddress((void**)&rowmax,g_rowmax);
    cudaGetSymbolAddress((void**)&WkT,   g_WkT);
    cudaGetSymbolAddress((void**)&WvT,   g_WvT);
    cudaGetSymbolAddress((void**)&WqT,   g_WqT);

    // ---------------- Weight pre-transposes ----------------
    {
        dim3 b(32, 8);
        dim3 g784((784 + 31) / 32, (784 + 31) / 32);
        transpose_kernel<<<g784, b>>>(Wk, WkT, 784, 784);
        transpose_kernel<<<g784, b>>>(Wv, WvT, 784, 784);
        dim3 g196((196 + 31) / 32, (196 + 31) / 32);
        for (int i = 0; i < 4; i++)
            transpose_kernel<<<g196, b>>>(Wq[i], WqT + (long long)i * 38416, 196, 196);
    }

    // ---------------- Stage A: SATAT over emb_C ----------------
    gemm(0, emb_C, Wq_c, q3, 6272, 1024, 1024, 1024, 1024, 1024,
         0, 0, 0, 0, 0, 0, 1, 1, 1.0f);
    gemm(0, emb_C, Wk_c, k3, 6272, 1024, 1024, 1024, 1024, 1024,
         0, 0, 0, 0, 0, 0, 1, 1, 1.0f);
    gemm(0, emb_C, Wv_c, v3, 6272, 1024, 1024, 1024, 1024, 1024,
         0, 0, 0, 0, 0, 0, 1, 1, 1.0f);
    gemm(1, q3, k3, sc, 196, 196, 256, 1024, 1024, 196,
         200704, 256, 200704, 256, 153664, 38416, 128, 4, 0.0625f);
    softmax_kernel<<<25088, 256>>>(sc, 196);
    gemm(0, sc, v3, oat, 196, 256, 196, 196, 1024, 1024,
         153664, 38416, 200704, 256, 200704, 256, 128, 4, 1.0f);
    gemm(0, oat, Wo_c, that, 6272, 1024, 1024, 1024, 1024, 1024,
         0, 0, 0, 0, 0, 0, 1, 1, 1.0f);

    // ---------------- Stage B: KV token mix ----------------
    kvs_kernel<<<(unsigned)((SZ_BNDC + 255) / 256), 256>>>(that, kvs);
    gemm(0, WkT, kvs, Kb, 784, 256, 784, 784, 256, 256,
         0, 0, 200704, 0, 200704, 0, 32, 1, 1.0f);
    gemm(0, WvT, kvs, Vb, 784, 256, 784, 784, 256, 256,
         0, 0, 200704, 0, 200704, 0, 32, 1, 1.0f);

    // ---------------- Stage C: 4 query branches ----------------
    for (int br = 0; br < 4; br++) {
        // Q[b] = WqT @ emb[b]
        gemm(0, WqT + (long long)br * 38416, emb[br], Qb, 196, 256, 196, 196, 256, 256,
             0, 0, 50176, 0, 50176, 0, 32, 1, 1.0f);
        // attn[b,h] = Qh @ Kh^T : NT
        gemm(1, Qb, Kb, attn, 196, 784, 64, 256, 256, 784,
             50176, 64, 200704, 64, 614656, 153664, 128, 4, 1.0f);
        // one-pass stats: per-(b,h) gain + per-row max
        attn_stats_kernel<<<128, 256>>>(attn, rowmax, gain);
        // fused exp-softmax + P@V with in-block denominator
        {
            dim3 g(1, 2, 128), b(256);
            attn_pv_kernel<<<g, b>>>(attn, Vb, ctx, rowmax, gain);
        }
        // O = ctx @ Wo
        gemm(0, ctx, Wo[br], out + (long long)br * SZ_Q,
             6272, 256, 256, 256, 256, 256,
             0, 0, 0, 0, 0, 0, 1, 1, 1.0f);
    }
}

// round 7
// speedup vs baseline: 3.8933x; 1.1597x over previous
#include <cuda_runtime.h>
#include <cuda_bf16.h>
#include <cstdint>

// ---------------------------------------------------------------------------
// Problem constants: B=32, N=196, DQ=256, DC=1024, H=4, DH=64, DHC=256, 4N=784
// ---------------------------------------------------------------------------

#define SZ_BNDC   6422528LL   // 32*196*1024  (also 32*784*256)
#define SZ_SC     4917248LL   // 32*4*196*196
#define SZ_Q      1605632LL   // 32*196*256
#define SZ_ATTN  19668992LL   // 32*4*196*784 (one branch)

// Scratch (device .bss, allocation-free) — identical footprint to the
// known-good round-5 kernel (~322 MB).
__device__ float g_q3[SZ_BNDC];
__device__ float g_k3[SZ_BNDC];
__device__ float g_v3[SZ_BNDC];
__device__ float g_sc[SZ_SC];
__device__ float g_oat[SZ_BNDC];
__device__ float g_that[SZ_BNDC];
__device__ float g_kvs[SZ_BNDC];
__device__ float g_Kb[SZ_BNDC];
__device__ float g_Vb[SZ_BNDC];
__device__ float g_Qb[SZ_Q];
__device__ float g_attn[SZ_ATTN];
__device__ float g_ctx[SZ_Q];
__device__ float g_gain[128];
__device__ float g_rowmax[128 * 196];
__device__ float g_WkT[614656];       // 784*784
__device__ float g_WvT[614656];
__device__ float g_WqT[4 * 38416];    // 4 * 196*196

// ---------------------------------------------------------------------------
// PTX helpers
// ---------------------------------------------------------------------------
__device__ __forceinline__ uint32_t smem_u32(const void* p) {
    return (uint32_t)__cvta_generic_to_shared(p);
}

__device__ __forceinline__ void ldsm_x4(uint32_t& r0, uint32_t& r1,
                                        uint32_t& r2, uint32_t& r3, uint32_t addr) {
    asm volatile("ldmatrix.sync.aligned.m8n8.x4.shared.b16 {%0,%1,%2,%3},[%4];"
                 : "=r"(r0), "=r"(r1), "=r"(r2), "=r"(r3) : "r"(addr));
}

__device__ __forceinline__ void ldsm_x4_t(uint32_t& r0, uint32_t& r1,
                                          uint32_t& r2, uint32_t& r3, uint32_t addr) {
    asm volatile("ldmatrix.sync.aligned.m8n8.x4.trans.shared.b16 {%0,%1,%2,%3},[%4];"
                 : "=r"(r0), "=r"(r1), "=r"(r2), "=r"(r3) : "r"(addr));
}

__device__ __forceinline__ void mma_bf16(float* c, const uint32_t* a, const uint32_t* b) {
    asm volatile("mma.sync.aligned.m16n8k16.row.col.f32.bf16.bf16.f32 "
                 "{%0,%1,%2,%3},{%4,%5,%6,%7},{%8,%9},{%0,%1,%2,%3};"
                 : "+f"(c[0]), "+f"(c[1]), "+f"(c[2]), "+f"(c[3])
                 : "r"(a[0]), "r"(a[1]), "r"(a[2]), "r"(a[3]),
                   "r"(b[0]), "r"(b[1]));
}

// ---------------------------------------------------------------------------
// Tile geometry: 128x128 block tile, TBK=16, double-buffered STATIC smem.
// ---------------------------------------------------------------------------
#define TBM 128
#define TBN 128
#define TBK 16
#define A_STRIDE 24                 // TBK + 8 pad
#define B_STRIDE 136                // TBN + 8 pad
#define PVB_STRIDE 72               // 64 + 8 pad

// ---------------------------------------------------------------------------
// Tensor-core batched GEMM, split-bf16 (3 MMA) fp32 emulation.
// Double-buffered static smem: one __syncthreads per 16-k tile; the smem
// fill of tile t+1 overlaps other warps' MMAs on tile t.
//   C = alpha * A @ op(B);  A [M,K] row-major.
//   TB=false: B [K,N] row-major.  TB=true: B [N,K] row-major.
// Batch: z = bb*nh + hh, pointer offsets sXb/sXh.
// ---------------------------------------------------------------------------
template<bool TB>
__global__ __launch_bounds__(256)
void gemm_mma(const float* __restrict__ A, const float* __restrict__ B,
              float* __restrict__ C,
              int M, int N, int K, int lda, int ldb, int ldc,
              long long sAb, long long sAh, long long sBb, long long sBh,
              long long sCb, long long sCh, int nh, float alpha)
{
    int z  = blockIdx.z;
    int bb = z / nh, hh = z % nh;
    A += bb * sAb + hh * sAh;
    B += bb * sBb + hh * sBh;
    C += bb * sCb + hh * sCh;

    __shared__ __align__(16) __nv_bfloat16 As[2][2][TBM][A_STRIDE];  // 24.0 KB
    __shared__ __align__(16) __nv_bfloat16 Bs[2][2][TBK][B_STRIDE];  // 17.0 KB

    const int tid  = threadIdx.x;
    const int lane = tid & 31;
    const int wid  = tid >> 5;
    const int wm   = wid >> 2;
    const int wn   = wid & 3;
    const int m0 = blockIdx.y * TBM, n0 = blockIdx.x * TBN;

    float acc[4][4][4];
#pragma unroll
    for (int i = 0; i < 4; i++)
#pragma unroll
        for (int j = 0; j < 4; j++)
#pragma unroll
            for (int r = 0; r < 4; r++) acc[i][j][r] = 0.f;

    const int ar  = tid >> 2, ac4 = tid & 3;    // A: 64 rows/pass, 4 f4/row
    const int bkr = tid >> 5, bc4 = tid & 31;   // B NN: 8 k-rows/pass, 32 f4/row
    const int bnr = tid >> 2, bk4 = tid & 3;    // B NT: 64 n-rows/pass, 4 f4/row

    float4 aPre[2], bPre[2];

#define LOAD_REGS(K0)                                                           \
    {                                                                           \
        int k0_ = (K0);                                                         \
        _Pragma("unroll")                                                       \
        for (int i = 0; i < 2; i++) {                                           \
            int gm = m0 + ar + i * 64, gk = k0_ + ac4 * 4;                      \
            aPre[i] = (gm < M && gk < K)                                        \
                ? *(const float4*)&A[(long long)gm * lda + gk]                  \
                : make_float4(0.f, 0.f, 0.f, 0.f);                              \
        }                                                                       \
        if (!TB) {                                                              \
            _Pragma("unroll")                                                   \
            for (int i = 0; i < 2; i++) {                                       \
                int gk = k0_ + bkr + i * 8, gn = n0 + bc4 * 4;                  \
                bPre[i] = (gk < K && gn < N)                                    \
                    ? *(const float4*)&B[(long long)gk * ldb + gn]              \
                    : make_float4(0.f, 0.f, 0.f, 0.f);                          \
            }                                                                   \
        } else {                                                                \
            _Pragma("unroll")                                                   \
            for (int i = 0; i < 2; i++) {                                       \
                int gn = n0 + bnr + i * 64, gk = k0_ + bk4 * 4;                 \
                bPre[i] = (gn < N && gk < K)                                    \
                    ? *(const float4*)&B[(long long)gn * ldb + gk]              \
                    : make_float4(0.f, 0.f, 0.f, 0.f);                          \
            }                                                                   \
        }                                                                       \
    }

#define CVT_A(s, dr, dc, f)                                                     \
    {                                                                           \
        __nv_bfloat16 hi_ = __float2bfloat16(f);                                \
        As[s][0][dr][dc] = hi_;                                                 \
        As[s][1][dr][dc] = __float2bfloat16((f) - __bfloat162float(hi_));       \
    }
#define CVT_B(s, dr, dc, f)                                                     \
    {                                                                           \
        __nv_bfloat16 hi_ = __float2bfloat16(f);                                \
        Bs[s][0][dr][dc] = hi_;                                                 \
        Bs[s][1][dr][dc] = __float2bfloat16((f) - __bfloat162float(hi_));       \
    }

#define STORE_SMEM(s)                                                           \
    {                                                                           \
        _Pragma("unroll")                                                       \
        for (int i = 0; i < 2; i++) {                                           \
            int m = ar + i * 64, c = ac4 * 4;                                   \
            CVT_A(s, m, c + 0, aPre[i].x); CVT_A(s, m, c + 1, aPre[i].y);       \
            CVT_A(s, m, c + 2, aPre[i].z); CVT_A(s, m, c + 3, aPre[i].w);       \
        }                                                                       \
        if (!TB) {                                                              \
            _Pragma("unroll")                                                   \
            for (int i = 0; i < 2; i++) {                                       \
                int k = bkr + i * 8, c = bc4 * 4;                               \
                CVT_B(s, k, c + 0, bPre[i].x); CVT_B(s, k, c + 1, bPre[i].y);   \
                CVT_B(s, k, c + 2, bPre[i].z); CVT_B(s, k, c + 3, bPre[i].w);   \
            }                                                                   \
        } else {                                                                \
            _Pragma("unroll")                                                   \
            for (int i = 0; i < 2; i++) {                                       \
                int n = bnr + i * 64, k = bk4 * 4;                              \
                CVT_B(s, k + 0, n, bPre[i].x); CVT_B(s, k + 1, n, bPre[i].y);   \
                CVT_B(s, k + 2, n, bPre[i].z); CVT_B(s, k + 3, n, bPre[i].w);   \
            }                                                                   \
        }                                                                       \
    }

#define COMPUTE(s)                                                              \
    {                                                                           \
        uint32_t Ah[4][4], Al[4][4], Bh[4][2], Bl[4][2];                        \
        _Pragma("unroll")                                                       \
        for (int i = 0; i < 4; i++) {                                           \
            int row = wm * 64 + i * 16 + (lane & 15);                           \
            int col = (lane >> 4) << 3;                                         \
            ldsm_x4(Ah[i][0], Ah[i][1], Ah[i][2], Ah[i][3],                     \
                    smem_u32(&As[s][0][row][col]));                             \
            ldsm_x4(Al[i][0], Al[i][1], Al[i][2], Al[i][3],                     \
                    smem_u32(&As[s][1][row][col]));                             \
        }                                                                       \
        _Pragma("unroll")                                                       \
        for (int t2 = 0; t2 < 2; t2++) {                                        \
            int row = lane & 15;                                                \
            int col = wn * 32 + t2 * 16 + ((lane >> 4) << 3);                   \
            uint32_t r0, r1, r2, r3;                                            \
            ldsm_x4_t(r0, r1, r2, r3, smem_u32(&Bs[s][0][row][col]));           \
            Bh[t2*2][0] = r0; Bh[t2*2][1] = r1;                                 \
            Bh[t2*2+1][0] = r2; Bh[t2*2+1][1] = r3;                             \
            ldsm_x4_t(r0, r1, r2, r3, smem_u32(&Bs[s][1][row][col]));           \
            Bl[t2*2][0] = r0; Bl[t2*2][1] = r1;                                 \
            Bl[t2*2+1][0] = r2; Bl[t2*2+1][1] = r3;                             \
        }                                                                       \
        _Pragma("unroll")                                                       \
        for (int i = 0; i < 4; i++)                                             \
            _Pragma("unroll")                                                   \
            for (int j = 0; j < 4; j++) {                                       \
                mma_bf16(acc[i][j], Ah[i], Bh[j]);                              \
                mma_bf16(acc[i][j], Ah[i], Bl[j]);                              \
                mma_bf16(acc[i][j], Al[i], Bh[j]);                              \
            }                                                                   \
    }

    const int ktiles = (K + TBK - 1) / TBK;

    LOAD_REGS(0);
    STORE_SMEM(0);
    __syncthreads();

    for (int t = 0; t < ktiles; t++) {
        const int cur = t & 1;
        bool last = (t == ktiles - 1);
        if (!last) LOAD_REGS((t + 1) * TBK);
        COMPUTE(cur);
        if (!last) {
            STORE_SMEM(cur ^ 1);      // other stage: prior sync drained its readers
            __syncthreads();
        }
    }

    const int g  = lane >> 2;
    const int tg = lane & 3;
#pragma unroll
    for (int i = 0; i < 4; i++) {
        int r0w = m0 + wm * 64 + i * 16 + g;
        int r1w = r0w + 8;
#pragma unroll
        for (int j = 0; j < 4; j++) {
            int c0 = n0 + wn * 32 + j * 8 + tg * 2;
            if (c0 < N) {
                if (r0w < M) {
                    float2 v = make_float2(alpha * acc[i][j][0], alpha * acc[i][j][1]);
                    *(float2*)&C[(long long)r0w * ldc + c0] = v;
                }
                if (r1w < M) {
                    float2 v = make_float2(alpha * acc[i][j][2], alpha * acc[i][j][3]);
                    *(float2*)&C[(long long)r1w * ldc + c0] = v;
                }
            }
        }
    }
#undef LOAD_REGS
#undef STORE_SMEM
#undef COMPUTE
#undef CVT_A
#undef CVT_B
}

// ---------------------------------------------------------------------------
// Fused attention stats (one branch): per z=(b,h) read logits once, produce
// per-row max and instance-norm gain (mean shift cancels in softmax).
// ---------------------------------------------------------------------------
__global__ __launch_bounds__(256)
void attn_stats_kernel(const float* __restrict__ attn,
                       float* __restrict__ rm, float* __restrict__ gn)
{
    int z = blockIdx.x;           // 0..127 = b*4+h
    const float* X = attn + (long long)z * 153664;
    int warp = threadIdx.x >> 5, lane = threadIdx.x & 31;
    float s = 0.f, s2 = 0.f;
    for (int r = warp; r < 196; r += 8) {
        const float* row = X + (long long)r * 784;
        float m = -1e30f;
        for (int c = lane; c < 784; c += 32) {
            float v = row[c];
            m = fmaxf(m, v); s += v; s2 += v * v;
        }
#pragma unroll
        for (int o = 16; o; o >>= 1) m = fmaxf(m, __shfl_xor_sync(~0u, m, o));
        if (lane == 0) rm[(long long)z * 196 + r] = m;
    }
    __shared__ float rs[256], rs2[256];
    rs[threadIdx.x] = s; rs2[threadIdx.x] = s2; __syncthreads();
    for (int t = 128; t; t >>= 1) {
        if (threadIdx.x < t) {
            rs[threadIdx.x]  += rs[threadIdx.x + t];
            rs2[threadIdx.x] += rs2[threadIdx.x + t];
        }
        __syncthreads();
    }
    if (threadIdx.x == 0) {
        float mean = rs[0] / 153664.f;
        float var  = rs2[0] / 153664.f - mean * mean;
        gn[z] = rsqrtf(var + 1e-5f);
    }
}

// ---------------------------------------------------------------------------
// Fused exp-softmax + P@V GEMM (one branch).  M=196, N=64, K=784 per z (128).
// p = exp(g*(x - rowmax)); denominator accumulated in smem (each block spans
// all of K); epilogue divides.  TBN=64, TBK=16, double-buffered static smem.
// ---------------------------------------------------------------------------
__global__ __launch_bounds__(256)
void attn_pv_kernel(const float* __restrict__ attn, const float* __restrict__ V,
                    float* __restrict__ ctx,
                    const float* __restrict__ rm, const float* __restrict__ gn)
{
    const int Mv = 196, Kv = 784;
    int z = blockIdx.z;               // 0..127 = b*4+h
    int bb = z >> 2, hh = z & 3;
    const float* A = attn + (long long)bb * 614656 + (long long)hh * 153664;
    const float* B = V    + (long long)bb * 200704 + hh * 64;
    float*       C = ctx  + (long long)bb * 50176  + hh * 64;
    const float  gv  = gn[z];
    const float* rmz = rm + (long long)z * 196;

    __shared__ __align__(16) __nv_bfloat16 As[2][2][128][A_STRIDE];    // 24 KB
    __shared__ __align__(16) __nv_bfloat16 Bs[2][2][TBK][PVB_STRIDE];  // 9 KB
    __shared__ float sden[128];

    const int tid  = threadIdx.x;
    const int lane = tid & 31;
    const int wid  = tid >> 5;
    const int wm   = wid >> 1;   // 0..3 : 32 rows each
    const int wn   = wid & 1;    // 0..1 : 32 cols each
    const int m0 = blockIdx.y * 128;

    if (tid < 128) sden[tid] = 0.f;

    float acc[2][4][4];
#pragma unroll
    for (int i = 0; i < 2; i++)
#pragma unroll
        for (int j = 0; j < 4; j++)
#pragma unroll
            for (int r = 0; r < 4; r++) acc[i][j][r] = 0.f;

    const int ar  = tid >> 2, ac4 = tid & 3;   // A: 64 rows/pass, 4 f4/row
    const int brr = tid >> 4, bc4 = tid & 15;  // B: 16 rows, 16 f4/row, 1 pass

    float4 aPre[2], bPre;
    int k0s = 0;

#define PV_LOAD(K0)                                                             \
    {                                                                           \
        int k0_ = (K0);                                                         \
        _Pragma("unroll")                                                       \
        for (int i = 0; i < 2; i++) {                                           \
            int gm = m0 + ar + i * 64, gk = k0_ + ac4 * 4;                      \
            aPre[i] = (gm < Mv && gk < Kv)                                      \
                ? *(const float4*)&A[(long long)gm * 784 + gk]                  \
                : make_float4(0.f, 0.f, 0.f, 0.f);                              \
        }                                                                       \
        {                                                                       \
            int gk = k0_ + brr;                                                 \
            bPre = (gk < Kv)                                                    \
                ? *(const float4*)&B[(long long)gk * 256 + bc4 * 4]             \
                : make_float4(0.f, 0.f, 0.f, 0.f);                              \
        }                                                                       \
        k0s = k0_;                                                              \
    }

#define PV_CVT_A(s, dr, dc, f)                                                  \
    {                                                                           \
        __nv_bfloat16 hi_ = __float2bfloat16(f);                                \
        As[s][0][dr][dc] = hi_;                                                 \
        As[s][1][dr][dc] = __float2bfloat16((f) - __bfloat162float(hi_));       \
    }
#define PV_CVT_B(s, dr, dc, f)                                                  \
    {                                                                           \
        __nv_bfloat16 hi_ = __float2bfloat16(f);                                \
        Bs[s][0][dr][dc] = hi_;                                                 \
        Bs[s][1][dr][dc] = __float2bfloat16((f) - __bfloat162float(hi_));       \
    }

#define PV_STORE(s)                                                             \
    {                                                                           \
        _Pragma("unroll")                                                       \
        for (int i = 0; i < 2; i++) {                                           \
            int m = ar + i * 64, gm = m0 + m;                                   \
            bool rok = (gm < Mv);                                               \
            float rmv = rok ? rmz[gm] : 0.f;                                    \
            float part = 0.f;                                                   \
            float vv[4] = { aPre[i].x, aPre[i].y, aPre[i].z, aPre[i].w };       \
            _Pragma("unroll")                                                   \
            for (int cc = 0; cc < 4; cc++) {                                    \
                int gk = k0s + ac4 * 4 + cc;                                    \
                float e = (rok && gk < Kv) ? __expf(gv * (vv[cc] - rmv)) : 0.f; \
                part += e;                                                      \
                PV_CVT_A(s, m, ac4 * 4 + cc, e);                                \
            }                                                                   \
            if (part != 0.f) atomicAdd(&sden[m], part);                         \
        }                                                                       \
        {                                                                       \
            int k = brr, c = bc4 * 4;                                           \
            PV_CVT_B(s, k, c + 0, bPre.x); PV_CVT_B(s, k, c + 1, bPre.y);       \
            PV_CVT_B(s, k, c + 2, bPre.z); PV_CVT_B(s, k, c + 3, bPre.w);       \
        }                                                                       \
    }

    const int ktiles = (Kv + TBK - 1) / TBK;   // 49

    PV_LOAD(0);
    __syncthreads();           // sden init visible before first atomicAdd
    PV_STORE(0);
    __syncthreads();

    for (int t = 0; t < ktiles; t++) {
        const int cur = t & 1;
        bool last = (t == ktiles - 1);
        if (!last) PV_LOAD((t + 1) * TBK);
        {
            uint32_t Ah[2][4], Al[2][4], Bh[4][2], Bl[4][2];
#pragma unroll
            for (int i = 0; i < 2; i++) {
                int row = wm * 32 + i * 16 + (lane & 15);
                int col = (lane >> 4) << 3;
                ldsm_x4(Ah[i][0], Ah[i][1], Ah[i][2], Ah[i][3],
                        smem_u32(&As[cur][0][row][col]));
                ldsm_x4(Al[i][0], Al[i][1], Al[i][2], Al[i][3],
                        smem_u32(&As[cur][1][row][col]));
            }
            {
                int row = lane & 15;
                int col = wn * 32 + ((lane >> 4) << 3);
                uint32_t r0, r1, r2, r3;
                ldsm_x4_t(r0, r1, r2, r3, smem_u32(&Bs[cur][0][row][col]));
                Bh[0][0] = r0; Bh[0][1] = r1; Bh[1][0] = r2; Bh[1][1] = r3;
                ldsm_x4_t(r0, r1, r2, r3, smem_u32(&Bs[cur][0][row][col + 16]));
                Bh[2][0] = r0; Bh[2][1] = r1; Bh[3][0] = r2; Bh[3][1] = r3;
                ldsm_x4_t(r0, r1, r2, r3, smem_u32(&Bs[cur][1][row][col]));
                Bl[0][0] = r0; Bl[0][1] = r1; Bl[1][0] = r2; Bl[1][1] = r3;
                ldsm_x4_t(r0, r1, r2, r3, smem_u32(&Bs[cur][1][row][col + 16]));
                Bl[2][0] = r0; Bl[2][1] = r1; Bl[3][0] = r2; Bl[3][1] = r3;
            }
#pragma unroll
            for (int i = 0; i < 2; i++)
#pragma unroll
                for (int j = 0; j < 4; j++) {
                    mma_bf16(acc[i][j], Ah[i], Bh[j]);
                    mma_bf16(acc[i][j], Ah[i], Bl[j]);
                    mma_bf16(acc[i][j], Al[i], Bh[j]);
                }
        }
        if (!last) {
            PV_STORE(cur ^ 1);
            __syncthreads();
        }
    }

    const int g  = lane >> 2;
    const int tg = lane & 3;
#pragma unroll
    for (int i = 0; i < 2; i++) {
        int lr0 = wm * 32 + i * 16 + g;
        int lr1 = lr0 + 8;
        int r0w = m0 + lr0, r1w = m0 + lr1;
        float d0 = (r0w < Mv) ? 1.0f / sden[lr0] : 0.f;
        float d1 = (r1w < Mv) ? 1.0f / sden[lr1] : 0.f;
#pragma unroll
        for (int j = 0; j < 4; j++) {
            int c0 = wn * 32 + j * 8 + tg * 2;
            if (r0w < Mv) {
                float2 v = make_float2(acc[i][j][0] * d0, acc[i][j][1] * d0);
                *(float2*)&C[(long long)r0w * 256 + c0] = v;
            }
            if (r1w < Mv) {
                float2 v = make_float2(acc[i][j][2] * d1, acc[i][j][3] * d1);
                *(float2*)&C[(long long)r1w * 256 + c0] = v;
            }
        }
    }
#undef PV_LOAD
#undef PV_STORE
#undef PV_CVT_A
#undef PV_CVT_B
}

// ---------------------------------------------------------------------------
// Small helpers
// ---------------------------------------------------------------------------
__global__ void transpose_kernel(const float* __restrict__ src, float* __restrict__ dst,
                                 int M, int N)
{
    __shared__ float t[32][33];
    int x = blockIdx.x * 32 + threadIdx.x;
    int y0 = blockIdx.y * 32 + threadIdx.y;
#pragma unroll
    for (int i = 0; i < 32; i += 8) {
        int y = y0 + i;
        t[threadIdx.y + i][threadIdx.x] = (y < M && x < N) ? src[(long long)y * N + x] : 0.f;
    }
    __syncthreads();
    int xo = blockIdx.y * 32 + threadIdx.x;
    int yo0 = blockIdx.x * 32 + threadIdx.y;
#pragma unroll
    for (int i = 0; i < 32; i += 8) {
        int yo = yo0 + i;
        if (yo < N && xo < M) dst[(long long)yo * M + xo] = t[threadIdx.x][threadIdx.y + i];
    }
}

// KV_S[b, j*196+t, c] = T_hat[b, t, j*256 + c]
__global__ void kvs_kernel(const float* __restrict__ T, float* __restrict__ KVS)
{
    long long i = (long long)blockIdx.x * blockDim.x + threadIdx.x;
    if (i >= SZ_BNDC) return;
    int c = (int)(i & 255);
    long long t2 = i >> 8;
    int n = (int)(t2 % 784);
    int b = (int)(t2 / 784);
    int j = n / 196, t = n % 196;
    KVS[i] = T[((long long)b * 196 + t) * 1024 + (long long)j * 256 + c];
}

// Plain row softmax (SATAT scores, 196 cols)
__global__ void softmax_kernel(float* __restrict__ X, int cols)
{
    int row = blockIdx.x;
    float* x = X + (long long)row * cols;
    int tid = threadIdx.x;
    __shared__ float red[256];

    float m = -1e30f;
    for (int c = tid; c < cols; c += 256) m = fmaxf(m, x[c]);
    red[tid] = m; __syncthreads();
    for (int s = 128; s > 0; s >>= 1) {
        if (tid < s) red[tid] = fmaxf(red[tid], red[tid + s]);
        __syncthreads();
    }
    m = red[0]; __syncthreads();

    float sum = 0.f;
    for (int c = tid; c < cols; c += 256) {
        float e = __expf(x[c] - m);
        x[c] = e; sum += e;
    }
    red[tid] = sum; __syncthreads();
    for (int s = 128; s > 0; s >>= 1) {
        if (tid < s) red[tid] += red[tid + s];
        __syncthreads();
    }
    float inv = 1.0f / red[0];
    for (int c = tid; c < cols; c += 256) x[c] *= inv;
}

// ---------------------------------------------------------------------------
// Host-side driver
// ---------------------------------------------------------------------------
static inline void gemm(int tb,
                        const float* A, const float* B, float* C,
                        int M, int N, int K, int lda, int ldb, int ldc,
                        long long sAb, long long sAh,
                        long long sBb, long long sBh,
                        long long sCb, long long sCh,
                        int batch, int nh, float alpha)
{
    dim3 g((N + TBN - 1) / TBN, (M + TBM - 1) / TBM, batch), b(256);
    if (tb)
        gemm_mma<true><<<g, b>>>(A, B, C, M, N, K, lda, ldb, ldc,
                                 sAb, sAh, sBb, sBh, sCb, sCh, nh, alpha);
    else
        gemm_mma<false><<<g, b>>>(A, B, C, M, N, K, lda, ldb, ldc,
                                  sAb, sAh, sBb, sBh, sCb, sCh, nh, alpha);
}

extern "C" void kernel_launch(void* const* d_in, const int* in_sizes, int n_in,
                              void* d_out, int out_size)
{
    const float* emb[4] = { (const float*)d_in[0], (const float*)d_in[1],
                            (const float*)d_in[2], (const float*)d_in[3] };
    const float* emb_C = (const float*)d_in[4];
    const float* Wq_c  = (const float*)d_in[5];
    const float* Wk_c  = (const float*)d_in[6];
    const float* Wv_c  = (const float*)d_in[7];
    const float* Wo_c  = (const float*)d_in[8];
    const float* Wq[4] = { (const float*)d_in[9],  (const float*)d_in[10],
                           (const float*)d_in[11], (const float*)d_in[12] };
    const float* Wk    = (const float*)d_in[13];
    const float* Wv    = (const float*)d_in[14];
    const float* Wo[4] = { (const float*)d_in[15], (const float*)d_in[16],
                           (const float*)d_in[17], (const float*)d_in[18] };
    float* out = (float*)d_out;

    float *q3, *k3, *v3, *sc, *oat, *that, *kvs, *Kb, *Vb, *Qb, *attn, *ctx;
    float *gain, *rowmax, *WkT, *WvT, *WqT;
    cudaGetSymbolAddress((void**)&q3,    g_q3);
    cudaGetSymbolAddress((void**)&k3,    g_k3);
    cudaGetSymbolAddress((void**)&v3,    g_v3);
    cudaGetSymbolAddress((void**)&sc,    g_sc);
    cudaGetSymbolAddress((void**)&oat,   g_oat);
    cudaGetSymbolAddress((void**)&that,  g_that);
    cudaGetSymbolAddress((void**)&kvs,   g_kvs);
    cudaGetSymbolAddress((void**)&Kb,    g_Kb);
    cudaGetSymbolAddress((void**)&Vb,    g_Vb);
    cudaGetSymbolAddress((void**)&Qb,    g_Qb);
    cudaGetSymbolAddress((void**)&attn,  g_attn);
    cudaGetSymbolAddress((void**)&ctx,   g_ctx);
    cudaGetSymbolAddress((void**)&gain,  g_gain);
    cudaGetSymbolAddress((void**)&rowmax,g_rowmax);
    cudaGetSymbolAddress((void**)&WkT,   g_WkT);
    cudaGetSymbolAddress((void**)&WvT,   g_WvT);
    cudaGetSymbolAddress((void**)&WqT,   g_WqT);

    // ---------------- Weight pre-transposes ----------------
    {
        dim3 b(32, 8);
        dim3 g784((784 + 31) / 32, (784 + 31) / 32);
        transpose_kernel<<<g784, b>>>(Wk, WkT, 784, 784);
        transpose_kernel<<<g784, b>>>(Wv, WvT, 784, 784);
        dim3 g196((196 + 31) / 32, (196 + 31) / 32);
        for (int i = 0; i < 4; i++)
            transpose_kernel<<<g196, b>>>(Wq[i], WqT + (long long)i * 38416, 196, 196);
    }

    // ---------------- Stage A: SATAT over emb_C ----------------
    gemm(0, emb_C, Wq_c, q3, 6272, 1024, 1024, 1024, 1024, 1024,
         0, 0, 0, 0, 0, 0, 1, 1, 1.0f);
    gemm(0, emb_C, Wk_c, k3, 6272, 1024, 1024, 1024, 1024, 1024,
         0, 0, 0, 0, 0, 0, 1, 1, 1.0f);
    gemm(0, emb_C, Wv_c, v3, 6272, 1024, 1024, 1024, 1024, 1024,
         0, 0, 0, 0, 0, 0, 1, 1, 1.0f);
    gemm(1, q3, k3, sc, 196, 196, 256, 1024, 1024, 196,
         200704, 256, 200704, 256, 153664, 38416, 128, 4, 0.0625f);
    softmax_kernel<<<25088, 256>>>(sc, 196);
    gemm(0, sc, v3, oat, 196, 256, 196, 196, 1024, 1024,
         153664, 38416, 200704, 256, 200704, 256, 128, 4, 1.0f);
    gemm(0, oat, Wo_c, that, 6272, 1024, 1024, 1024, 1024, 1024,
         0, 0, 0, 0, 0, 0, 1, 1, 1.0f);

    // ---------------- Stage B: KV token mix ----------------
    kvs_kernel<<<(unsigned)((SZ_BNDC + 255) / 256), 256>>>(that, kvs);
    gemm(0, WkT, kvs, Kb, 784, 256, 784, 784, 256, 256,
         0, 0, 200704, 0, 200704, 0, 32, 1, 1.0f);
    gemm(0, WvT, kvs, Vb, 784, 256, 784, 784, 256, 256,
         0, 0, 200704, 0, 200704, 0, 32, 1, 1.0f);

    // ---------------- Stage C: 4 query branches ----------------
    for (int br = 0; br < 4; br++) {
        // Q[b] = WqT @ emb[b]
        gemm(0, WqT + (long long)br * 38416, emb[br], Qb, 196, 256, 196, 196, 256, 256,
             0, 0, 50176, 0, 50176, 0, 32, 1, 1.0f);
        // attn[b,h] = Qh @ Kh^T : NT
        gemm(1, Qb, Kb, attn, 196, 784, 64, 256, 256, 784,
             50176, 64, 200704, 64, 614656, 153664, 128, 4, 1.0f);
        // one-pass stats: per-(b,h) gain + per-row max
        attn_stats_kernel<<<128, 256>>>(attn, rowmax, gain);
        // fused exp-softmax + P@V with in-block denominator
        {
            dim3 g(1, 2, 128), b(256);
            attn_pv_kernel<<<g, b>>>(attn, Vb, ctx, rowmax, gain);
        }
        // O = ctx @ Wo
        gemm(0, ctx, Wo[br], out + (long long)br * SZ_Q,
             6272, 256, 256, 256, 256, 256,
             0, 0, 0, 0, 0, 0, 1, 1, 1.0f);
    }
}

// round 8
// speedup vs baseline: 3.9148x; 1.0055x over previous
#include <cuda_runtime.h>
#include <cuda_bf16.h>
#include <cstdint>

// ---------------------------------------------------------------------------
// Problem constants: B=32, N=196, DQ=256, DC=1024, H=4, DH=64, DHC=256, 4N=784
// ---------------------------------------------------------------------------

#define SZ_BNDC   6422528LL   // 32*196*1024  (also 32*784*256)
#define SZ_SC     4917248LL   // 32*4*196*196
#define SZ_Q      1605632LL   // 32*196*256
#define SZ_ATTN  19668992LL   // 32*4*196*784 (one branch)

// Scratch (device .bss, allocation-free) — identical footprint to the
// known-good round-7 kernel (~322 MB).
__device__ float g_q3[SZ_BNDC];
__device__ float g_k3[SZ_BNDC];
__device__ float g_v3[SZ_BNDC];
__device__ float g_sc[SZ_SC];
__device__ float g_oat[SZ_BNDC];
__device__ float g_that[SZ_BNDC];
__device__ float g_kvs[SZ_BNDC];
__device__ float g_Kb[SZ_BNDC];
__device__ float g_Vb[SZ_BNDC];
__device__ float g_Qb[SZ_Q];
__device__ float g_attn[SZ_ATTN];
__device__ float g_ctx[SZ_Q];
__device__ float g_gain[128];
__device__ float g_rowmax[128 * 196];
__device__ float g_WkT[614656];       // 784*784
__device__ float g_WvT[614656];
__device__ float g_WqT[4 * 38416];    // 4 * 196*196

// ---------------------------------------------------------------------------
// PTX helpers
// ---------------------------------------------------------------------------
__device__ __forceinline__ uint32_t smem_u32(const void* p) {
    return (uint32_t)__cvta_generic_to_shared(p);
}

__device__ __forceinline__ void ldsm_x4(uint32_t& r0, uint32_t& r1,
                                        uint32_t& r2, uint32_t& r3, uint32_t addr) {
    asm volatile("ldmatrix.sync.aligned.m8n8.x4.shared.b16 {%0,%1,%2,%3},[%4];"
                 : "=r"(r0), "=r"(r1), "=r"(r2), "=r"(r3) : "r"(addr));
}

__device__ __forceinline__ void ldsm_x4_t(uint32_t& r0, uint32_t& r1,
                                          uint32_t& r2, uint32_t& r3, uint32_t addr) {
    asm volatile("ldmatrix.sync.aligned.m8n8.x4.trans.shared.b16 {%0,%1,%2,%3},[%4];"
                 : "=r"(r0), "=r"(r1), "=r"(r2), "=r"(r3) : "r"(addr));
}

__device__ __forceinline__ void mma_bf16(float* c, const uint32_t* a, const uint32_t* b) {
    asm volatile("mma.sync.aligned.m16n8k16.row.col.f32.bf16.bf16.f32 "
                 "{%0,%1,%2,%3},{%4,%5,%6,%7},{%8,%9},{%0,%1,%2,%3};"
                 : "+f"(c[0]), "+f"(c[1]), "+f"(c[2]), "+f"(c[3])
                 : "r"(a[0]), "r"(a[1]), "r"(a[2]), "r"(a[3]),
                   "r"(b[0]), "r"(b[1]));
}

// Split-convert 4 consecutive fp32 into hi/lo bf16 planes with ONE 8-byte
// store per plane (addresses are 8B-aligned: row strides 24/136/72 bf16).
__device__ __forceinline__ void cvt_store4(__nv_bfloat16* hi, __nv_bfloat16* lo,
                                           float4 v) {
    __nv_bfloat16 h0 = __float2bfloat16(v.x), h1 = __float2bfloat16(v.y);
    __nv_bfloat16 h2 = __float2bfloat16(v.z), h3 = __float2bfloat16(v.w);
    __nv_bfloat162 hA = __halves2bfloat162(h0, h1);
    __nv_bfloat162 hB = __halves2bfloat162(h2, h3);
    uint2 hp; hp.x = *(uint32_t*)&hA; hp.y = *(uint32_t*)&hB;
    *(uint2*)hi = hp;
    __nv_bfloat162 lA = __halves2bfloat162(
        __float2bfloat16(v.x - __bfloat162float(h0)),
        __float2bfloat16(v.y - __bfloat162float(h1)));
    __nv_bfloat162 lB = __halves2bfloat162(
        __float2bfloat16(v.z - __bfloat162float(h2)),
        __float2bfloat16(v.w - __bfloat162float(h3)));
    uint2 lp; lp.x = *(uint32_t*)&lA; lp.y = *(uint32_t*)&lB;
    *(uint2*)lo = lp;
}

// ---------------------------------------------------------------------------
// Tile geometry: 128x128 block tile, TBK=16, double-buffered STATIC smem.
// ---------------------------------------------------------------------------
#define TBM 128
#define TBN 128
#define TBK 16
#define A_STRIDE 24                 // TBK + 8 pad
#define B_STRIDE 136                // TBN + 8 pad
#define PVB_STRIDE 72               // 64 + 8 pad

// ---------------------------------------------------------------------------
// Tensor-core batched GEMM, split-bf16 (3 MMA) fp32 emulation.
// Double-buffered static smem, vectorized (STS.64) split-convert fill.
//   C = alpha * A @ op(B);  A [M,K] row-major.
//   TB=false: B [K,N] row-major.  TB=true: B [N,K] row-major.
// Batch: z = bb*nh + hh, pointer offsets sXb/sXh.
// ---------------------------------------------------------------------------
template<bool TB>
__global__ __launch_bounds__(256)
void gemm_mma(const float* __restrict__ A, const float* __restrict__ B,
              float* __restrict__ C,
              int M, int N, int K, int lda, int ldb, int ldc,
              long long sAb, long long sAh, long long sBb, long long sBh,
              long long sCb, long long sCh, int nh, float alpha)
{
    int z  = blockIdx.z;
    int bb = z / nh, hh = z % nh;
    A += bb * sAb + hh * sAh;
    B += bb * sBb + hh * sBh;
    C += bb * sCb + hh * sCh;

    __shared__ __align__(16) __nv_bfloat16 As[2][2][TBM][A_STRIDE];  // 24.0 KB
    __shared__ __align__(16) __nv_bfloat16 Bs[2][2][TBK][B_STRIDE];  // 17.0 KB

    const int tid  = threadIdx.x;
    const int lane = tid & 31;
    const int wid  = tid >> 5;
    const int wm   = wid >> 2;
    const int wn   = wid & 3;
    const int m0 = blockIdx.y * TBM, n0 = blockIdx.x * TBN;

    float acc[4][4][4];
#pragma unroll
    for (int i = 0; i < 4; i++)
#pragma unroll
        for (int j = 0; j < 4; j++)
#pragma unroll
            for (int r = 0; r < 4; r++) acc[i][j][r] = 0.f;

    const int ar  = tid >> 2, ac4 = tid & 3;    // A: 64 rows/pass, 4 f4/row
    const int bkr = tid >> 5, bc4 = tid & 31;   // B NN: 8 k-rows/pass, 32 f4/row
    const int bnr = tid >> 2, bk4 = tid & 3;    // B NT: 64 n-rows/pass, 4 f4/row

    float4 aPre[2], bPre[2];

#define LOAD_REGS(K0)                                                           \
    {                                                                           \
        int k0_ = (K0);                                                         \
        _Pragma("unroll")                                                       \
        for (int i = 0; i < 2; i++) {                                           \
            int gm = m0 + ar + i * 64, gk = k0_ + ac4 * 4;                      \
            aPre[i] = (gm < M && gk < K)                                        \
                ? *(const float4*)&A[(long long)gm * lda + gk]                  \
                : make_float4(0.f, 0.f, 0.f, 0.f);                              \
        }                                                                       \
        if (!TB) {                                                              \
            _Pragma("unroll")                                                   \
            for (int i = 0; i < 2; i++) {                                       \
                int gk = k0_ + bkr + i * 8, gn = n0 + bc4 * 4;                  \
                bPre[i] = (gk < K && gn < N)                                    \
                    ? *(const float4*)&B[(long long)gk * ldb + gn]              \
                    : make_float4(0.f, 0.f, 0.f, 0.f);                          \
            }                                                                   \
        } else {                                                                \
            _Pragma("unroll")                                                   \
            for (int i = 0; i < 2; i++) {                                       \
                int gn = n0 + bnr + i * 64, gk = k0_ + bk4 * 4;                 \
                bPre[i] = (gn < N && gk < K)                                    \
                    ? *(const float4*)&B[(long long)gn * ldb + gk]              \
                    : make_float4(0.f, 0.f, 0.f, 0.f);                          \
            }                                                                   \
        }                                                                       \
    }

#define CVT_B_SC(s, dr, dc, f)                                                  \
    {                                                                           \
        __nv_bfloat16 hi_ = __float2bfloat16(f);                                \
        Bs[s][0][dr][dc] = hi_;                                                 \
        Bs[s][1][dr][dc] = __float2bfloat16((f) - __bfloat162float(hi_));       \
    }

#define STORE_SMEM(s)                                                           \
    {                                                                           \
        _Pragma("unroll")                                                       \
        for (int i = 0; i < 2; i++) {                                           \
            int m = ar + i * 64, c = ac4 * 4;                                   \
            cvt_store4(&As[s][0][m][c], &As[s][1][m][c], aPre[i]);              \
        }                                                                       \
        if (!TB) {                                                              \
            _Pragma("unroll")                                                   \
            for (int i = 0; i < 2; i++) {                                       \
                int k = bkr + i * 8, c = bc4 * 4;                               \
                cvt_store4(&Bs[s][0][k][c], &Bs[s][1][k][c], bPre[i]);          \
            }                                                                   \
        } else {                                                                \
            _Pragma("unroll")                                                   \
            for (int i = 0; i < 2; i++) {                                       \
                int n = bnr + i * 64, k = bk4 * 4;                              \
                CVT_B_SC(s, k + 0, n, bPre[i].x); CVT_B_SC(s, k + 1, n, bPre[i].y); \
                CVT_B_SC(s, k + 2, n, bPre[i].z); CVT_B_SC(s, k + 3, n, bPre[i].w); \
            }                                                                   \
        }                                                                       \
    }

#define COMPUTE(s)                                                              \
    {                                                                           \
        uint32_t Ah[4][4], Al[4][4], Bh[4][2], Bl[4][2];                        \
        _Pragma("unroll")                                                       \
        for (int i = 0; i < 4; i++) {                                           \
            int row = wm * 64 + i * 16 + (lane & 15);                           \
            int col = (lane >> 4) << 3;                                         \
            ldsm_x4(Ah[i][0], Ah[i][1], Ah[i][2], Ah[i][3],                     \
                    smem_u32(&As[s][0][row][col]));                             \
            ldsm_x4(Al[i][0], Al[i][1], Al[i][2], Al[i][3],                     \
                    smem_u32(&As[s][1][row][col]));                             \
        }                                                                       \
        _Pragma("unroll")                                                       \
        for (int t2 = 0; t2 < 2; t2++) {                                        \
            int row = lane & 15;                                                \
            int col = wn * 32 + t2 * 16 + ((lane >> 4) << 3);                   \
            uint32_t r0, r1, r2, r3;                                            \
            ldsm_x4_t(r0, r1, r2, r3, smem_u32(&Bs[s][0][row][col]));           \
            Bh[t2*2][0] = r0; Bh[t2*2][1] = r1;                                 \
            Bh[t2*2+1][0] = r2; Bh[t2*2+1][1] = r3;                             \
            ldsm_x4_t(r0, r1, r2, r3, smem_u32(&Bs[s][1][row][col]));           \
            Bl[t2*2][0] = r0; Bl[t2*2][1] = r1;                                 \
            Bl[t2*2+1][0] = r2; Bl[t2*2+1][1] = r3;                             \
        }                                                                       \
        _Pragma("unroll")                                                       \
        for (int i = 0; i < 4; i++)                                             \
            _Pragma("unroll")                                                   \
            for (int j = 0; j < 4; j++) {                                       \
                mma_bf16(acc[i][j], Ah[i], Bh[j]);                              \
                mma_bf16(acc[i][j], Ah[i], Bl[j]);                              \
                mma_bf16(acc[i][j], Al[i], Bh[j]);                              \
            }                                                                   \
    }

    const int ktiles = (K + TBK - 1) / TBK;

    LOAD_REGS(0);
    STORE_SMEM(0);
    __syncthreads();

    for (int t = 0; t < ktiles; t++) {
        const int cur = t & 1;
        bool last = (t == ktiles - 1);
        if (!last) LOAD_REGS((t + 1) * TBK);
        COMPUTE(cur);
        if (!last) {
            STORE_SMEM(cur ^ 1);      // other stage: prior sync drained its readers
            __syncthreads();
        }
    }

    const int g  = lane >> 2;
    const int tg = lane & 3;
#pragma unroll
    for (int i = 0; i < 4; i++) {
        int r0w = m0 + wm * 64 + i * 16 + g;
        int r1w = r0w + 8;
#pragma unroll
        for (int j = 0; j < 4; j++) {
            int c0 = n0 + wn * 32 + j * 8 + tg * 2;
            if (c0 < N) {
                if (r0w < M) {
                    float2 v = make_float2(alpha * acc[i][j][0], alpha * acc[i][j][1]);
                    *(float2*)&C[(long long)r0w * ldc + c0] = v;
                }
                if (r1w < M) {
                    float2 v = make_float2(alpha * acc[i][j][2], alpha * acc[i][j][3]);
                    *(float2*)&C[(long long)r1w * ldc + c0] = v;
                }
            }
        }
    }
#undef LOAD_REGS
#undef STORE_SMEM
#undef COMPUTE
#undef CVT_B_SC
}

// ---------------------------------------------------------------------------
// Fused attention stats (one branch): per z=(b,h) read logits once, produce
// per-row max and instance-norm gain (mean shift cancels in softmax).
// ---------------------------------------------------------------------------
__global__ __launch_bounds__(256)
void attn_stats_kernel(const float* __restrict__ attn,
                       float* __restrict__ rm, float* __restrict__ gn)
{
    int z = blockIdx.x;           // 0..127 = b*4+h
    const float* X = attn + (long long)z * 153664;
    int warp = threadIdx.x >> 5, lane = threadIdx.x & 31;
    float s = 0.f, s2 = 0.f;
    for (int r = warp; r < 196; r += 8) {
        const float* row = X + (long long)r * 784;
        float m = -1e30f;
        for (int c = lane; c < 784; c += 32) {
            float v = row[c];
            m = fmaxf(m, v); s += v; s2 += v * v;
        }
#pragma unroll
        for (int o = 16; o; o >>= 1) m = fmaxf(m, __shfl_xor_sync(~0u, m, o));
        if (lane == 0) rm[(long long)z * 196 + r] = m;
    }
    __shared__ float rs[256], rs2[256];
    rs[threadIdx.x] = s; rs2[threadIdx.x] = s2; __syncthreads();
    for (int t = 128; t; t >>= 1) {
        if (threadIdx.x < t) {
            rs[threadIdx.x]  += rs[threadIdx.x + t];
            rs2[threadIdx.x] += rs2[threadIdx.x + t];
        }
        __syncthreads();
    }
    if (threadIdx.x == 0) {
        float mean = rs[0] / 153664.f;
        float var  = rs2[0] / 153664.f - mean * mean;
        gn[z] = rsqrtf(var + 1e-5f);
    }
}

// ---------------------------------------------------------------------------
// Fused exp-softmax + P@V GEMM (one branch).  M=196, N=64, K=784 per z (128).
// p = exp(g*(x - rowmax)); denominator accumulated in smem (each block spans
// all of K); epilogue divides.  TBN=64, TBK=16, double-buffered static smem.
// ---------------------------------------------------------------------------
__global__ __launch_bounds__(256)
void attn_pv_kernel(const float* __restrict__ attn, const float* __restrict__ V,
                    float* __restrict__ ctx,
                    const float* __restrict__ rm, const float* __restrict__ gn)
{
    const int Mv = 196, Kv = 784;
    int z = blockIdx.z;               // 0..127 = b*4+h
    int bb = z >> 2, hh = z & 3;
    const float* A = attn + (long long)bb * 614656 + (long long)hh * 153664;
    const float* B = V    + (long long)bb * 200704 + hh * 64;
    float*       C = ctx  + (long long)bb * 50176  + hh * 64;
    const float  gv  = gn[z];
    const float* rmz = rm + (long long)z * 196;

    __shared__ __align__(16) __nv_bfloat16 As[2][2][128][A_STRIDE];    // 24 KB
    __shared__ __align__(16) __nv_bfloat16 Bs[2][2][TBK][PVB_STRIDE];  // 9 KB
    __shared__ float sden[128];

    const int tid  = threadIdx.x;
    const int lane = tid & 31;
    const int wid  = tid >> 5;
    const int wm   = wid >> 1;   // 0..3 : 32 rows each
    const int wn   = wid & 1;    // 0..1 : 32 cols each
    const int m0 = blockIdx.y * 128;

    if (tid < 128) sden[tid] = 0.f;

    float acc[2][4][4];
#pragma unroll
    for (int i = 0; i < 2; i++)
#pragma unroll
        for (int j = 0; j < 4; j++)
#pragma unroll
            for (int r = 0; r < 4; r++) acc[i][j][r] = 0.f;

    const int ar  = tid >> 2, ac4 = tid & 3;   // A: 64 rows/pass, 4 f4/row
    const int brr = tid >> 4, bc4 = tid & 15;  // B: 16 rows, 16 f4/row, 1 pass

    float4 aPre[2], bPre;
    int k0s = 0;

#define PV_LOAD(K0)                                                             \
    {                                                                           \
        int k0_ = (K0);                                                         \
        _Pragma("unroll")                                                       \
        for (int i = 0; i < 2; i++) {                                           \
            int gm = m0 + ar + i * 64, gk = k0_ + ac4 * 4;                      \
            aPre[i] = (gm < Mv && gk < Kv)                                      \
                ? *(const float4*)&A[(long long)gm * 784 + gk]                  \
                : make_float4(0.f, 0.f, 0.f, 0.f);                              \
        }                                                                       \
        {                                                                       \
            int gk = k0_ + brr;                                                 \
            bPre = (gk < Kv)                                                    \
                ? *(const float4*)&B[(long long)gk * 256 + bc4 * 4]             \
                : make_float4(0.f, 0.f, 0.f, 0.f);                              \
        }                                                                       \
        k0s = k0_;                                                              \
    }

#define PV_STORE(s)                                                             \
    {                                                                           \
        _Pragma("unroll")                                                       \
        for (int i = 0; i < 2; i++) {                                           \
            int m = ar + i * 64, gm = m0 + m;                                   \
            bool rok = (gm < Mv);                                               \
            float rmv = rok ? rmz[gm] : 0.f;                                    \
            float4 e4;                                                          \
            float vv[4] = { aPre[i].x, aPre[i].y, aPre[i].z, aPre[i].w };       \
            float ee[4];                                                        \
            _Pragma("unroll")                                                   \
            for (int cc = 0; cc < 4; cc++) {                                    \
                int gk = k0s + ac4 * 4 + cc;                                    \
                ee[cc] = (rok && gk < Kv) ? __expf(gv * (vv[cc] - rmv)) : 0.f;  \
            }                                                                   \
            e4 = make_float4(ee[0], ee[1], ee[2], ee[3]);                       \
            float part = ee[0] + ee[1] + ee[2] + ee[3];                         \
            cvt_store4(&As[s][0][m][ac4 * 4], &As[s][1][m][ac4 * 4], e4);       \
            if (part != 0.f) atomicAdd(&sden[m], part);                         \
        }                                                                       \
        {                                                                       \
            int k = brr, c = bc4 * 4;                                           \
            cvt_store4(&Bs[s][0][k][c], &Bs[s][1][k][c], bPre);                 \
        }                                                                       \
    }

    const int ktiles = (Kv + TBK - 1) / TBK;   // 49

    PV_LOAD(0);
    __syncthreads();           // sden init visible before first atomicAdd
    PV_STORE(0);
    __syncthreads();

    for (int t = 0; t < ktiles; t++) {
        const int cur = t & 1;
        bool last = (t == ktiles - 1);
        if (!last) PV_LOAD((t + 1) * TBK);
        {
            uint32_t Ah[2][4], Al[2][4], Bh[4][2], Bl[4][2];
#pragma unroll
            for (int i = 0; i < 2; i++) {
                int row = wm * 32 + i * 16 + (lane & 15);
                int col = (lane >> 4) << 3;
                ldsm_x4(Ah[i][0], Ah[i][1], Ah[i][2], Ah[i][3],
                        smem_u32(&As[cur][0][row][col]));
                ldsm_x4(Al[i][0], Al[i][1], Al[i][2], Al[i][3],
                        smem_u32(&As[cur][1][row][col]));
            }
            {
                int row = lane & 15;
                int col = wn * 32 + ((lane >> 4) << 3);
                uint32_t r0, r1, r2, r3;
                ldsm_x4_t(r0, r1, r2, r3, smem_u32(&Bs[cur][0][row][col]));
                Bh[0][0] = r0; Bh[0][1] = r1; Bh[1][0] = r2; Bh[1][1] = r3;
                ldsm_x4_t(r0, r1, r2, r3, smem_u32(&Bs[cur][0][row][col + 16]));
                Bh[2][0] = r0; Bh[2][1] = r1; Bh[3][0] = r2; Bh[3][1] = r3;
                ldsm_x4_t(r0, r1, r2, r3, smem_u32(&Bs[cur][1][row][col]));
                Bl[0][0] = r0; Bl[0][1] = r1; Bl[1][0] = r2; Bl[1][1] = r3;
                ldsm_x4_t(r0, r1, r2, r3, smem_u32(&Bs[cur][1][row][col + 16]));
                Bl[2][0] = r0; Bl[2][1] = r1; Bl[3][0] = r2; Bl[3][1] = r3;
            }
#pragma unroll
            for (int i = 0; i < 2; i++)
#pragma unroll
                for (int j = 0; j < 4; j++) {
                    mma_bf16(acc[i][j], Ah[i], Bh[j]);
                    mma_bf16(acc[i][j], Ah[i], Bl[j]);
                    mma_bf16(acc[i][j], Al[i], Bh[j]);
                }
        }
        if (!last) {
            PV_STORE(cur ^ 1);
            __syncthreads();
        }
    }

    const int g  = lane >> 2;
    const int tg = lane & 3;
#pragma unroll
    for (int i = 0; i < 2; i++) {
        int lr0 = wm * 32 + i * 16 + g;
        int lr1 = lr0 + 8;
        int r0w = m0 + lr0, r1w = m0 + lr1;
        float d0 = (r0w < Mv) ? 1.0f / sden[lr0] : 0.f;
        float d1 = (r1w < Mv) ? 1.0f / sden[lr1] : 0.f;
#pragma unroll
        for (int j = 0; j < 4; j++) {
            int c0 = wn * 32 + j * 8 + tg * 2;
            if (r0w < Mv) {
                float2 v = make_float2(acc[i][j][0] * d0, acc[i][j][1] * d0);
                *(float2*)&C[(long long)r0w * 256 + c0] = v;
            }
            if (r1w < Mv) {
                float2 v = make_float2(acc[i][j][2] * d1, acc[i][j][3] * d1);
                *(float2*)&C[(long long)r1w * 256 + c0] = v;
            }
        }
    }
#undef PV_LOAD
#undef PV_STORE
}

// ---------------------------------------------------------------------------
// Small helpers
// ---------------------------------------------------------------------------
__global__ void transpose_kernel(const float* __restrict__ src, float* __restrict__ dst,
                                 int M, int N)
{
    __shared__ float t[32][33];
    int x = blockIdx.x * 32 + threadIdx.x;
    int y0 = blockIdx.y * 32 + threadIdx.y;
#pragma unroll
    for (int i = 0; i < 32; i += 8) {
        int y = y0 + i;
        t[threadIdx.y + i][threadIdx.x] = (y < M && x < N) ? src[(long long)y * N + x] : 0.f;
    }
    __syncthreads();
    int xo = blockIdx.y * 32 + threadIdx.x;
    int yo0 = blockIdx.x * 32 + threadIdx.y;
#pragma unroll
    for (int i = 0; i < 32; i += 8) {
        int yo = yo0 + i;
        if (yo < N && xo < M) dst[(long long)yo * M + xo] = t[threadIdx.x][threadIdx.y + i];
    }
}

// KV_S[b, j*196+t, c] = T_hat[b, t, j*256 + c]
__global__ void kvs_kernel(const float* __restrict__ T, float* __restrict__ KVS)
{
    long long i = (long long)blockIdx.x * blockDim.x + threadIdx.x;
    if (i >= SZ_BNDC) return;
    int c = (int)(i & 255);
    long long t2 = i >> 8;
    int n = (int)(t2 % 784);
    int b = (int)(t2 / 784);
    int j = n / 196, t = n % 196;
    KVS[i] = T[((long long)b * 196 + t) * 1024 + (long long)j * 256 + c];
}

// Plain row softmax (SATAT scores, 196 cols)
__global__ void softmax_kernel(float* __restrict__ X, int cols)
{
    int row = blockIdx.x;
    float* x = X + (long long)row * cols;
    int tid = threadIdx.x;
    __shared__ float red[256];

    float m = -1e30f;
    for (int c = tid; c < cols; c += 256) m = fmaxf(m, x[c]);
    red[tid] = m; __syncthreads();
    for (int s = 128; s > 0; s >>= 1) {
        if (tid < s) red[tid] = fmaxf(red[tid], red[tid + s]);
        __syncthreads();
    }
    m = red[0]; __syncthreads();

    float sum = 0.f;
    for (int c = tid; c < cols; c += 256) {
        float e = __expf(x[c] - m);
        x[c] = e; sum += e;
    }
    red[tid] = sum; __syncthreads();
    for (int s = 128; s > 0; s >>= 1) {
        if (tid < s) red[tid] += red[tid + s];
        __syncthreads();
    }
    float inv = 1.0f / red[0];
    for (int c = tid; c < cols; c += 256) x[c] *= inv;
}

// ---------------------------------------------------------------------------
// Host-side driver
// ---------------------------------------------------------------------------
static inline void gemm(int tb,
                        const float* A, const float* B, float* C,
                        int M, int N, int K, int lda, int ldb, int ldc,
                        long long sAb, long long sAh,
                        long long sBb, long long sBh,
                        long long sCb, long long sCh,
                        int batch, int nh, float alpha)
{
    dim3 g((N + TBN - 1) / TBN, (M + TBM - 1) / TBM, batch), b(256);
    if (tb)
        gemm_mma<true><<<g, b>>>(A, B, C, M, N, K, lda, ldb, ldc,
                                 sAb, sAh, sBb, sBh, sCb, sCh, nh, alpha);
    else
        gemm_mma<false><<<g, b>>>(A, B, C, M, N, K, lda, ldb, ldc,
                                  sAb, sAh, sBb, sBh, sCb, sCh, nh, alpha);
}

extern "C" void kernel_launch(void* const* d_in, const int* in_sizes, int n_in,
                              void* d_out, int out_size)
{
    const float* emb[4] = { (const float*)d_in[0], (const float*)d_in[1],
                            (const float*)d_in[2], (const float*)d_in[3] };
    const float* emb_C = (const float*)d_in[4];
    const float* Wq_c  = (const float*)d_in[5];
    const float* Wk_c  = (const float*)d_in[6];
    const float* Wv_c  = (const float*)d_in[7];
    const float* Wo_c  = (const float*)d_in[8];
    const float* Wq[4] = { (const float*)d_in[9],  (const float*)d_in[10],
                           (const float*)d_in[11], (const float*)d_in[12] };
    const float* Wk    = (const float*)d_in[13];
    const float* Wv    = (const float*)d_in[14];
    const float* Wo[4] = { (const float*)d_in[15], (const float*)d_in[16],
                           (const float*)d_in[17], (const float*)d_in[18] };
    float* out = (float*)d_out;

    float *q3, *k3, *v3, *sc, *oat, *that, *kvs, *Kb, *Vb, *Qb, *attn, *ctx;
    float *gain, *rowmax, *WkT, *WvT, *WqT;
    cudaGetSymbolAddress((void**)&q3,    g_q3);
    cudaGetSymbolAddress((void**)&k3,    g_k3);
    cudaGetSymbolAddress((void**)&v3,    g_v3);
    cudaGetSymbolAddress((void**)&sc,    g_sc);
    cudaGetSymbolAddress((void**)&oat,   g_oat);
    cudaGetSymbolAddress((void**)&that,  g_that);
    cudaGetSymbolAddress((void**)&kvs,   g_kvs);
    cudaGetSymbolAddress((void**)&Kb,    g_Kb);
    cudaGetSymbolAddress((void**)&Vb,    g_Vb);
    cudaGetSymbolAddress((void**)&Qb,    g_Qb);
    cudaGetSymbolAddress((void**)&attn,  g_attn);
    cudaGetSymbolAddress((void**)&ctx,   g_ctx);
    cudaGetSymbolAddress((void**)&gain,  g_gain);
    cudaGetSymbolAddress((void**)&rowmax,g_rowmax);
    cudaGetSymbolAddress((void**)&WkT,   g_WkT);
    cudaGetSymbolAddress((void**)&WvT,   g_WvT);
    cudaGetSymbolAddress((void**)&WqT,   g_WqT);

    // ---------------- Weight pre-transposes ----------------
    {
        dim3 b(32, 8);
        dim3 g784((784 + 31) / 32, (784 + 31) / 32);
        transpose_kernel<<<g784, b>>>(Wk, WkT, 784, 784);
        transpose_kernel<<<g784, b>>>(Wv, WvT, 784, 784);
        dim3 g196((196 + 31) / 32, (196 + 31) / 32);
        for (int i = 0; i < 4; i++)
            transpose_kernel<<<g196, b>>>(Wq[i], WqT + (long long)i * 38416, 196, 196);
    }

    // ---------------- Stage A: SATAT over emb_C ----------------
    gemm(0, emb_C, Wq_c, q3, 6272, 1024, 1024, 1024, 1024, 1024,
         0, 0, 0, 0, 0, 0, 1, 1, 1.0f);
    gemm(0, emb_C, Wk_c, k3, 6272, 1024, 1024, 1024, 1024, 1024,
         0, 0, 0, 0, 0, 0, 1, 1, 1.0f);
    gemm(0, emb_C, Wv_c, v3, 6272, 1024, 1024, 1024, 1024, 1024,
         0, 0, 0, 0, 0, 0, 1, 1, 1.0f);
    gemm(1, q3, k3, sc, 196, 196, 256, 1024, 1024, 196,
         200704, 256, 200704, 256, 153664, 38416, 128, 4, 0.0625f);
    softmax_kernel<<<25088, 256>>>(sc, 196);
    gemm(0, sc, v3, oat, 196, 256, 196, 196, 1024, 1024,
         153664, 38416, 200704, 256, 200704, 256, 128, 4, 1.0f);
    gemm(0, oat, Wo_c, that, 6272, 1024, 1024, 1024, 1024, 1024,
         0, 0, 0, 0, 0, 0, 1, 1, 1.0f);

    // ---------------- Stage B: KV token mix ----------------
    kvs_kernel<<<(unsigned)((SZ_BNDC + 255) / 256), 256>>>(that, kvs);
    gemm(0, WkT, kvs, Kb, 784, 256, 784, 784, 256, 256,
         0, 0, 200704, 0, 200704, 0, 32, 1, 1.0f);
    gemm(0, WvT, kvs, Vb, 784, 256, 784, 784, 256, 256,
         0, 0, 200704, 0, 200704, 0, 32, 1, 1.0f);

    // ---------------- Stage C: 4 query branches ----------------
    for (int br = 0; br < 4; br++) {
        // Q[b] = WqT @ emb[b]
        gemm(0, WqT + (long long)br * 38416, emb[br], Qb, 196, 256, 196, 196, 256, 256,
             0, 0, 50176, 0, 50176, 0, 32, 1, 1.0f);
        // attn[b,h] = Qh @ Kh^T : NT
        gemm(1, Qb, Kb, attn, 196, 784, 64, 256, 256, 784,
             50176, 64, 200704, 64, 614656, 153664, 128, 4, 1.0f);
        // one-pass stats: per-(b,h) gain + per-row max
        attn_stats_kernel<<<128, 256>>>(attn, rowmax, gain);
        // fused exp-softmax + P@V with in-block denominator
        {
            dim3 g(1, 2, 128), b(256);
            attn_pv_kernel<<<g, b>>>(attn, Vb, ctx, rowmax, gain);
        }
        // O = ctx @ Wo
        gemm(0, ctx, Wo[br], out + (long long)br * SZ_Q,
             6272, 256, 256, 256, 256, 256,
             0, 0, 0, 0, 0, 0, 1, 1, 1.0f);
    }
}

// round 10
// speedup vs baseline: 3.9877x; 1.0186x over previous
#include <cuda_runtime.h>
#include <cuda_bf16.h>
#include <cstdint>

// ---------------------------------------------------------------------------
// Problem constants: B=32, N=196, DQ=256, DC=1024, H=4, DH=64, DHC=256, 4N=784
// ---------------------------------------------------------------------------

#define SZ_BNDC   6422528LL   // 32*196*1024  (also 32*784*256)
#define SZ_SC     4917248LL   // 32*4*196*196
#define SZ_Q      1605632LL   // 32*196*256
#define SZ_ATTN  19668992LL   // 32*4*196*784 (one branch)

// Scratch (device .bss, allocation-free) — identical footprint to the
// known-good round-7/8 kernel (~322 MB).
// Stage-C reuse: g_q3 = packed emb[4], g_k3 = Qb4, g_v3 = packed Wo[4],
//                g_oat = ctx4.
__device__ float g_q3[SZ_BNDC];
__device__ float g_k3[SZ_BNDC];
__device__ float g_v3[SZ_BNDC];
__device__ float g_sc[SZ_SC];
__device__ float g_oat[SZ_BNDC];
__device__ float g_that[SZ_BNDC];
__device__ float g_kvs[SZ_BNDC];
__device__ float g_Kb[SZ_BNDC];
__device__ float g_Vb[SZ_BNDC];
__device__ float g_Qb[SZ_Q];
__device__ float g_attn[SZ_ATTN];
__device__ float g_ctx[SZ_Q];
__device__ float g_gain[128];
__device__ float g_rowmax[128 * 196];
__device__ float g_WkT[614656];       // 784*784
__device__ float g_WvT[614656];
__device__ float g_WqT[4 * 38416];    // 4 * 196*196

// ---------------------------------------------------------------------------
// PTX helpers
// ---------------------------------------------------------------------------
__device__ __forceinline__ uint32_t smem_u32(const void* p) {
    return (uint32_t)__cvta_generic_to_shared(p);
}

__device__ __forceinline__ void ldsm_x4(uint32_t& r0, uint32_t& r1,
                                        uint32_t& r2, uint32_t& r3, uint32_t addr) {
    asm volatile("ldmatrix.sync.aligned.m8n8.x4.shared.b16 {%0,%1,%2,%3},[%4];"
                 : "=r"(r0), "=r"(r1), "=r"(r2), "=r"(r3) : "r"(addr));
}

__device__ __forceinline__ void ldsm_x4_t(uint32_t& r0, uint32_t& r1,
                                          uint32_t& r2, uint32_t& r3, uint32_t addr) {
    asm volatile("ldmatrix.sync.aligned.m8n8.x4.trans.shared.b16 {%0,%1,%2,%3},[%4];"
                 : "=r"(r0), "=r"(r1), "=r"(r2), "=r"(r3) : "r"(addr));
}

__device__ __forceinline__ void mma_bf16(float* c, const uint32_t* a, const uint32_t* b) {
    asm volatile("mma.sync.aligned.m16n8k16.row.col.f32.bf16.bf16.f32 "
                 "{%0,%1,%2,%3},{%4,%5,%6,%7},{%8,%9},{%0,%1,%2,%3};"
                 : "+f"(c[0]), "+f"(c[1]), "+f"(c[2]), "+f"(c[3])
                 : "r"(a[0]), "r"(a[1]), "r"(a[2]), "r"(a[3]),
                   "r"(b[0]), "r"(b[1]));
}

// Split-convert 4 consecutive fp32 into hi/lo bf16 planes with ONE 8-byte
// store per plane (addresses are 8B-aligned: row strides 24/136/72 bf16).
__device__ __forceinline__ void cvt_store4(__nv_bfloat16* hi, __nv_bfloat16* lo,
                                           float4 v) {
    __nv_bfloat16 h0 = __float2bfloat16(v.x), h1 = __float2bfloat16(v.y);
    __nv_bfloat16 h2 = __float2bfloat16(v.z), h3 = __float2bfloat16(v.w);
    __nv_bfloat162 hA = __halves2bfloat162(h0, h1);
    __nv_bfloat162 hB = __halves2bfloat162(h2, h3);
    uint2 hp; hp.x = *(uint32_t*)&hA; hp.y = *(uint32_t*)&hB;
    *(uint2*)hi = hp;
    __nv_bfloat162 lA = __halves2bfloat162(
        __float2bfloat16(v.x - __bfloat162float(h0)),
        __float2bfloat16(v.y - __bfloat162float(h1)));
    __nv_bfloat162 lB = __halves2bfloat162(
        __float2bfloat16(v.z - __bfloat162float(h2)),
        __float2bfloat16(v.w - __bfloat162float(h3)));
    uint2 lp; lp.x = *(uint32_t*)&lA; lp.y = *(uint32_t*)&lB;
    *(uint2*)lo = lp;
}

// ---------------------------------------------------------------------------
// Tile geometry: 128x128 block tile, TBK=16, double-buffered STATIC smem.
// ---------------------------------------------------------------------------
#define TBM 128
#define TBN 128
#define TBK 16
#define A_STRIDE 24                 // TBK + 8 pad
#define B_STRIDE 136                // TBN + 8 pad
#define PVB_STRIDE 72               // 64 + 8 pad

// ---------------------------------------------------------------------------
// Tensor-core batched GEMM, split-bf16 (3 MMA) fp32 emulation.
// Double-buffered static smem, vectorized (STS.64) split-convert fill.
//   C = alpha * A @ op(B);  A [M,K] row-major.
//   TB=false: B [K,N] row-major.  TB=true: B [N,K] row-major.
// Batch: z = bb*nh + hh, pointer offsets sXb/sXh.
// ---------------------------------------------------------------------------
template<bool TB>
__global__ __launch_bounds__(256)
void gemm_mma(const float* __restrict__ A, const float* __restrict__ B,
              float* __restrict__ C,
              int M, int N, int K, int lda, int ldb, int ldc,
              long long sAb, long long sAh, long long sBb, long long sBh,
              long long sCb, long long sCh, int nh, float alpha)
{
    int z  = blockIdx.z;
    int bb = z / nh, hh = z % nh;
    A += bb * sAb + hh * sAh;
    B += bb * sBb + hh * sBh;
    C += bb * sCb + hh * sCh;

    __shared__ __align__(16) __nv_bfloat16 As[2][2][TBM][A_STRIDE];  // 24.0 KB
    __shared__ __align__(16) __nv_bfloat16 Bs[2][2][TBK][B_STRIDE];  // 17.0 KB

    const int tid  = threadIdx.x;
    const int lane = tid & 31;
    const int wid  = tid >> 5;
    const int wm   = wid >> 2;
    const int wn   = wid & 3;
    const int m0 = blockIdx.y * TBM, n0 = blockIdx.x * TBN;

    float acc[4][4][4];
#pragma unroll
    for (int i = 0; i < 4; i++)
#pragma unroll
        for (int j = 0; j < 4; j++)
#pragma unroll
            for (int r = 0; r < 4; r++) acc[i][j][r] = 0.f;

    const int ar  = tid >> 2, ac4 = tid & 3;    // A: 64 rows/pass, 4 f4/row
    const int bkr = tid >> 5, bc4 = tid & 31;   // B NN: 8 k-rows/pass, 32 f4/row
    const int bnr = tid >> 2, bk4 = tid & 3;    // B NT: 64 n-rows/pass, 4 f4/row

    float4 aPre[2], bPre[2];

#define LOAD_REGS(K0)                                                           \
    {                                                                           \
        int k0_ = (K0);                                                         \
        _Pragma("unroll")                                                       \
        for (int i = 0; i < 2; i++) {                                           \
            int gm = m0 + ar + i * 64, gk = k0_ + ac4 * 4;                      \
            aPre[i] = (gm < M && gk < K)                                        \
                ? *(const float4*)&A[(long long)gm * lda + gk]                  \
                : make_float4(0.f, 0.f, 0.f, 0.f);                              \
        }                                                                       \
        if (!TB) {                                                              \
            _Pragma("unroll")                                                   \
            for (int i = 0; i < 2; i++) {                                       \
                int gk = k0_ + bkr + i * 8, gn = n0 + bc4 * 4;                  \
                bPre[i] = (gk < K && gn < N)                                    \
                    ? *(const float4*)&B[(long long)gk * ldb + gn]              \
                    : make_float4(0.f, 0.f, 0.f, 0.f);                          \
            }                                                                   \
        } else {                                                                \
            _Pragma("unroll")                                                   \
            for (int i = 0; i < 2; i++) {                                       \
                int gn = n0 + bnr + i * 64, gk = k0_ + bk4 * 4;                 \
                bPre[i] = (gn < N && gk < K)                                    \
                    ? *(const float4*)&B[(long long)gn * ldb + gk]              \
                    : make_float4(0.f, 0.f, 0.f, 0.f);                          \
            }                                                                   \
        }                                                                       \
    }

#define CVT_B_SC(s, dr, dc, f)                                                  \
    {                                                                           \
        __nv_bfloat16 hi_ = __float2bfloat16(f);                                \
        Bs[s][0][dr][dc] = hi_;                                                 \
        Bs[s][1][dr][dc] = __float2bfloat16((f) - __bfloat162float(hi_));       \
    }

#define STORE_SMEM(s)                                                           \
    {                                                                           \
        _Pragma("unroll")                                                       \
        for (int i = 0; i < 2; i++) {                                           \
            int m = ar + i * 64, c = ac4 * 4;                                   \
            cvt_store4(&As[s][0][m][c], &As[s][1][m][c], aPre[i]);              \
        }                                                                       \
        if (!TB) {                                                              \
            _Pragma("unroll")                                                   \
            for (int i = 0; i < 2; i++) {                                       \
                int k = bkr + i * 8, c = bc4 * 4;                               \
                cvt_store4(&Bs[s][0][k][c], &Bs[s][1][k][c], bPre[i]);          \
            }                                                                   \
        } else {                                                                \
            _Pragma("unroll")                                                   \
            for (int i = 0; i < 2; i++) {                                       \
                int n = bnr + i * 64, k = bk4 * 4;                              \
                CVT_B_SC(s, k + 0, n, bPre[i].x); CVT_B_SC(s, k + 1, n, bPre[i].y); \
                CVT_B_SC(s, k + 2, n, bPre[i].z); CVT_B_SC(s, k + 3, n, bPre[i].w); \
            }                                                                   \
        }                                                                       \
    }

#define COMPUTE(s)                                                              \
    {                                                                           \
        uint32_t Ah[4][4], Al[4][4], Bh[4][2], Bl[4][2];                        \
        _Pragma("unroll")                                                       \
        for (int i = 0; i < 4; i++) {                                           \
            int row = wm * 64 + i * 16 + (lane & 15);                           \
            int col = (lane >> 4) << 3;                                         \
            ldsm_x4(Ah[i][0], Ah[i][1], Ah[i][2], Ah[i][3],                     \
                    smem_u32(&As[s][0][row][col]));                             \
            ldsm_x4(Al[i][0], Al[i][1], Al[i][2], Al[i][3],                     \
                    smem_u32(&As[s][1][row][col]));                             \
        }                                                                       \
        _Pragma("unroll")                                                       \
        for (int t2 = 0; t2 < 2; t2++) {                                        \
            int row = lane & 15;                                                \
            int col = wn * 32 + t2 * 16 + ((lane >> 4) << 3);                   \
            uint32_t r0, r1, r2, r3;                                            \
            ldsm_x4_t(r0, r1, r2, r3, smem_u32(&Bs[s][0][row][col]));           \
            Bh[t2*2][0] = r0; Bh[t2*2][1] = r1;                                 \
            Bh[t2*2+1][0] = r2; Bh[t2*2+1][1] = r3;                             \
            ldsm_x4_t(r0, r1, r2, r3, smem_u32(&Bs[s][1][row][col]));           \
            Bl[t2*2][0] = r0; Bl[t2*2][1] = r1;                                 \
            Bl[t2*2+1][0] = r2; Bl[t2*2+1][1] = r3;                             \
        }                                                                       \
        _Pragma("unroll")                                                       \
        for (int i = 0; i < 4; i++)                                             \
            _Pragma("unroll")                                                   \
            for (int j = 0; j < 4; j++) {                                       \
                mma_bf16(acc[i][j], Ah[i], Bh[j]);                              \
                mma_bf16(acc[i][j], Ah[i], Bl[j]);                              \
                mma_bf16(acc[i][j], Al[i], Bh[j]);                              \
            }                                                                   \
    }

    const int ktiles = (K + TBK - 1) / TBK;

    LOAD_REGS(0);
    STORE_SMEM(0);
    __syncthreads();

    for (int t = 0; t < ktiles; t++) {
        const int cur = t & 1;
        bool last = (t == ktiles - 1);
        if (!last) LOAD_REGS((t + 1) * TBK);
        COMPUTE(cur);
        if (!last) {
            STORE_SMEM(cur ^ 1);      // other stage: prior sync drained its readers
            __syncthreads();
        }
    }

    const int g  = lane >> 2;
    const int tg = lane & 3;
#pragma unroll
    for (int i = 0; i < 4; i++) {
        int r0w = m0 + wm * 64 + i * 16 + g;
        int r1w = r0w + 8;
#pragma unroll
        for (int j = 0; j < 4; j++) {
            int c0 = n0 + wn * 32 + j * 8 + tg * 2;
            if (c0 < N) {
                if (r0w < M) {
                    float2 v = make_float2(alpha * acc[i][j][0], alpha * acc[i][j][1]);
                    *(float2*)&C[(long long)r0w * ldc + c0] = v;
                }
                if (r1w < M) {
                    float2 v = make_float2(alpha * acc[i][j][2], alpha * acc[i][j][3]);
                    *(float2*)&C[(long long)r1w * ldc + c0] = v;
                }
            }
        }
    }
#undef LOAD_REGS
#undef STORE_SMEM
#undef COMPUTE
#undef CVT_B_SC
}

// ---------------------------------------------------------------------------
// Fused attention stats (one branch): per z=(b,h) read logits once, produce
// per-row max and instance-norm gain (mean shift cancels in softmax).
// ---------------------------------------------------------------------------
__global__ __launch_bounds__(256)
void attn_stats_kernel(const float* __restrict__ attn,
                       float* __restrict__ rm, float* __restrict__ gn)
{
    int z = blockIdx.x;           // 0..127 = b*4+h
    const float* X = attn + (long long)z * 153664;
    int warp = threadIdx.x >> 5, lane = threadIdx.x & 31;
    float s = 0.f, s2 = 0.f;
    for (int r = warp; r < 196; r += 8) {
        const float* row = X + (long long)r * 784;
        float m = -1e30f;
        for (int c = lane; c < 784; c += 32) {
            float v = row[c];
            m = fmaxf(m, v); s += v; s2 += v * v;
        }
#pragma unroll
        for (int o = 16; o; o >>= 1) m = fmaxf(m, __shfl_xor_sync(~0u, m, o));
        if (lane == 0) rm[(long long)z * 196 + r] = m;
    }
    __shared__ float rs[256], rs2[256];
    rs[threadIdx.x] = s; rs2[threadIdx.x] = s2; __syncthreads();
    for (int t = 128; t; t >>= 1) {
        if (threadIdx.x < t) {
            rs[threadIdx.x]  += rs[threadIdx.x + t];
            rs2[threadIdx.x] += rs2[threadIdx.x + t];
        }
        __syncthreads();
    }
    if (threadIdx.x == 0) {
        float mean = rs[0] / 153664.f;
        float var  = rs2[0] / 153664.f - mean * mean;
        gn[z] = rsqrtf(var + 1e-5f);
    }
}

// ---------------------------------------------------------------------------
// Fused exp-softmax + P@V GEMM (one branch).  M=196, N=64, K=784 per z (128).
// p = exp(g*(x - rowmax)); denominator accumulated in smem (each block spans
// all of K); epilogue divides.  TBN=64, TBK=16, double-buffered static smem.
// ---------------------------------------------------------------------------
__global__ __launch_bounds__(256)
void attn_pv_kernel(const float* __restrict__ attn, const float* __restrict__ V,
                    float* __restrict__ ctx,
                    const float* __restrict__ rm, const float* __restrict__ gn)
{
    const int Mv = 196, Kv = 784;
    int z = blockIdx.z;               // 0..127 = b*4+h
    int bb = z >> 2, hh = z & 3;
    const float* A = attn + (long long)bb * 614656 + (long long)hh * 153664;
    const float* B = V    + (long long)bb * 200704 + hh * 64;
    float*       C = ctx  + (long long)bb * 50176  + hh * 64;
    const float  gv  = gn[z];
    const float* rmz = rm + (long long)z * 196;

    __shared__ __align__(16) __nv_bfloat16 As[2][2][128][A_STRIDE];    // 24 KB
    __shared__ __align__(16) __nv_bfloat16 Bs[2][2][TBK][PVB_STRIDE];  // 9 KB
    __shared__ float sden[128];

    const int tid  = threadIdx.x;
    const int lane = tid & 31;
    const int wid  = tid >> 5;
    const int wm   = wid >> 1;   // 0..3 : 32 rows each
    const int wn   = wid & 1;    // 0..1 : 32 cols each
    const int m0 = blockIdx.y * 128;

    if (tid < 128) sden[tid] = 0.f;

    float acc[2][4][4];
#pragma unroll
    for (int i = 0; i < 2; i++)
#pragma unroll
        for (int j = 0; j < 4; j++)
#pragma unroll
            for (int r = 0; r < 4; r++) acc[i][j][r] = 0.f;

    const int ar  = tid >> 2, ac4 = tid & 3;   // A: 64 rows/pass, 4 f4/row
    const int brr = tid >> 4, bc4 = tid & 15;  // B: 16 rows, 16 f4/row, 1 pass

    float4 aPre[2], bPre;
    int k0s = 0;

#define PV_LOAD(K0)                                                             \
    {                                                                           \
        int k0_ = (K0);                                                         \
        _Pragma("unroll")                                                       \
        for (int i = 0; i < 2; i++) {                                           \
            int gm = m0 + ar + i * 64, gk = k0_ + ac4 * 4;                      \
            aPre[i] = (gm < Mv && gk < Kv)                                      \
                ? *(const float4*)&A[(long long)gm * 784 + gk]                  \
                : make_float4(0.f, 0.f, 0.f, 0.f);                              \
        }                                                                       \
        {                                                                       \
            int gk = k0_ + brr;                                                 \
            bPre = (gk < Kv)                                                    \
                ? *(const float4*)&B[(long long)gk * 256 + bc4 * 4]             \
                : make_float4(0.f, 0.f, 0.f, 0.f);                              \
        }                                                                       \
        k0s = k0_;                                                              \
    }

#define PV_STORE(s)                                                             \
    {                                                                           \
        _Pragma("unroll")                                                       \
        for (int i = 0; i < 2; i++) {                                           \
            int m = ar + i * 64, gm = m0 + m;                                   \
            bool rok = (gm < Mv);                                               \
            float rmv = rok ? rmz[gm] : 0.f;                                    \
            float4 e4;                                                          \
            float vv[4] = { aPre[i].x, aPre[i].y, aPre[i].z, aPre[i].w };       \
            float ee[4];                                                        \
            _Pragma("unroll")                                                   \
            for (int cc = 0; cc < 4; cc++) {                                    \
                int gk = k0s + ac4 * 4 + cc;                                    \
                ee[cc] = (rok && gk < Kv) ? __expf(gv * (vv[cc] - rmv)) : 0.f;  \
            }                                                                   \
            e4 = make_float4(ee[0], ee[1], ee[2], ee[3]);                       \
            float part = ee[0] + ee[1] + ee[2] + ee[3];                         \
            cvt_store4(&As[s][0][m][ac4 * 4], &As[s][1][m][ac4 * 4], e4);       \
            if (part != 0.f) atomicAdd(&sden[m], part);                         \
        }                                                                       \
        {                                                                       \
            int k = brr, c = bc4 * 4;                                           \
            cvt_store4(&Bs[s][0][k][c], &Bs[s][1][k][c], bPre);                 \
        }                                                                       \
    }

    const int ktiles = (Kv + TBK - 1) / TBK;   // 49

    PV_LOAD(0);
    __syncthreads();           // sden init visible before first atomicAdd
    PV_STORE(0);
    __syncthreads();

    for (int t = 0; t < ktiles; t++) {
        const int cur = t & 1;
        bool last = (t == ktiles - 1);
        if (!last) PV_LOAD((t + 1) * TBK);
        {
            uint32_t Ah[2][4], Al[2][4], Bh[4][2], Bl[4][2];
#pragma unroll
            for (int i = 0; i < 2; i++) {
                int row = wm * 32 + i * 16 + (lane & 15);
                int col = (lane >> 4) << 3;
                ldsm_x4(Ah[i][0], Ah[i][1], Ah[i][2], Ah[i][3],
                        smem_u32(&As[cur][0][row][col]));
                ldsm_x4(Al[i][0], Al[i][1], Al[i][2], Al[i][3],
                        smem_u32(&As[cur][1][row][col]));
            }
            {
                int row = lane & 15;
                int col = wn * 32 + ((lane >> 4) << 3);
                uint32_t r0, r1, r2, r3;
                ldsm_x4_t(r0, r1, r2, r3, smem_u32(&Bs[cur][0][row][col]));
                Bh[0][0] = r0; Bh[0][1] = r1; Bh[1][0] = r2; Bh[1][1] = r3;
                ldsm_x4_t(r0, r1, r2, r3, smem_u32(&Bs[cur][0][row][col + 16]));
                Bh[2][0] = r0; Bh[2][1] = r1; Bh[3][0] = r2; Bh[3][1] = r3;
                ldsm_x4_t(r0, r1, r2, r3, smem_u32(&Bs[cur][1][row][col]));
                Bl[0][0] = r0; Bl[0][1] = r1; Bl[1][0] = r2; Bl[1][1] = r3;
                ldsm_x4_t(r0, r1, r2, r3, smem_u32(&Bs[cur][1][row][col + 16]));
                Bl[2][0] = r0; Bl[2][1] = r1; Bl[3][0] = r2; Bl[3][1] = r3;
            }
#pragma unroll
            for (int i = 0; i < 2; i++)
#pragma unroll
                for (int j = 0; j < 4; j++) {
                    mma_bf16(acc[i][j], Ah[i], Bh[j]);
                    mma_bf16(acc[i][j], Ah[i], Bl[j]);
                    mma_bf16(acc[i][j], Al[i], Bh[j]);
                }
        }
        if (!last) {
            PV_STORE(cur ^ 1);
            __syncthreads();
        }
    }

    const int g  = lane >> 2;
    const int tg = lane & 3;
#pragma unroll
    for (int i = 0; i < 2; i++) {
        int lr0 = wm * 32 + i * 16 + g;
        int lr1 = lr0 + 8;
        int r0w = m0 + lr0, r1w = m0 + lr1;
        float d0 = (r0w < Mv) ? 1.0f / sden[lr0] : 0.f;
        float d1 = (r1w < Mv) ? 1.0f / sden[lr1] : 0.f;
#pragma unroll
        for (int j = 0; j < 4; j++) {
            int c0 = wn * 32 + j * 8 + tg * 2;
            if (r0w < Mv) {
                float2 v = make_float2(acc[i][j][0] * d0, acc[i][j][1] * d0);
                *(float2*)&C[(long long)r0w * 256 + c0] = v;
            }
            if (r1w < Mv) {
                float2 v = make_float2(acc[i][j][2] * d1, acc[i][j][3] * d1);
                *(float2*)&C[(long long)r1w * 256 + c0] = v;
            }
        }
    }
#undef PV_LOAD
#undef PV_STORE
}

// ---------------------------------------------------------------------------
// Small helpers
// ---------------------------------------------------------------------------
__global__ void transpose_kernel(const float* __restrict__ src, float* __restrict__ dst,
                                 int M, int N)
{
    __shared__ float t[32][33];
    int x = blockIdx.x * 32 + threadIdx.x;
    int y0 = blockIdx.y * 32 + threadIdx.y;
#pragma unroll
    for (int i = 0; i < 32; i += 8) {
        int y = y0 + i;
        t[threadIdx.y + i][threadIdx.x] = (y < M && x < N) ? src[(long long)y * N + x] : 0.f;
    }
    __syncthreads();
    int xo = blockIdx.y * 32 + threadIdx.x;
    int yo0 = blockIdx.x * 32 + threadIdx.y;
#pragma unroll
    for (int i = 0; i < 32; i += 8) {
        int yo = yo0 + i;
        if (yo < N && xo < M) dst[(long long)yo * M + xo] = t[threadIdx.x][threadIdx.y + i];
    }
}

// Pack 4 separate branch buffers into one contiguous [4][n] buffer.
__global__ void pack4_kernel(const float* __restrict__ p0, const float* __restrict__ p1,
                             const float* __restrict__ p2, const float* __restrict__ p3,
                             float* __restrict__ dst, long long n)
{
    long long i = (long long)blockIdx.x * 256 + threadIdx.x;
    int br = blockIdx.y;
    if (i < n) {
        const float* src = (br == 0) ? p0 : (br == 1) ? p1 : (br == 2) ? p2 : p3;
        dst[(long long)br * n + i] = src[i];
    }
}

// KV_S[b, j*196+t, c] = T_hat[b, t, j*256 + c]
__global__ void kvs_kernel(const float* __restrict__ T, float* __restrict__ KVS)
{
    long long i = (long long)blockIdx.x * blockDim.x + threadIdx.x;
    if (i >= SZ_BNDC) return;
    int c = (int)(i & 255);
    long long t2 = i >> 8;
    int n = (int)(t2 % 784);
    int b = (int)(t2 / 784);
    int j = n / 196, t = n % 196;
    KVS[i] = T[((long long)b * 196 + t) * 1024 + (long long)j * 256 + c];
}

// Plain row softmax (SATAT scores, 196 cols)
__global__ void softmax_kernel(float* __restrict__ X, int cols)
{
    int row = blockIdx.x;
    float* x = X + (long long)row * cols;
    int tid = threadIdx.x;
    __shared__ float red[256];

    float m = -1e30f;
    for (int c = tid; c < cols; c += 256) m = fmaxf(m, x[c]);
    red[tid] = m; __syncthreads();
    for (int s = 128; s > 0; s >>= 1) {
        if (tid < s) red[tid] = fmaxf(red[tid], red[tid + s]);
        __syncthreads();
    }
    m = red[0]; __syncthreads();

    float sum = 0.f;
    for (int c = tid; c < cols; c += 256) {
        float e = __expf(x[c] - m);
        x[c] = e; sum += e;
    }
    red[tid] = sum; __syncthreads();
    for (int s = 128; s > 0; s >>= 1) {
        if (tid < s) red[tid] += red[tid + s];
        __syncthreads();
    }
    float inv = 1.0f / red[0];
    for (int c = tid; c < cols; c += 256) x[c] *= inv;
}

// ---------------------------------------------------------------------------
// Host-side driver
// ---------------------------------------------------------------------------
static inline void gemm(int tb,
                        const float* A, const float* B, float* C,
                        int M, int N, int K, int lda, int ldb, int ldc,
                        long long sAb, long long sAh,
                        long long sBb, long long sBh,
                        long long sCb, long long sCh,
                        int batch, int nh, float alpha)
{
    dim3 g((N + TBN - 1) / TBN, (M + TBM - 1) / TBM, batch), b(256);
    if (tb)
        gemm_mma<true><<<g, b>>>(A, B, C, M, N, K, lda, ldb, ldc,
                                 sAb, sAh, sBb, sBh, sCb, sCh, nh, alpha);
    else
        gemm_mma<false><<<g, b>>>(A, B, C, M, N, K, lda, ldb, ldc,
                                  sAb, sAh, sBb, sBh, sCb, sCh, nh, alpha);
}

extern "C" void kernel_launch(void* const* d_in, const int* in_sizes, int n_in,
                              void* d_out, int out_size)
{
    const float* emb[4] = { (const float*)d_in[0], (const float*)d_in[1],
                            (const float*)d_in[2], (const float*)d_in[3] };
    const float* emb_C = (const float*)d_in[4];
    const float* Wq_c  = (const float*)d_in[5];
    const float* Wk_c  = (const float*)d_in[6];
    const float* Wv_c  = (const float*)d_in[7];
    const float* Wo_c  = (const float*)d_in[8];
    const float* Wq[4] = { (const float*)d_in[9],  (const float*)d_in[10],
                           (const float*)d_in[11], (const float*)d_in[12] };
    const float* Wk    = (const float*)d_in[13];
    const float* Wv    = (const float*)d_in[14];
    const float* Wo[4] = { (const float*)d_in[15], (const float*)d_in[16],
                           (const float*)d_in[17], (const float*)d_in[18] };
    float* out = (float*)d_out;

    float *q3, *k3, *v3, *sc, *oat, *that, *kvs, *Kb, *Vb, *attn;
    float *gain, *rowmax, *WkT, *WvT, *WqT;
    cudaGetSymbolAddress((void**)&q3,    g_q3);
    cudaGetSymbolAddress((void**)&k3,    g_k3);
    cudaGetSymbolAddress((void**)&v3,    g_v3);
    cudaGetSymbolAddress((void**)&sc,    g_sc);
    cudaGetSymbolAddress((void**)&oat,   g_oat);
    cudaGetSymbolAddress((void**)&that,  g_that);
    cudaGetSymbolAddress((void**)&kvs,   g_kvs);
    cudaGetSymbolAddress((void**)&Kb,    g_Kb);
    cudaGetSymbolAddress((void**)&Vb,    g_Vb);
    cudaGetSymbolAddress((void**)&attn,  g_attn);
    cudaGetSymbolAddress((void**)&gain,  g_gain);
    cudaGetSymbolAddress((void**)&rowmax,g_rowmax);
    cudaGetSymbolAddress((void**)&WkT,   g_WkT);
    cudaGetSymbolAddress((void**)&WvT,   g_WvT);
    cudaGetSymbolAddress((void**)&WqT,   g_WqT);

    // ---------------- Weight pre-transposes ----------------
    {
        dim3 b(32, 8);
        dim3 g784((784 + 31) / 32, (784 + 31) / 32);
        transpose_kernel<<<g784, b>>>(Wk, WkT, 784, 784);
        transpose_kernel<<<g784, b>>>(Wv, WvT, 784, 784);
        dim3 g196((196 + 31) / 32, (196 + 31) / 32);
        for (int i = 0; i < 4; i++)
            transpose_kernel<<<g196, b>>>(Wq[i], WqT + (long long)i * 38416, 196, 196);
    }

    // ---------------- Stage A: SATAT over emb_C ----------------
    gemm(0, emb_C, Wq_c, q3, 6272, 1024, 1024, 1024, 1024, 1024,
         0, 0, 0, 0, 0, 0, 1, 1, 1.0f);
    gemm(0, emb_C, Wk_c, k3, 6272, 1024, 1024, 1024, 1024, 1024,
         0, 0, 0, 0, 0, 0, 1, 1, 1.0f);
    gemm(0, emb_C, Wv_c, v3, 6272, 1024, 1024, 1024, 1024, 1024,
         0, 0, 0, 0, 0, 0, 1, 1, 1.0f);
    gemm(1, q3, k3, sc, 196, 196, 256, 1024, 1024, 196,
         200704, 256, 200704, 256, 153664, 38416, 128, 4, 0.0625f);
    softmax_kernel<<<25088, 256>>>(sc, 196);
    gemm(0, sc, v3, oat, 196, 256, 196, 196, 1024, 1024,
         153664, 38416, 200704, 256, 200704, 256, 128, 4, 1.0f);
    gemm(0, oat, Wo_c, that, 6272, 1024, 1024, 1024, 1024, 1024,
         0, 0, 0, 0, 0, 0, 1, 1, 1.0f);

    // ---------------- Stage B: KV token mix ----------------
    kvs_kernel<<<(unsigned)((SZ_BNDC + 255) / 256), 256>>>(that, kvs);
    gemm(0, WkT, kvs, Kb, 784, 256, 784, 784, 256, 256,
         0, 0, 200704, 0, 200704, 0, 32, 1, 1.0f);
    gemm(0, WvT, kvs, Vb, 784, 256, 784, 784, 256, 256,
         0, 0, 200704, 0, 200704, 0, 32, 1, 1.0f);

    // ---------------- Stage C: 4 branches ----------------
    // Stage-A/B scratch now dead; reuse:
    //   embP = g_q3 (packed emb[4]), Qb4 = g_k3, WoP = g_v3, ctx4 = g_oat.
    float* embP = q3;
    float* Qb4  = k3;
    float* WoP  = v3;
    float* ctx4 = oat;
    pack4_kernel<<<dim3((unsigned)((SZ_Q + 255) / 256), 4), 256>>>(
        emb[0], emb[1], emb[2], emb[3], embP, SZ_Q);
    pack4_kernel<<<dim3(256, 4), 256>>>(
        Wo[0], Wo[1], Wo[2], Wo[3], WoP, 65536);

    // Batched Q-mix: z = br*32 + b  (512 blocks, one launch)
    gemm(0, WqT, embP, Qb4, 196, 256, 196, 196, 256, 256,
         38416, 0, SZ_Q, 50176, SZ_Q, 50176, 128, 32, 1.0f);

    // QK + stats + fused softmax-PV per branch
    for (int br = 0; br < 4; br++) {
        const float* Qb = Qb4 + (long long)br * SZ_Q;
        gemm(1, Qb, Kb, attn, 196, 784, 64, 256, 256, 784,
             50176, 64, 200704, 64, 614656, 153664, 128, 4, 1.0f);
        attn_stats_kernel<<<128, 256>>>(attn, rowmax, gain);
        dim3 g(1, 2, 128), b(256);
        attn_pv_kernel<<<g, b>>>(attn, Vb, ctx4 + (long long)br * SZ_Q,
                                 rowmax, gain);
    }

    // Batched Wo: z = br  (392 blocks, one launch)
    gemm(0, ctx4, WoP, out, 6272, 256, 256, 256, 256, 256,
         SZ_Q, 0, 65536, 0, SZ_Q, 0, 4, 1, 1.0f);
}

// round 11
// speedup vs baseline: 4.1271x; 1.0350x over previous
#include <cuda_runtime.h>
#include <cuda_bf16.h>
#include <cstdint>

// ---------------------------------------------------------------------------
// Problem constants: B=32, N=196, DQ=256, DC=1024, H=4, DH=64, DHC=256, 4N=784
// ---------------------------------------------------------------------------

#define SZ_BNDC   6422528LL   // 32*196*1024  (also 32*784*256)
#define SZ_SC     4917248LL   // 32*4*196*196
#define SZ_Q      1605632LL   // 32*196*256
#define SZ_ATTN  19668992LL   // 32*4*196*784 (one branch)

// Scratch (device .bss, allocation-free) — identical footprint to the
// known-good round-10 kernel (~322 MB).
// Stage-A reuse: g_attn holds fused QKV output (q,k,v slabs); g_q3 holds the
// packed Wq_c|Wk_c|Wv_c weights.  Stage-C reuse: g_q3 = packed emb[4],
// g_k3 = Qb4, g_v3 = packed Wo[4], g_oat = ctx4.
__device__ float g_q3[SZ_BNDC];
__device__ float g_k3[SZ_BNDC];
__device__ float g_v3[SZ_BNDC];
__device__ float g_sc[SZ_SC];
__device__ float g_oat[SZ_BNDC];
__device__ float g_that[SZ_BNDC];
__device__ float g_kvs[SZ_BNDC];
__device__ float g_Kb[SZ_BNDC];
__device__ float g_Vb[SZ_BNDC];
__device__ float g_Qb[SZ_Q];
__device__ float g_attn[SZ_ATTN];
__device__ float g_ctx[SZ_Q];
__device__ float g_gain[128];
__device__ float g_rowmax[128 * 196];
__device__ float g_WkT[614656];       // 784*784
__device__ float g_WvT[614656];
__device__ float g_WqT[4 * 38416];    // 4 * 196*196

// ---------------------------------------------------------------------------
// PTX helpers
// ---------------------------------------------------------------------------
__device__ __forceinline__ uint32_t smem_u32(const void* p) {
    return (uint32_t)__cvta_generic_to_shared(p);
}

__device__ __forceinline__ void ldsm_x4(uint32_t& r0, uint32_t& r1,
                                        uint32_t& r2, uint32_t& r3, uint32_t addr) {
    asm volatile("ldmatrix.sync.aligned.m8n8.x4.shared.b16 {%0,%1,%2,%3},[%4];"
                 : "=r"(r0), "=r"(r1), "=r"(r2), "=r"(r3) : "r"(addr));
}

__device__ __forceinline__ void ldsm_x4_t(uint32_t& r0, uint32_t& r1,
                                          uint32_t& r2, uint32_t& r3, uint32_t addr) {
    asm volatile("ldmatrix.sync.aligned.m8n8.x4.trans.shared.b16 {%0,%1,%2,%3},[%4];"
                 : "=r"(r0), "=r"(r1), "=r"(r2), "=r"(r3) : "r"(addr));
}

__device__ __forceinline__ void mma_bf16(float* c, const uint32_t* a, const uint32_t* b) {
    asm volatile("mma.sync.aligned.m16n8k16.row.col.f32.bf16.bf16.f32 "
                 "{%0,%1,%2,%3},{%4,%5,%6,%7},{%8,%9},{%0,%1,%2,%3};"
                 : "+f"(c[0]), "+f"(c[1]), "+f"(c[2]), "+f"(c[3])
                 : "r"(a[0]), "r"(a[1]), "r"(a[2]), "r"(a[3]),
                   "r"(b[0]), "r"(b[1]));
}

// Split-convert 4 consecutive fp32 into hi/lo bf16 planes with ONE 8-byte
// store per plane (addresses are 8B-aligned: row strides 24/136/72 bf16).
__device__ __forceinline__ void cvt_store4(__nv_bfloat16* hi, __nv_bfloat16* lo,
                                           float4 v) {
    __nv_bfloat16 h0 = __float2bfloat16(v.x), h1 = __float2bfloat16(v.y);
    __nv_bfloat16 h2 = __float2bfloat16(v.z), h3 = __float2bfloat16(v.w);
    __nv_bfloat162 hA = __halves2bfloat162(h0, h1);
    __nv_bfloat162 hB = __halves2bfloat162(h2, h3);
    uint2 hp; hp.x = *(uint32_t*)&hA; hp.y = *(uint32_t*)&hB;
    *(uint2*)hi = hp;
    __nv_bfloat162 lA = __halves2bfloat162(
        __float2bfloat16(v.x - __bfloat162float(h0)),
        __float2bfloat16(v.y - __bfloat162float(h1)));
    __nv_bfloat162 lB = __halves2bfloat162(
        __float2bfloat16(v.z - __bfloat162float(h2)),
        __float2bfloat16(v.w - __bfloat162float(h3)));
    uint2 lp; lp.x = *(uint32_t*)&lA; lp.y = *(uint32_t*)&lB;
    *(uint2*)lo = lp;
}

// ---------------------------------------------------------------------------
// Tile geometry: 128x128 block tile, TBK=16, double-buffered STATIC smem.
// ---------------------------------------------------------------------------
#define TBM 128
#define TBN 128
#define TBK 16
#define A_STRIDE 24                 // TBK + 8 pad
#define B_STRIDE 136                // TBN + 8 pad
#define PVB_STRIDE 72               // 64 + 8 pad

// ---------------------------------------------------------------------------
// Tensor-core batched GEMM, split-bf16 (3 MMA) fp32 emulation.
// Double-buffered static smem, vectorized (STS.64) split-convert fill.
//   C = alpha * A @ op(B);  A [M,K] row-major.
//   TB=false: B [K,N] row-major.  TB=true: B [N,K] row-major.
// Batch: z = bb*nh + hh, pointer offsets sXb/sXh.
// ---------------------------------------------------------------------------
template<bool TB>
__global__ __launch_bounds__(256)
void gemm_mma(const float* __restrict__ A, const float* __restrict__ B,
              float* __restrict__ C,
              int M, int N, int K, int lda, int ldb, int ldc,
              long long sAb, long long sAh, long long sBb, long long sBh,
              long long sCb, long long sCh, int nh, float alpha)
{
    int z  = blockIdx.z;
    int bb = z / nh, hh = z % nh;
    A += bb * sAb + hh * sAh;
    B += bb * sBb + hh * sBh;
    C += bb * sCb + hh * sCh;

    __shared__ __align__(16) __nv_bfloat16 As[2][2][TBM][A_STRIDE];  // 24.0 KB
    __shared__ __align__(16) __nv_bfloat16 Bs[2][2][TBK][B_STRIDE];  // 17.0 KB

    const int tid  = threadIdx.x;
    const int lane = tid & 31;
    const int wid  = tid >> 5;
    const int wm   = wid >> 2;
    const int wn   = wid & 3;
    const int m0 = blockIdx.y * TBM, n0 = blockIdx.x * TBN;

    float acc[4][4][4];
#pragma unroll
    for (int i = 0; i < 4; i++)
#pragma unroll
        for (int j = 0; j < 4; j++)
#pragma unroll
            for (int r = 0; r < 4; r++) acc[i][j][r] = 0.f;

    const int ar  = tid >> 2, ac4 = tid & 3;    // A: 64 rows/pass, 4 f4/row
    const int bkr = tid >> 5, bc4 = tid & 31;   // B NN: 8 k-rows/pass, 32 f4/row
    const int bnr = tid >> 2, bk4 = tid & 3;    // B NT: 64 n-rows/pass, 4 f4/row

    float4 aPre[2], bPre[2];

#define LOAD_REGS(K0)                                                           \
    {                                                                           \
        int k0_ = (K0);                                                         \
        _Pragma("unroll")                                                       \
        for (int i = 0; i < 2; i++) {                                           \
            int gm = m0 + ar + i * 64, gk = k0_ + ac4 * 4;                      \
            aPre[i] = (gm < M && gk < K)                                        \
                ? *(const float4*)&A[(long long)gm * lda + gk]                  \
                : make_float4(0.f, 0.f, 0.f, 0.f);                              \
        }                                                                       \
        if (!TB) {                                                              \
            _Pragma("unroll")                                                   \
            for (int i = 0; i < 2; i++) {                                       \
                int gk = k0_ + bkr + i * 8, gn = n0 + bc4 * 4;                  \
                bPre[i] = (gk < K && gn < N)                                    \
                    ? *(const float4*)&B[(long long)gk * ldb + gn]              \
                    : make_float4(0.f, 0.f, 0.f, 0.f);                          \
            }                                                                   \
        } else {                                                                \
            _Pragma("unroll")                                                   \
            for (int i = 0; i < 2; i++) {                                       \
                int gn = n0 + bnr + i * 64, gk = k0_ + bk4 * 4;                 \
                bPre[i] = (gn < N && gk < K)                                    \
                    ? *(const float4*)&B[(long long)gn * ldb + gk]              \
                    : make_float4(0.f, 0.f, 0.f, 0.f);                          \
            }                                                                   \
        }                                                                       \
    }

#define CVT_B_SC(s, dr, dc, f)                                                  \
    {                                                                           \
        __nv_bfloat16 hi_ = __float2bfloat16(f);                                \
        Bs[s][0][dr][dc] = hi_;                                                 \
        Bs[s][1][dr][dc] = __float2bfloat16((f) - __bfloat162float(hi_));       \
    }

#define STORE_SMEM(s)                                                           \
    {                                                                           \
        _Pragma("unroll")                                                       \
        for (int i = 0; i < 2; i++) {                                           \
            int m = ar + i * 64, c = ac4 * 4;                                   \
            cvt_store4(&As[s][0][m][c], &As[s][1][m][c], aPre[i]);              \
        }                                                                       \
        if (!TB) {                                                              \
            _Pragma("unroll")                                                   \
            for (int i = 0; i < 2; i++) {                                       \
                int k = bkr + i * 8, c = bc4 * 4;                               \
                cvt_store4(&Bs[s][0][k][c], &Bs[s][1][k][c], bPre[i]);          \
            }                                                                   \
        } else {                                                                \
            _Pragma("unroll")                                                   \
            for (int i = 0; i < 2; i++) {                                       \
                int n = bnr + i * 64, k = bk4 * 4;                              \
                CVT_B_SC(s, k + 0, n, bPre[i].x); CVT_B_SC(s, k + 1, n, bPre[i].y); \
                CVT_B_SC(s, k + 2, n, bPre[i].z); CVT_B_SC(s, k + 3, n, bPre[i].w); \
            }                                                                   \
        }                                                                       \
    }

#define COMPUTE(s)                                                              \
    {                                                                           \
        uint32_t Ah[4][4], Al[4][4], Bh[4][2], Bl[4][2];                        \
        _Pragma("unroll")                                                       \
        for (int i = 0; i < 4; i++) {                                           \
            int row = wm * 64 + i * 16 + (lane & 15);                           \
            int col = (lane >> 4) << 3;                                         \
            ldsm_x4(Ah[i][0], Ah[i][1], Ah[i][2], Ah[i][3],                     \
                    smem_u32(&As[s][0][row][col]));                             \
            ldsm_x4(Al[i][0], Al[i][1], Al[i][2], Al[i][3],                     \
                    smem_u32(&As[s][1][row][col]));                             \
        }                                                                       \
        _Pragma("unroll")                                                       \
        for (int t2 = 0; t2 < 2; t2++) {                                        \
            int row = lane & 15;                                                \
            int col = wn * 32 + t2 * 16 + ((lane >> 4) << 3);                   \
            uint32_t r0, r1, r2, r3;                                            \
            ldsm_x4_t(r0, r1, r2, r3, smem_u32(&Bs[s][0][row][col]));           \
            Bh[t2*2][0] = r0; Bh[t2*2][1] = r1;                                 \
            Bh[t2*2+1][0] = r2; Bh[t2*2+1][1] = r3;                             \
            ldsm_x4_t(r0, r1, r2, r3, smem_u32(&Bs[s][1][row][col]));           \
            Bl[t2*2][0] = r0; Bl[t2*2][1] = r1;                                 \
            Bl[t2*2+1][0] = r2; Bl[t2*2+1][1] = r3;                             \
        }                                                                       \
        _Pragma("unroll")                                                       \
        for (int i = 0; i < 4; i++)                                             \
            _Pragma("unroll")                                                   \
            for (int j = 0; j < 4; j++) {                                       \
                mma_bf16(acc[i][j], Ah[i], Bh[j]);                              \
                mma_bf16(acc[i][j], Ah[i], Bl[j]);                              \
                mma_bf16(acc[i][j], Al[i], Bh[j]);                              \
            }                                                                   \
    }

    const int ktiles = (K + TBK - 1) / TBK;

    LOAD_REGS(0);
    STORE_SMEM(0);
    __syncthreads();

    for (int t = 0; t < ktiles; t++) {
        const int cur = t & 1;
        bool last = (t == ktiles - 1);
        if (!last) LOAD_REGS((t + 1) * TBK);
        COMPUTE(cur);
        if (!last) {
            STORE_SMEM(cur ^ 1);      // other stage: prior sync drained its readers
            __syncthreads();
        }
    }

    const int g  = lane >> 2;
    const int tg = lane & 3;
#pragma unroll
    for (int i = 0; i < 4; i++) {
        int r0w = m0 + wm * 64 + i * 16 + g;
        int r1w = r0w + 8;
#pragma unroll
        for (int j = 0; j < 4; j++) {
            int c0 = n0 + wn * 32 + j * 8 + tg * 2;
            if (c0 < N) {
                if (r0w < M) {
                    float2 v = make_float2(alpha * acc[i][j][0], alpha * acc[i][j][1]);
                    *(float2*)&C[(long long)r0w * ldc + c0] = v;
                }
                if (r1w < M) {
                    float2 v = make_float2(alpha * acc[i][j][2], alpha * acc[i][j][3]);
                    *(float2*)&C[(long long)r1w * ldc + c0] = v;
                }
            }
        }
    }
#undef LOAD_REGS
#undef STORE_SMEM
#undef COMPUTE
#undef CVT_B_SC
}

// ---------------------------------------------------------------------------
// Fused attention stats (one branch): per z=(b,h) read logits once, produce
// per-row max and instance-norm gain (mean shift cancels in softmax).
// ---------------------------------------------------------------------------
__global__ __launch_bounds__(256)
void attn_stats_kernel(const float* __restrict__ attn,
                       float* __restrict__ rm, float* __restrict__ gn)
{
    int z = blockIdx.x;           // 0..127 = b*4+h
    const float* X = attn + (long long)z * 153664;
    int warp = threadIdx.x >> 5, lane = threadIdx.x & 31;
    float s = 0.f, s2 = 0.f;
    for (int r = warp; r < 196; r += 8) {
        const float* row = X + (long long)r * 784;
        float m = -1e30f;
        for (int c = lane; c < 784; c += 32) {
            float v = row[c];
            m = fmaxf(m, v); s += v; s2 += v * v;
        }
#pragma unroll
        for (int o = 16; o; o >>= 1) m = fmaxf(m, __shfl_xor_sync(~0u, m, o));
        if (lane == 0) rm[(long long)z * 196 + r] = m;
    }
    __shared__ float rs[256], rs2[256];
    rs[threadIdx.x] = s; rs2[threadIdx.x] = s2; __syncthreads();
    for (int t = 128; t; t >>= 1) {
        if (threadIdx.x < t) {
            rs[threadIdx.x]  += rs[threadIdx.x + t];
            rs2[threadIdx.x] += rs2[threadIdx.x + t];
        }
        __syncthreads();
    }
    if (threadIdx.x == 0) {
        float mean = rs[0] / 153664.f;
        float var  = rs2[0] / 153664.f - mean * mean;
        gn[z] = rsqrtf(var + 1e-5f);
    }
}

// ---------------------------------------------------------------------------
// Fused exp-softmax + P@V GEMM (one branch).  M=196, N=64, K=784 per z (128).
// p = exp(g*(x - rowmax)); denominator accumulated in smem (each block spans
// all of K); epilogue divides.  TBN=64, TBK=16, double-buffered static smem.
// ---------------------------------------------------------------------------
__global__ __launch_bounds__(256)
void attn_pv_kernel(const float* __restrict__ attn, const float* __restrict__ V,
                    float* __restrict__ ctx,
                    const float* __restrict__ rm, const float* __restrict__ gn)
{
    const int Mv = 196, Kv = 784;
    int z = blockIdx.z;               // 0..127 = b*4+h
    int bb = z >> 2, hh = z & 3;
    const float* A = attn + (long long)bb * 614656 + (long long)hh * 153664;
    const float* B = V    + (long long)bb * 200704 + hh * 64;
    float*       C = ctx  + (long long)bb * 50176  + hh * 64;
    const float  gv  = gn[z];
    const float* rmz = rm + (long long)z * 196;

    __shared__ __align__(16) __nv_bfloat16 As[2][2][128][A_STRIDE];    // 24 KB
    __shared__ __align__(16) __nv_bfloat16 Bs[2][2][TBK][PVB_STRIDE];  // 9 KB
    __shared__ float sden[128];

    const int tid  = threadIdx.x;
    const int lane = tid & 31;
    const int wid  = tid >> 5;
    const int wm   = wid >> 1;   // 0..3 : 32 rows each
    const int wn   = wid & 1;    // 0..1 : 32 cols each
    const int m0 = blockIdx.y * 128;

    if (tid < 128) sden[tid] = 0.f;

    float acc[2][4][4];
#pragma unroll
    for (int i = 0; i < 2; i++)
#pragma unroll
        for (int j = 0; j < 4; j++)
#pragma unroll
            for (int r = 0; r < 4; r++) acc[i][j][r] = 0.f;

    const int ar  = tid >> 2, ac4 = tid & 3;   // A: 64 rows/pass, 4 f4/row
    const int brr = tid >> 4, bc4 = tid & 15;  // B: 16 rows, 16 f4/row, 1 pass

    float4 aPre[2], bPre;
    int k0s = 0;

#define PV_LOAD(K0)                                                             \
    {                                                                           \
        int k0_ = (K0);                                                         \
        _Pragma("unroll")                                                       \
        for (int i = 0; i < 2; i++) {                                           \
            int gm = m0 + ar + i * 64, gk = k0_ + ac4 * 4;                      \
            aPre[i] = (gm < Mv && gk < Kv)                                      \
                ? *(const float4*)&A[(long long)gm * 784 + gk]                  \
                : make_float4(0.f, 0.f, 0.f, 0.f);                              \
        }                                                                       \
        {                                                                       \
            int gk = k0_ + brr;                                                 \
            bPre = (gk < Kv)                                                    \
                ? *(const float4*)&B[(long long)gk * 256 + bc4 * 4]             \
                : make_float4(0.f, 0.f, 0.f, 0.f);                              \
        }                                                                       \
        k0s = k0_;                                                              \
    }

#define PV_STORE(s)                                                             \
    {                                                                           \
        _Pragma("unroll")                                                       \
        for (int i = 0; i < 2; i++) {                                           \
            int m = ar + i * 64, gm = m0 + m;                                   \
            bool rok = (gm < Mv);                                               \
            float rmv = rok ? rmz[gm] : 0.f;                                    \
            float4 e4;                                                          \
            float vv[4] = { aPre[i].x, aPre[i].y, aPre[i].z, aPre[i].w };       \
            float ee[4];                                                        \
            _Pragma("unroll")                                                   \
            for (int cc = 0; cc < 4; cc++) {                                    \
                int gk = k0s + ac4 * 4 + cc;                                    \
                ee[cc] = (rok && gk < Kv) ? __expf(gv * (vv[cc] - rmv)) : 0.f;  \
            }                                                                   \
            e4 = make_float4(ee[0], ee[1], ee[2], ee[3]);                       \
            float part = ee[0] + ee[1] + ee[2] + ee[3];                         \
            cvt_store4(&As[s][0][m][ac4 * 4], &As[s][1][m][ac4 * 4], e4);       \
            if (part != 0.f) atomicAdd(&sden[m], part);                         \
        }                                                                       \
        {                                                                       \
            int k = brr, c = bc4 * 4;                                           \
            cvt_store4(&Bs[s][0][k][c], &Bs[s][1][k][c], bPre);                 \
        }                                                                       \
    }

    const int ktiles = (Kv + TBK - 1) / TBK;   // 49

    PV_LOAD(0);
    __syncthreads();           // sden init visible before first atomicAdd
    PV_STORE(0);
    __syncthreads();

    for (int t = 0; t < ktiles; t++) {
        const int cur = t & 1;
        bool last = (t == ktiles - 1);
        if (!last) PV_LOAD((t + 1) * TBK);
        {
            uint32_t Ah[2][4], Al[2][4], Bh[4][2], Bl[4][2];
#pragma unroll
            for (int i = 0; i < 2; i++) {
                int row = wm * 32 + i * 16 + (lane & 15);
                int col = (lane >> 4) << 3;
                ldsm_x4(Ah[i][0], Ah[i][1], Ah[i][2], Ah[i][3],
                        smem_u32(&As[cur][0][row][col]));
                ldsm_x4(Al[i][0], Al[i][1], Al[i][2], Al[i][3],
                        smem_u32(&As[cur][1][row][col]));
            }
            {
                int row = lane & 15;
                int col = wn * 32 + ((lane >> 4) << 3);
                uint32_t r0, r1, r2, r3;
                ldsm_x4_t(r0, r1, r2, r3, smem_u32(&Bs[cur][0][row][col]));
                Bh[0][0] = r0; Bh[0][1] = r1; Bh[1][0] = r2; Bh[1][1] = r3;
                ldsm_x4_t(r0, r1, r2, r3, smem_u32(&Bs[cur][0][row][col + 16]));
                Bh[2][0] = r0; Bh[2][1] = r1; Bh[3][0] = r2; Bh[3][1] = r3;
                ldsm_x4_t(r0, r1, r2, r3, smem_u32(&Bs[cur][1][row][col]));
                Bl[0][0] = r0; Bl[0][1] = r1; Bl[1][0] = r2; Bl[1][1] = r3;
                ldsm_x4_t(r0, r1, r2, r3, smem_u32(&Bs[cur][1][row][col + 16]));
                Bl[2][0] = r0; Bl[2][1] = r1; Bl[3][0] = r2; Bl[3][1] = r3;
            }
#pragma unroll
            for (int i = 0; i < 2; i++)
#pragma unroll
                for (int j = 0; j < 4; j++) {
                    mma_bf16(acc[i][j], Ah[i], Bh[j]);
                    mma_bf16(acc[i][j], Ah[i], Bl[j]);
                    mma_bf16(acc[i][j], Al[i], Bh[j]);
                }
        }
        if (!last) {
            PV_STORE(cur ^ 1);
            __syncthreads();
        }
    }

    const int g  = lane >> 2;
    const int tg = lane & 3;
#pragma unroll
    for (int i = 0; i < 2; i++) {
        int lr0 = wm * 32 + i * 16 + g;
        int lr1 = lr0 + 8;
        int r0w = m0 + lr0, r1w = m0 + lr1;
        float d0 = (r0w < Mv) ? 1.0f / sden[lr0] : 0.f;
        float d1 = (r1w < Mv) ? 1.0f / sden[lr1] : 0.f;
#pragma unroll
        for (int j = 0; j < 4; j++) {
            int c0 = wn * 32 + j * 8 + tg * 2;
            if (r0w < Mv) {
                float2 v = make_float2(acc[i][j][0] * d0, acc[i][j][1] * d0);
                *(float2*)&C[(long long)r0w * 256 + c0] = v;
            }
            if (r1w < Mv) {
                float2 v = make_float2(acc[i][j][2] * d1, acc[i][j][3] * d1);
                *(float2*)&C[(long long)r1w * 256 + c0] = v;
            }
        }
    }
#undef PV_LOAD
#undef PV_STORE
}

// ---------------------------------------------------------------------------
// Small helpers
// ---------------------------------------------------------------------------
__global__ void transpose_kernel(const float* __restrict__ src, float* __restrict__ dst,
                                 int M, int N)
{
    __shared__ float t[32][33];
    int x = blockIdx.x * 32 + threadIdx.x;
    int y0 = blockIdx.y * 32 + threadIdx.y;
#pragma unroll
    for (int i = 0; i < 32; i += 8) {
        int y = y0 + i;
        t[threadIdx.y + i][threadIdx.x] = (y < M && x < N) ? src[(long long)y * N + x] : 0.f;
    }
    __syncthreads();
    int xo = blockIdx.y * 32 + threadIdx.x;
    int yo0 = blockIdx.x * 32 + threadIdx.y;
#pragma unroll
    for (int i = 0; i < 32; i += 8) {
        int yo = yo0 + i;
        if (yo < N && xo < M) dst[(long long)yo * M + xo] = t[threadIdx.x][threadIdx.y + i];
    }
}

// Pack up to 4 separate buffers into one contiguous [grid.y][n] buffer.
__global__ void pack4_kernel(const float* __restrict__ p0, const float* __restrict__ p1,
                             const float* __restrict__ p2, const float* __restrict__ p3,
                             float* __restrict__ dst, long long n)
{
    long long i = (long long)blockIdx.x * 256 + threadIdx.x;
    int br = blockIdx.y;
    if (i < n) {
        const float* src = (br == 0) ? p0 : (br == 1) ? p1 : (br == 2) ? p2 : p3;
        dst[(long long)br * n + i] = src[i];
    }
}

// KV_S[b, j*196+t, c] = T_hat[b, t, j*256 + c]
__global__ void kvs_kernel(const float* __restrict__ T, float* __restrict__ KVS)
{
    long long i = (long long)blockIdx.x * blockDim.x + threadIdx.x;
    if (i >= SZ_BNDC) return;
    int c = (int)(i & 255);
    long long t2 = i >> 8;
    int n = (int)(t2 % 784);
    int b = (int)(t2 / 784);
    int j = n / 196, t = n % 196;
    KVS[i] = T[((long long)b * 196 + t) * 1024 + (long long)j * 256 + c];
}

// Plain row softmax (SATAT scores, 196 cols)
__global__ void softmax_kernel(float* __restrict__ X, int cols)
{
    int row = blockIdx.x;
    float* x = X + (long long)row * cols;
    int tid = threadIdx.x;
    __shared__ float red[256];

    float m = -1e30f;
    for (int c = tid; c < cols; c += 256) m = fmaxf(m, x[c]);
    red[tid] = m; __syncthreads();
    for (int s = 128; s > 0; s >>= 1) {
        if (tid < s) red[tid] = fmaxf(red[tid], red[tid + s]);
        __syncthreads();
    }
    m = red[0]; __syncthreads();

    float sum = 0.f;
    for (int c = tid; c < cols; c += 256) {
        float e = __expf(x[c] - m);
        x[c] = e; sum += e;
    }
    red[tid] = sum; __syncthreads();
    for (int s = 128; s > 0; s >>= 1) {
        if (tid < s) red[tid] += red[tid + s];
        __syncthreads();
    }
    float inv = 1.0f / red[0];
    for (int c = tid; c < cols; c += 256) x[c] *= inv;
}

// ---------------------------------------------------------------------------
// Host-side driver
// ---------------------------------------------------------------------------
static inline void gemm(int tb,
                        const float* A, const float* B, float* C,
                        int M, int N, int K, int lda, int ldb, int ldc,
                        long long sAb, long long sAh,
                        long long sBb, long long sBh,
                        long long sCb, long long sCh,
                        int batch, int nh, float alpha)
{
    dim3 g((N + TBN - 1) / TBN, (M + TBM - 1) / TBM, batch), b(256);
    if (tb)
        gemm_mma<true><<<g, b>>>(A, B, C, M, N, K, lda, ldb, ldc,
                                 sAb, sAh, sBb, sBh, sCb, sCh, nh, alpha);
    else
        gemm_mma<false><<<g, b>>>(A, B, C, M, N, K, lda, ldb, ldc,
                                  sAb, sAh, sBb, sBh, sCb, sCh, nh, alpha);
}

extern "C" void kernel_launch(void* const* d_in, const int* in_sizes, int n_in,
                              void* d_out, int out_size)
{
    const float* emb[4] = { (const float*)d_in[0], (const float*)d_in[1],
                            (const float*)d_in[2], (const float*)d_in[3] };
    const float* emb_C = (const float*)d_in[4];
    const float* Wq_c  = (const float*)d_in[5];
    const float* Wk_c  = (const float*)d_in[6];
    const float* Wv_c  = (const float*)d_in[7];
    const float* Wo_c  = (const float*)d_in[8];
    const float* Wq[4] = { (const float*)d_in[9],  (const float*)d_in[10],
                           (const float*)d_in[11], (const float*)d_in[12] };
    const float* Wk    = (const float*)d_in[13];
    const float* Wv    = (const float*)d_in[14];
    const float* Wo[4] = { (const float*)d_in[15], (const float*)d_in[16],
                           (const float*)d_in[17], (const float*)d_in[18] };
    float* out = (float*)d_out;

    float *q3, *k3, *v3, *sc, *oat, *that, *kvs, *Kb, *Vb, *attn;
    float *gain, *rowmax, *WkT, *WvT, *WqT;
    cudaGetSymbolAddress((void**)&q3,    g_q3);
    cudaGetSymbolAddress((void**)&k3,    g_k3);
    cudaGetSymbolAddress((void**)&v3,    g_v3);
    cudaGetSymbolAddress((void**)&sc,    g_sc);
    cudaGetSymbolAddress((void**)&oat,   g_oat);
    cudaGetSymbolAddress((void**)&that,  g_that);
    cudaGetSymbolAddress((void**)&kvs,   g_kvs);
    cudaGetSymbolAddress((void**)&Kb,    g_Kb);
    cudaGetSymbolAddress((void**)&Vb,    g_Vb);
    cudaGetSymbolAddress((void**)&attn,  g_attn);
    cudaGetSymbolAddress((void**)&gain,  g_gain);
    cudaGetSymbolAddress((void**)&rowmax,g_rowmax);
    cudaGetSymbolAddress((void**)&WkT,   g_WkT);
    cudaGetSymbolAddress((void**)&WvT,   g_WvT);
    cudaGetSymbolAddress((void**)&WqT,   g_WqT);

    // ---------------- Weight pre-transposes ----------------
    {
        dim3 b(32, 8);
        dim3 g784((784 + 31) / 32, (784 + 31) / 32);
        transpose_kernel<<<g784, b>>>(Wk, WkT, 784, 784);
        transpose_kernel<<<g784, b>>>(Wv, WvT, 784, 784);
        dim3 g196((196 + 31) / 32, (196 + 31) / 32);
        for (int i = 0; i < 4; i++)
            transpose_kernel<<<g196, b>>>(Wq[i], WqT + (long long)i * 38416, 196, 196);
    }

    // ---------------- Stage A: SATAT over emb_C ----------------
    // Fused QKV: pack Wq_c|Wk_c|Wv_c into g_q3 (dead scratch), write q/k/v
    // into the attn buffer (dead during stage A): q=attn, k=attn+S, v=attn+2S.
    float* Wqkv = q3;                       // 3*1048576 floats = 12.6 MB
    float* qv   = attn;                     // q slab
    float* kvh  = attn + SZ_BNDC;           // k slab
    float* vv   = attn + 2 * SZ_BNDC;       // v slab
    pack4_kernel<<<dim3(4096, 3), 256>>>(Wq_c, Wk_c, Wv_c, Wv_c, Wqkv, 1048576LL);
    // One launch, batch=3 (z=0:Q, 1:K, 2:V) -> 1176 blocks (~4 full waves)
    gemm(0, emb_C, Wqkv, qv, 6272, 1024, 1024, 1024, 1024, 1024,
         0, 0, 1048576, 0, SZ_BNDC, 0, 3, 1, 1.0f);

    gemm(1, qv, kvh, sc, 196, 196, 256, 1024, 1024, 196,
         200704, 256, 200704, 256, 153664, 38416, 128, 4, 0.0625f);
    softmax_kernel<<<25088, 256>>>(sc, 196);
    gemm(0, sc, vv, oat, 196, 256, 196, 196, 1024, 1024,
         153664, 38416, 200704, 256, 200704, 256, 128, 4, 1.0f);
    gemm(0, oat, Wo_c, that, 6272, 1024, 1024, 1024, 1024, 1024,
         0, 0, 0, 0, 0, 0, 1, 1, 1.0f);

    // ---------------- Stage B: KV token mix ----------------
    kvs_kernel<<<(unsigned)((SZ_BNDC + 255) / 256), 256>>>(that, kvs);
    gemm(0, WkT, kvs, Kb, 784, 256, 784, 784, 256, 256,
         0, 0, 200704, 0, 200704, 0, 32, 1, 1.0f);
    gemm(0, WvT, kvs, Vb, 784, 256, 784, 784, 256, 256,
         0, 0, 200704, 0, 200704, 0, 32, 1, 1.0f);

    // ---------------- Stage C: 4 branches ----------------
    // Stage-A/B scratch now dead; reuse:
    //   embP = g_q3 (packed emb[4]), Qb4 = g_k3, WoP = g_v3, ctx4 = g_oat.
    float* embP = q3;
    float* Qb4  = k3;
    float* WoP  = v3;
    float* ctx4 = oat;
    pack4_kernel<<<dim3((unsigned)((SZ_Q + 255) / 256), 4), 256>>>(
        emb[0], emb[1], emb[2], emb[3], embP, SZ_Q);
    pack4_kernel<<<dim3(256, 4), 256>>>(
        Wo[0], Wo[1], Wo[2], Wo[3], WoP, 65536);

    // Batched Q-mix: z = br*32 + b  (512 blocks, one launch)
    gemm(0, WqT, embP, Qb4, 196, 256, 196, 196, 256, 256,
         38416, 0, SZ_Q, 50176, SZ_Q, 50176, 128, 32, 1.0f);

    // QK + stats + fused softmax-PV per branch
    for (int br = 0; br < 4; br++) {
        const float* Qb = Qb4 + (long long)br * SZ_Q;
        gemm(1, Qb, Kb, attn, 196, 784, 64, 256, 256, 784,
             50176, 64, 200704, 64, 614656, 153664, 128, 4, 1.0f);
        attn_stats_kernel<<<128, 256>>>(attn, rowmax, gain);
        dim3 g(1, 2, 128), b(256);
        attn_pv_kernel<<<g, b>>>(attn, Vb, ctx4 + (long long)br * SZ_Q,
                                 rowmax, gain);
    }

    // Batched Wo: z = br  (392 blocks, one launch)
    gemm(0, ctx4, WoP, out, 6272, 256, 256, 256, 256, 256,
         SZ_Q, 0, 65536, 0, SZ_Q, 0, 4, 1, 1.0f);
}

// round 12
// speedup vs baseline: 4.5410x; 1.1003x over previous
#include <cuda_runtime.h>
#include <cuda_bf16.h>
#include <cstdint>

// ---------------------------------------------------------------------------
// Problem constants: B=32, N=196, DQ=256, DC=1024, H=4, DH=64, DHC=256, 4N=784
// ---------------------------------------------------------------------------

#define SZ_BNDC   6422528LL   // 32*196*1024  (also 32*784*256)
#define SZ_SC     4917248LL   // 32*4*196*196
#define SZ_Q      1605632LL   // 32*196*256
#define SZ_ATTN  19668992LL   // 32*4*196*784 (one branch)

// Scratch (device .bss, allocation-free) — identical footprint to the
// known-good round-11 kernel (~322 MB).
__device__ float g_q3[SZ_BNDC];
__device__ float g_k3[SZ_BNDC];
__device__ float g_v3[SZ_BNDC];
__device__ float g_sc[SZ_SC];
__device__ float g_oat[SZ_BNDC];
__device__ float g_that[SZ_BNDC];
__device__ float g_kvs[SZ_BNDC];
__device__ float g_Kb[SZ_BNDC];
__device__ float g_Vb[SZ_BNDC];
__device__ float g_Qb[SZ_Q];
__device__ float g_attn[SZ_ATTN];
__device__ float g_ctx[SZ_Q];        // stage-C: stats partial sums scratch
__device__ float g_gain[128];
__device__ float g_rowmax[128 * 196];
__device__ float g_WkT[614656];       // 784*784
__device__ float g_WvT[614656];
__device__ float g_WqT[4 * 38416];    // 4 * 196*196

// ---------------------------------------------------------------------------
// PTX helpers
// ---------------------------------------------------------------------------
__device__ __forceinline__ uint32_t smem_u32(const void* p) {
    return (uint32_t)__cvta_generic_to_shared(p);
}

__device__ __forceinline__ void ldsm_x4(uint32_t& r0, uint32_t& r1,
                                        uint32_t& r2, uint32_t& r3, uint32_t addr) {
    asm volatile("ldmatrix.sync.aligned.m8n8.x4.shared.b16 {%0,%1,%2,%3},[%4];"
                 : "=r"(r0), "=r"(r1), "=r"(r2), "=r"(r3) : "r"(addr));
}

__device__ __forceinline__ void ldsm_x4_t(uint32_t& r0, uint32_t& r1,
                                          uint32_t& r2, uint32_t& r3, uint32_t addr) {
    asm volatile("ldmatrix.sync.aligned.m8n8.x4.trans.shared.b16 {%0,%1,%2,%3},[%4];"
                 : "=r"(r0), "=r"(r1), "=r"(r2), "=r"(r3) : "r"(addr));
}

__device__ __forceinline__ void mma_bf16(float* c, const uint32_t* a, const uint32_t* b) {
    asm volatile("mma.sync.aligned.m16n8k16.row.col.f32.bf16.bf16.f32 "
                 "{%0,%1,%2,%3},{%4,%5,%6,%7},{%8,%9},{%0,%1,%2,%3};"
                 : "+f"(c[0]), "+f"(c[1]), "+f"(c[2]), "+f"(c[3])
                 : "r"(a[0]), "r"(a[1]), "r"(a[2]), "r"(a[3]),
                   "r"(b[0]), "r"(b[1]));
}

// Split-convert 4 consecutive fp32 into hi/lo bf16 planes with ONE 8-byte
// store per plane (addresses are 8B-aligned: row strides 24/136/72 bf16).
__device__ __forceinline__ void cvt_store4(__nv_bfloat16* hi, __nv_bfloat16* lo,
                                           float4 v) {
    __nv_bfloat16 h0 = __float2bfloat16(v.x), h1 = __float2bfloat16(v.y);
    __nv_bfloat16 h2 = __float2bfloat16(v.z), h3 = __float2bfloat16(v.w);
    __nv_bfloat162 hA = __halves2bfloat162(h0, h1);
    __nv_bfloat162 hB = __halves2bfloat162(h2, h3);
    uint2 hp; hp.x = *(uint32_t*)&hA; hp.y = *(uint32_t*)&hB;
    *(uint2*)hi = hp;
    __nv_bfloat162 lA = __halves2bfloat162(
        __float2bfloat16(v.x - __bfloat162float(h0)),
        __float2bfloat16(v.y - __bfloat162float(h1)));
    __nv_bfloat162 lB = __halves2bfloat162(
        __float2bfloat16(v.z - __bfloat162float(h2)),
        __float2bfloat16(v.w - __bfloat162float(h3)));
    uint2 lp; lp.x = *(uint32_t*)&lA; lp.y = *(uint32_t*)&lB;
    *(uint2*)lo = lp;
}

// ---------------------------------------------------------------------------
// Tile geometry: 128x128 block tile, TBK=16, double-buffered STATIC smem.
// ---------------------------------------------------------------------------
#define TBM 128
#define TBN 128
#define TBK 16
#define A_STRIDE 24                 // TBK + 8 pad
#define B_STRIDE 136                // TBN + 8 pad
#define PVB_STRIDE 72               // 64 + 8 pad

// ---------------------------------------------------------------------------
// Tensor-core batched GEMM, split-bf16 (3 MMA) fp32 emulation.
// Double-buffered static smem, vectorized (STS.64) split-convert fill.
//   C = alpha * A @ op(B);  A [M,K] row-major.
//   TB=false: B [K,N] row-major.  TB=true: B [N,K] row-major.
// Batch: z = bb*nh + hh, pointer offsets sXb/sXh.
// ---------------------------------------------------------------------------
template<bool TB>
__global__ __launch_bounds__(256)
void gemm_mma(const float* __restrict__ A, const float* __restrict__ B,
              float* __restrict__ C,
              int M, int N, int K, int lda, int ldb, int ldc,
              long long sAb, long long sAh, long long sBb, long long sBh,
              long long sCb, long long sCh, int nh, float alpha)
{
    int z  = blockIdx.z;
    int bb = z / nh, hh = z % nh;
    A += bb * sAb + hh * sAh;
    B += bb * sBb + hh * sBh;
    C += bb * sCb + hh * sCh;

    __shared__ __align__(16) __nv_bfloat16 As[2][2][TBM][A_STRIDE];  // 24.0 KB
    __shared__ __align__(16) __nv_bfloat16 Bs[2][2][TBK][B_STRIDE];  // 17.0 KB

    const int tid  = threadIdx.x;
    const int lane = tid & 31;
    const int wid  = tid >> 5;
    const int wm   = wid >> 2;
    const int wn   = wid & 3;
    const int m0 = blockIdx.y * TBM, n0 = blockIdx.x * TBN;

    float acc[4][4][4];
#pragma unroll
    for (int i = 0; i < 4; i++)
#pragma unroll
        for (int j = 0; j < 4; j++)
#pragma unroll
            for (int r = 0; r < 4; r++) acc[i][j][r] = 0.f;

    const int ar  = tid >> 2, ac4 = tid & 3;    // A: 64 rows/pass, 4 f4/row
    const int bkr = tid >> 5, bc4 = tid & 31;   // B NN: 8 k-rows/pass, 32 f4/row
    const int bnr = tid >> 2, bk4 = tid & 3;    // B NT: 64 n-rows/pass, 4 f4/row

    float4 aPre[2], bPre[2];

#define LOAD_REGS(K0)                                                           \
    {                                                                           \
        int k0_ = (K0);                                                         \
        _Pragma("unroll")                                                       \
        for (int i = 0; i < 2; i++) {                                           \
            int gm = m0 + ar + i * 64, gk = k0_ + ac4 * 4;                      \
            aPre[i] = (gm < M && gk < K)                                        \
                ? *(const float4*)&A[(long long)gm * lda + gk]                  \
                : make_float4(0.f, 0.f, 0.f, 0.f);                              \
        }                                                                       \
        if (!TB) {                                                              \
            _Pragma("unroll")                                                   \
            for (int i = 0; i < 2; i++) {                                       \
                int gk = k0_ + bkr + i * 8, gn = n0 + bc4 * 4;                  \
                bPre[i] = (gk < K && gn < N)                                    \
                    ? *(const float4*)&B[(long long)gk * ldb + gn]              \
                    : make_float4(0.f, 0.f, 0.f, 0.f);                          \
            }                                                                   \
        } else {                                                                \
            _Pragma("unroll")                                                   \
            for (int i = 0; i < 2; i++) {                                       \
                int gn = n0 + bnr + i * 64, gk = k0_ + bk4 * 4;                 \
                bPre[i] = (gn < N && gk < K)                                    \
                    ? *(const float4*)&B[(long long)gn * ldb + gk]              \
                    : make_float4(0.f, 0.f, 0.f, 0.f);                          \
            }                                                                   \
        }                                                                       \
    }

#define CVT_B_SC(s, dr, dc, f)                                                  \
    {                                                                           \
        __nv_bfloat16 hi_ = __float2bfloat16(f);                                \
        Bs[s][0][dr][dc] = hi_;                                                 \
        Bs[s][1][dr][dc] = __float2bfloat16((f) - __bfloat162float(hi_));       \
    }

#define STORE_SMEM(s)                                                           \
    {                                                                           \
        _Pragma("unroll")                                                       \
        for (int i = 0; i < 2; i++) {                                           \
            int m = ar + i * 64, c = ac4 * 4;                                   \
            cvt_store4(&As[s][0][m][c], &As[s][1][m][c], aPre[i]);              \
        }                                                                       \
        if (!TB) {                                                              \
            _Pragma("unroll")                                                   \
            for (int i = 0; i < 2; i++) {                                       \
                int k = bkr + i * 8, c = bc4 * 4;                               \
                cvt_store4(&Bs[s][0][k][c], &Bs[s][1][k][c], bPre[i]);          \
            }                                                                   \
        } else {                                                                \
            _Pragma("unroll")                                                   \
            for (int i = 0; i < 2; i++) {                                       \
                int n = bnr + i * 64, k = bk4 * 4;                              \
                CVT_B_SC(s, k + 0, n, bPre[i].x); CVT_B_SC(s, k + 1, n, bPre[i].y); \
                CVT_B_SC(s, k + 2, n, bPre[i].z); CVT_B_SC(s, k + 3, n, bPre[i].w); \
            }                                                                   \
        }                                                                       \
    }

#define COMPUTE(s)                                                              \
    {                                                                           \
        uint32_t Ah[4][4], Al[4][4], Bh[4][2], Bl[4][2];                        \
        _Pragma("unroll")                                                       \
        for (int i = 0; i < 4; i++) {                                           \
            int row = wm * 64 + i * 16 + (lane & 15);                           \
            int col = (lane >> 4) << 3;                                         \
            ldsm_x4(Ah[i][0], Ah[i][1], Ah[i][2], Ah[i][3],                     \
                    smem_u32(&As[s][0][row][col]));                             \
            ldsm_x4(Al[i][0], Al[i][1], Al[i][2], Al[i][3],                     \
                    smem_u32(&As[s][1][row][col]));                             \
        }                                                                       \
        _Pragma("unroll")                                                       \
        for (int t2 = 0; t2 < 2; t2++) {                                        \
            int row = lane & 15;                                                \
            int col = wn * 32 + t2 * 16 + ((lane >> 4) << 3);                   \
            uint32_t r0, r1, r2, r3;                                            \
            ldsm_x4_t(r0, r1, r2, r3, smem_u32(&Bs[s][0][row][col]));           \
            Bh[t2*2][0] = r0; Bh[t2*2][1] = r1;                                 \
            Bh[t2*2+1][0] = r2; Bh[t2*2+1][1] = r3;                             \
            ldsm_x4_t(r0, r1, r2, r3, smem_u32(&Bs[s][1][row][col]));           \
            Bl[t2*2][0] = r0; Bl[t2*2][1] = r1;                                 \
            Bl[t2*2+1][0] = r2; Bl[t2*2+1][1] = r3;                             \
        }                                                                       \
        _Pragma("unroll")                                                       \
        for (int i = 0; i < 4; i++)                                             \
            _Pragma("unroll")                                                   \
            for (int j = 0; j < 4; j++) {                                       \
                mma_bf16(acc[i][j], Ah[i], Bh[j]);                              \
                mma_bf16(acc[i][j], Ah[i], Bl[j]);                              \
                mma_bf16(acc[i][j], Al[i], Bh[j]);                              \
            }                                                                   \
    }

    const int ktiles = (K + TBK - 1) / TBK;

    LOAD_REGS(0);
    STORE_SMEM(0);
    __syncthreads();

    for (int t = 0; t < ktiles; t++) {
        const int cur = t & 1;
        bool last = (t == ktiles - 1);
        if (!last) LOAD_REGS((t + 1) * TBK);
        COMPUTE(cur);
        if (!last) {
            STORE_SMEM(cur ^ 1);      // other stage: prior sync drained its readers
            __syncthreads();
        }
    }

    const int g  = lane >> 2;
    const int tg = lane & 3;
#pragma unroll
    for (int i = 0; i < 4; i++) {
        int r0w = m0 + wm * 64 + i * 16 + g;
        int r1w = r0w + 8;
#pragma unroll
        for (int j = 0; j < 4; j++) {
            int c0 = n0 + wn * 32 + j * 8 + tg * 2;
            if (c0 < N) {
                if (r0w < M) {
                    float2 v = make_float2(alpha * acc[i][j][0], alpha * acc[i][j][1]);
                    *(float2*)&C[(long long)r0w * ldc + c0] = v;
                }
                if (r1w < M) {
                    float2 v = make_float2(alpha * acc[i][j][2], alpha * acc[i][j][3]);
                    *(float2*)&C[(long long)r1w * ldc + c0] = v;
                }
            }
        }
    }
#undef LOAD_REGS
#undef STORE_SMEM
#undef COMPUTE
#undef CVT_B_SC
}

// ---------------------------------------------------------------------------
// Attention stats, split for occupancy: 512 blocks, zz = z*4 + chunk.
// Each block handles 49 rows of one (b,h): writes their rowmax and a partial
// (sum, sumsq) pair into part[zz*2..+1].  Finalize kernel folds 4 partials
// into the instance-norm gain.
// ---------------------------------------------------------------------------
__global__ __launch_bounds__(256)
void attn_stats_part(const float* __restrict__ attn,
                     float* __restrict__ rm, float* __restrict__ part)
{
    int zz = blockIdx.x;            // 0..511
    int z = zz >> 2, chunk = zz & 3;
    const float* X = attn + (long long)z * 153664;
    int warp = threadIdx.x >> 5, lane = threadIdx.x & 31;
    int r0 = chunk * 49, r1 = r0 + 49;
    float s = 0.f, s2 = 0.f;
    for (int r = r0 + warp; r < r1; r += 8) {
        const float* row = X + (long long)r * 784;
        float m = -1e30f;
        for (int c = lane; c < 784; c += 32) {
            float v = row[c];
            m = fmaxf(m, v); s += v; s2 += v * v;
        }
#pragma unroll
        for (int o = 16; o; o >>= 1) m = fmaxf(m, __shfl_xor_sync(~0u, m, o));
        if (lane == 0) rm[(long long)z * 196 + r] = m;
    }
    __shared__ float rs[256], rs2[256];
    rs[threadIdx.x] = s; rs2[threadIdx.x] = s2; __syncthreads();
    for (int t = 128; t; t >>= 1) {
        if (threadIdx.x < t) {
            rs[threadIdx.x]  += rs[threadIdx.x + t];
            rs2[threadIdx.x] += rs2[threadIdx.x + t];
        }
        __syncthreads();
    }
    if (threadIdx.x == 0) {
        part[zz * 2 + 0] = rs[0];
        part[zz * 2 + 1] = rs2[0];
    }
}

__global__ void attn_stats_fin(const float* __restrict__ part, float* __restrict__ gn)
{
    int z = threadIdx.x;            // 128 threads, 1 block
    float s = 0.f, s2 = 0.f;
#pragma unroll
    for (int c = 0; c < 4; c++) {
        s  += part[(z * 4 + c) * 2 + 0];
        s2 += part[(z * 4 + c) * 2 + 1];
    }
    float mean = s / 153664.f;
    float var  = s2 / 153664.f - mean * mean;
    gn[z] = rsqrtf(var + 1e-5f);
}

// ---------------------------------------------------------------------------
// Fused exp-softmax + P@V GEMM (one branch).  M=196, N=64, K=784 per z (128).
// p = exp(g*(x - rowmax)); denominator accumulated in smem (each block spans
// all of K); epilogue divides.  TBN=64, TBK=16, double-buffered static smem.
// ---------------------------------------------------------------------------
__global__ __launch_bounds__(256)
void attn_pv_kernel(const float* __restrict__ attn, const float* __restrict__ V,
                    float* __restrict__ ctx,
                    const float* __restrict__ rm, const float* __restrict__ gn)
{
    const int Mv = 196, Kv = 784;
    int z = blockIdx.z;               // 0..127 = b*4+h
    int bb = z >> 2, hh = z & 3;
    const float* A = attn + (long long)bb * 614656 + (long long)hh * 153664;
    const float* B = V    + (long long)bb * 200704 + hh * 64;
    float*       C = ctx  + (long long)bb * 50176  + hh * 64;
    const float  gv  = gn[z];
    const float* rmz = rm + (long long)z * 196;

    __shared__ __align__(16) __nv_bfloat16 As[2][2][128][A_STRIDE];    // 24 KB
    __shared__ __align__(16) __nv_bfloat16 Bs[2][2][TBK][PVB_STRIDE];  // 9 KB
    __shared__ float sden[128];

    const int tid  = threadIdx.x;
    const int lane = tid & 31;
    const int wid  = tid >> 5;
    const int wm   = wid >> 1;   // 0..3 : 32 rows each
    const int wn   = wid & 1;    // 0..1 : 32 cols each
    const int m0 = blockIdx.y * 128;

    if (tid < 128) sden[tid] = 0.f;

    float acc[2][4][4];
#pragma unroll
    for (int i = 0; i < 2; i++)
#pragma unroll
        for (int j = 0; j < 4; j++)
#pragma unroll
            for (int r = 0; r < 4; r++) acc[i][j][r] = 0.f;

    const int ar  = tid >> 2, ac4 = tid & 3;   // A: 64 rows/pass, 4 f4/row
    const int brr = tid >> 4, bc4 = tid & 15;  // B: 16 rows, 16 f4/row, 1 pass

    float4 aPre[2], bPre;
    int k0s = 0;

#define PV_LOAD(K0)                                                             \
    {                                                                           \
        int k0_ = (K0);                                                         \
        _Pragma("unroll")                                                       \
        for (int i = 0; i < 2; i++) {                                           \
            int gm = m0 + ar + i * 64, gk = k0_ + ac4 * 4;                      \
            aPre[i] = (gm < Mv && gk < Kv)                                      \
                ? *(const float4*)&A[(long long)gm * 784 + gk]                  \
                : make_float4(0.f, 0.f, 0.f, 0.f);                              \
        }                                                                       \
        {                                                                       \
            int gk = k0_ + brr;                                                 \
            bPre = (gk < Kv)                                                    \
                ? *(const float4*)&B[(long long)gk * 256 + bc4 * 4]             \
                : make_float4(0.f, 0.f, 0.f, 0.f);                              \
        }                                                                       \
        k0s = k0_;                                                              \
    }

#define PV_STORE(s)                                                             \
    {                                                                           \
        _Pragma("unroll")                                                       \
        for (int i = 0; i < 2; i++) {                                           \
            int m = ar + i * 64, gm = m0 + m;                                   \
            bool rok = (gm < Mv);                                               \
            float rmv = rok ? rmz[gm] : 0.f;                                    \
            float4 e4;                                                          \
            float vv[4] = { aPre[i].x, aPre[i].y, aPre[i].z, aPre[i].w };       \
            float ee[4];                                                        \
            _Pragma("unroll")                                                   \
            for (int cc = 0; cc < 4; cc++) {                                    \
                int gk = k0s + ac4 * 4 + cc;                                    \
                ee[cc] = (rok && gk < Kv) ? __expf(gv * (vv[cc] - rmv)) : 0.f;  \
            }                                                                   \
            e4 = make_float4(ee[0], ee[1], ee[2], ee[3]);                       \
            float part = ee[0] + ee[1] + ee[2] + ee[3];                         \
            cvt_store4(&As[s][0][m][ac4 * 4], &As[s][1][m][ac4 * 4], e4);       \
            if (part != 0.f) atomicAdd(&sden[m], part);                         \
        }                                                                       \
        {                                                                       \
            int k = brr, c = bc4 * 4;                                           \
            cvt_store4(&Bs[s][0][k][c], &Bs[s][1][k][c], bPre);                 \
        }                                                                       \
    }

    const int ktiles = (Kv + TBK - 1) / TBK;   // 49

    PV_LOAD(0);
    __syncthreads();           // sden init visible before first atomicAdd
    PV_STORE(0);
    __syncthreads();

    for (int t = 0; t < ktiles; t++) {
        const int cur = t & 1;
        bool last = (t == ktiles - 1);
        if (!last) PV_LOAD((t + 1) * TBK);
        {
            uint32_t Ah[2][4], Al[2][4], Bh[4][2], Bl[4][2];
#pragma unroll
            for (int i = 0; i < 2; i++) {
                int row = wm * 32 + i * 16 + (lane & 15);
                int col = (lane >> 4) << 3;
                ldsm_x4(Ah[i][0], Ah[i][1], Ah[i][2], Ah[i][3],
                        smem_u32(&As[cur][0][row][col]));
                ldsm_x4(Al[i][0], Al[i][1], Al[i][2], Al[i][3],
                        smem_u32(&As[cur][1][row][col]));
            }
            {
                int row = lane & 15;
                int col = wn * 32 + ((lane >> 4) << 3);
                uint32_t r0, r1, r2, r3;
                ldsm_x4_t(r0, r1, r2, r3, smem_u32(&Bs[cur][0][row][col]));
                Bh[0][0] = r0; Bh[0][1] = r1; Bh[1][0] = r2; Bh[1][1] = r3;
                ldsm_x4_t(r0, r1, r2, r3, smem_u32(&Bs[cur][0][row][col + 16]));
                Bh[2][0] = r0; Bh[2][1] = r1; Bh[3][0] = r2; Bh[3][1] = r3;
                ldsm_x4_t(r0, r1, r2, r3, smem_u32(&Bs[cur][1][row][col]));
                Bl[0][0] = r0; Bl[0][1] = r1; Bl[1][0] = r2; Bl[1][1] = r3;
                ldsm_x4_t(r0, r1, r2, r3, smem_u32(&Bs[cur][1][row][col + 16]));
                Bl[2][0] = r0; Bl[2][1] = r1; Bl[3][0] = r2; Bl[3][1] = r3;
            }
#pragma unroll
            for (int i = 0; i < 2; i++)
#pragma unroll
                for (int j = 0; j < 4; j++) {
                    mma_bf16(acc[i][j], Ah[i], Bh[j]);
                    mma_bf16(acc[i][j], Ah[i], Bl[j]);
                    mma_bf16(acc[i][j], Al[i], Bh[j]);
                }
        }
        if (!last) {
            PV_STORE(cur ^ 1);
            __syncthreads();
        }
    }

    const int g  = lane >> 2;
    const int tg = lane & 3;
#pragma unroll
    for (int i = 0; i < 2; i++) {
        int lr0 = wm * 32 + i * 16 + g;
        int lr1 = lr0 + 8;
        int r0w = m0 + lr0, r1w = m0 + lr1;
        float d0 = (r0w < Mv) ? 1.0f / sden[lr0] : 0.f;
        float d1 = (r1w < Mv) ? 1.0f / sden[lr1] : 0.f;
#pragma unroll
        for (int j = 0; j < 4; j++) {
            int c0 = wn * 32 + j * 8 + tg * 2;
            if (r0w < Mv) {
                float2 v = make_float2(acc[i][j][0] * d0, acc[i][j][1] * d0);
                *(float2*)&C[(long long)r0w * 256 + c0] = v;
            }
            if (r1w < Mv) {
                float2 v = make_float2(acc[i][j][2] * d1, acc[i][j][3] * d1);
                *(float2*)&C[(long long)r1w * 256 + c0] = v;
            }
        }
    }
#undef PV_LOAD
#undef PV_STORE
}

// ---------------------------------------------------------------------------
// Small helpers
// ---------------------------------------------------------------------------
__global__ void transpose_kernel(const float* __restrict__ src, float* __restrict__ dst,
                                 int M, int N)
{
    __shared__ float t[32][33];
    int x = blockIdx.x * 32 + threadIdx.x;
    int y0 = blockIdx.y * 32 + threadIdx.y;
#pragma unroll
    for (int i = 0; i < 32; i += 8) {
        int y = y0 + i;
        t[threadIdx.y + i][threadIdx.x] = (y < M && x < N) ? src[(long long)y * N + x] : 0.f;
    }
    __syncthreads();
    int xo = blockIdx.y * 32 + threadIdx.x;
    int yo0 = blockIdx.x * 32 + threadIdx.y;
#pragma unroll
    for (int i = 0; i < 32; i += 8) {
        int yo = yo0 + i;
        if (yo < N && xo < M) dst[(long long)yo * M + xo] = t[threadIdx.x][threadIdx.y + i];
    }
}

// Pack up to 4 separate buffers into one contiguous [grid.y][n] buffer.
__global__ void pack4_kernel(const float* __restrict__ p0, const float* __restrict__ p1,
                             const float* __restrict__ p2, const float* __restrict__ p3,
                             float* __restrict__ dst, long long n)
{
    long long i = (long long)blockIdx.x * 256 + threadIdx.x;
    int br = blockIdx.y;
    if (i < n) {
        const float* src = (br == 0) ? p0 : (br == 1) ? p1 : (br == 2) ? p2 : p3;
        dst[(long long)br * n + i] = src[i];
    }
}

// KV_S[b, j*196+t, c] = T_hat[b, t, j*256 + c]
__global__ void kvs_kernel(const float* __restrict__ T, float* __restrict__ KVS)
{
    long long i = (long long)blockIdx.x * blockDim.x + threadIdx.x;
    if (i >= SZ_BNDC) return;
    int c = (int)(i & 255);
    long long t2 = i >> 8;
    int n = (int)(t2 % 784);
    int b = (int)(t2 / 784);
    int j = n / 196, t = n % 196;
    KVS[i] = T[((long long)b * 196 + t) * 1024 + (long long)j * 256 + c];
}

// Plain row softmax (SATAT scores, 196 cols)
__global__ void softmax_kernel(float* __restrict__ X, int cols)
{
    int row = blockIdx.x;
    float* x = X + (long long)row * cols;
    int tid = threadIdx.x;
    __shared__ float red[256];

    float m = -1e30f;
    for (int c = tid; c < cols; c += 256) m = fmaxf(m, x[c]);
    red[tid] = m; __syncthreads();
    for (int s = 128; s > 0; s >>= 1) {
        if (tid < s) red[tid] = fmaxf(red[tid], red[tid + s]);
        __syncthreads();
    }
    m = red[0]; __syncthreads();

    float sum = 0.f;
    for (int c = tid; c < cols; c += 256) {
        float e = __expf(x[c] - m);
        x[c] = e; sum += e;
    }
    red[tid] = sum; __syncthreads();
    for (int s = 128; s > 0; s >>= 1) {
        if (tid < s) red[tid] += red[tid + s];
        __syncthreads();
    }
    float inv = 1.0f / red[0];
    for (int c = tid; c < cols; c += 256) x[c] *= inv;
}

// ---------------------------------------------------------------------------
// Host-side driver
// ---------------------------------------------------------------------------
static inline void gemm(int tb,
                        const float* A, const float* B, float* C,
                        int M, int N, int K, int lda, int ldb, int ldc,
                        long long sAb, long long sAh,
                        long long sBb, long long sBh,
                        long long sCb, long long sCh,
                        int batch, int nh, float alpha)
{
    dim3 g((N + TBN - 1) / TBN, (M + TBM - 1) / TBM, batch), b(256);
    if (tb)
        gemm_mma<true><<<g, b>>>(A, B, C, M, N, K, lda, ldb, ldc,
                                 sAb, sAh, sBb, sBh, sCb, sCh, nh, alpha);
    else
        gemm_mma<false><<<g, b>>>(A, B, C, M, N, K, lda, ldb, ldc,
                                  sAb, sAh, sBb, sBh, sCb, sCh, nh, alpha);
}

extern "C" void kernel_launch(void* const* d_in, const int* in_sizes, int n_in,
                              void* d_out, int out_size)
{
    const float* emb[4] = { (const float*)d_in[0], (const float*)d_in[1],
                            (const float*)d_in[2], (const float*)d_in[3] };
    const float* emb_C = (const float*)d_in[4];
    const float* Wq_c  = (const float*)d_in[5];
    const float* Wk_c  = (const float*)d_in[6];
    const float* Wv_c  = (const float*)d_in[7];
    const float* Wo_c  = (const float*)d_in[8];
    const float* Wq[4] = { (const float*)d_in[9],  (const float*)d_in[10],
                           (const float*)d_in[11], (const float*)d_in[12] };
    const float* Wk    = (const float*)d_in[13];
    const float* Wv    = (const float*)d_in[14];
    const float* Wo[4] = { (const float*)d_in[15], (const float*)d_in[16],
                           (const float*)d_in[17], (const float*)d_in[18] };
    float* out = (float*)d_out;

    float *q3, *k3, *v3, *sc, *oat, *that, *kvs, *Kb, *Vb, *attn, *ctxp;
    float *gain, *rowmax, *WkT, *WvT, *WqT;
    cudaGetSymbolAddress((void**)&q3,    g_q3);
    cudaGetSymbolAddress((void**)&k3,    g_k3);
    cudaGetSymbolAddress((void**)&v3,    g_v3);
    cudaGetSymbolAddress((void**)&sc,    g_sc);
    cudaGetSymbolAddress((void**)&oat,   g_oat);
    cudaGetSymbolAddress((void**)&that,  g_that);
    cudaGetSymbolAddress((void**)&kvs,   g_kvs);
    cudaGetSymbolAddress((void**)&Kb,    g_Kb);
    cudaGetSymbolAddress((void**)&Vb,    g_Vb);
    cudaGetSymbolAddress((void**)&attn,  g_attn);
    cudaGetSymbolAddress((void**)&ctxp,  g_ctx);
    cudaGetSymbolAddress((void**)&gain,  g_gain);
    cudaGetSymbolAddress((void**)&rowmax,g_rowmax);
    cudaGetSymbolAddress((void**)&WkT,   g_WkT);
    cudaGetSymbolAddress((void**)&WvT,   g_WvT);
    cudaGetSymbolAddress((void**)&WqT,   g_WqT);

    // ---------------- Weight pre-transposes ----------------
    {
        dim3 b(32, 8);
        dim3 g784((784 + 31) / 32, (784 + 31) / 32);
        transpose_kernel<<<g784, b>>>(Wk, WkT, 784, 784);
        transpose_kernel<<<g784, b>>>(Wv, WvT, 784, 784);
        dim3 g196((196 + 31) / 32, (196 + 31) / 32);
        for (int i = 0; i < 4; i++)
            transpose_kernel<<<g196, b>>>(Wq[i], WqT + (long long)i * 38416, 196, 196);
    }

    // ---------------- Stage A: SATAT over emb_C ----------------
    // Fused QKV: pack Wq_c|Wk_c|Wv_c into g_q3 (dead scratch), write q/k/v
    // into the attn buffer (dead during stage A): q=attn, k=attn+S, v=attn+2S.
    float* Wqkv = q3;                       // 3*1048576 floats = 12.6 MB
    float* qv   = attn;                     // q slab
    float* kvh  = attn + SZ_BNDC;           // k slab
    float* vv   = attn + 2 * SZ_BNDC;       // v slab
    pack4_kernel<<<dim3(4096, 3), 256>>>(Wq_c, Wk_c, Wv_c, Wv_c, Wqkv, 1048576LL);
    // One launch, batch=3 (z=0:Q, 1:K, 2:V) -> 1176 blocks (~4 full waves)
    gemm(0, emb_C, Wqkv, qv, 6272, 1024, 1024, 1024, 1024, 1024,
         0, 0, 1048576, 0, SZ_BNDC, 0, 3, 1, 1.0f);

    gemm(1, qv, kvh, sc, 196, 196, 256, 1024, 1024, 196,
         200704, 256, 200704, 256, 153664, 38416, 128, 4, 0.0625f);
    softmax_kernel<<<25088, 256>>>(sc, 196);
    gemm(0, sc, vv, oat, 196, 256, 196, 196, 1024, 1024,
         153664, 38416, 200704, 256, 200704, 256, 128, 4, 1.0f);
    gemm(0, oat, Wo_c, that, 6272, 1024, 1024, 1024, 1024, 1024,
         0, 0, 0, 0, 0, 0, 1, 1, 1.0f);

    // ---------------- Stage B: KV token mix ----------------
    kvs_kernel<<<(unsigned)((SZ_BNDC + 255) / 256), 256>>>(that, kvs);
    // Fused K+V mix: one launch, batch=64, z = s*32 + b; runtime pointer
    // diffs give the weight/output strides between the K and V variants.
    gemm(0, WkT, kvs, Kb, 784, 256, 784, 784, 256, 256,
         (long long)(WvT - WkT), 0, 0, 200704,
         (long long)(Vb - Kb), 200704, 64, 32, 1.0f);

    // ---------------- Stage C: 4 branches ----------------
    // Stage-A/B scratch now dead; reuse:
    //   embP = g_q3 (packed emb[4]), Qb4 = g_k3, WoP = g_v3, ctx4 = g_oat,
    //   stats partials in g_ctx.
    float* embP = q3;
    float* Qb4  = k3;
    float* WoP  = v3;
    float* ctx4 = oat;
    float* part = ctxp;           // 1024 floats used
    pack4_kernel<<<dim3((unsigned)((SZ_Q + 255) / 256), 4), 256>>>(
        emb[0], emb[1], emb[2], emb[3], embP, SZ_Q);
    pack4_kernel<<<dim3(256, 4), 256>>>(
        Wo[0], Wo[1], Wo[2], Wo[3], WoP, 65536);

    // Batched Q-mix: z = br*32 + b  (512 blocks, one launch)
    gemm(0, WqT, embP, Qb4, 196, 256, 196, 196, 256, 256,
         38416, 0, SZ_Q, 50176, SZ_Q, 50176, 128, 32, 1.0f);

    // QK + stats + fused softmax-PV per branch
    for (int br = 0; br < 4; br++) {
        const float* Qb = Qb4 + (long long)br * SZ_Q;
        gemm(1, Qb, Kb, attn, 196, 784, 64, 256, 256, 784,
             50176, 64, 200704, 64, 614656, 153664, 128, 4, 1.0f);
        attn_stats_part<<<512, 256>>>(attn, rowmax, part);
        attn_stats_fin<<<1, 128>>>(part, gain);
        dim3 g(1, 2, 128), b(256);
        attn_pv_kernel<<<g, b>>>(attn, Vb, ctx4 + (long long)br * SZ_Q,
                                 rowmax, gain);
    }

    // Batched Wo: z = br  (392 blocks, one launch)
    gemm(0, ctx4, WoP, out, 6272, 256, 256, 256, 256, 256,
         SZ_Q, 0, 65536, 0, SZ_Q, 0, 4, 1, 1.0f);
}